// round 5
// baseline (speedup 1.0000x reference)
#include <cuda_runtime.h>
#include <cuda_bf16.h>
#include <math.h>
#include <stdint.h>

#define BATCH      2048
#define NODES      12
#define NTOK       (BATCH * NODES)     // 24576
#define D          128
#define F          512
#define NHEAD      4
#define DH         32
#define SCALE      0.17677669529663687f

typedef __nv_bfloat16 bf16;

// ---------------- scratch (device globals; no allocation) ----------------
__device__ float g_x   [NTOK * D];
__device__ float g_qkv [NTOK * 384];
__device__ __align__(16) bf16 g_hh[NTOK * D],  g_hl[NTOK * D];
__device__ __align__(16) bf16 g_mh[NTOK * D],  g_ml[NTOK * D];
__device__ __align__(16) bf16 g_th[NTOK * F],  g_tl[NTOK * F];
__device__ __align__(16) bf16 g_wqkvh[2 * 384 * D], g_wqkvl[2 * 384 * D]; // [l][n][k]
__device__ __align__(16) bf16 g_woh[2 * D * D],     g_wol[2 * D * D];
__device__ __align__(16) bf16 g_w1h[2 * F * D],     g_w1l[2 * F * D];
__device__ __align__(16) bf16 g_w2h[2 * D * F],     g_w2l[2 * D * F];
__device__ float g_bqkv[2 * 384];

__device__ __forceinline__ float gelu_exact(float x) {
    return 0.5f * x * (1.0f + erff(x * 0.7071067811865476f));
}
__device__ __forceinline__ void split_bf(float x, bf16& h, bf16& l) {
    h = __float2bfloat16(x);
    l = __float2bfloat16(x - __bfloat162float(h));
}
__device__ __forceinline__ uint32_t smem_u32(const void* p) {
    uint32_t a;
    asm("{ .reg .u64 t; cvta.to.shared.u64 t, %1; cvt.u32.u64 %0, t; }" : "=r"(a) : "l"(p));
    return a;
}
__device__ __forceinline__ void cp16(uint32_t dst, const void* src) {
    asm volatile("cp.async.ca.shared.global [%0], [%1], 16;" :: "r"(dst), "l"(src));
}
#define CP_COMMIT() asm volatile("cp.async.commit_group;" ::: "memory")
#define CP_WAIT(n)  asm volatile("cp.async.wait_group %0;" :: "n"(n) : "memory")

__device__ __forceinline__ void ldsm4(uint32_t* r, uint32_t addr) {
    asm volatile("ldmatrix.sync.aligned.m8n8.x4.shared.b16 {%0,%1,%2,%3}, [%4];"
        : "=r"(r[0]), "=r"(r[1]), "=r"(r[2]), "=r"(r[3]) : "r"(addr));
}
__device__ __forceinline__ void mma_bf16(float* c, const uint32_t* a, uint32_t b0, uint32_t b1) {
    asm volatile(
        "mma.sync.aligned.m16n8k16.row.col.f32.bf16.bf16.f32 "
        "{%0,%1,%2,%3}, {%4,%5,%6,%7}, {%8,%9}, {%0,%1,%2,%3};"
        : "+f"(c[0]), "+f"(c[1]), "+f"(c[2]), "+f"(c[3])
        : "r"(a[0]), "r"(a[1]), "r"(a[2]), "r"(a[3]), "r"(b0), "r"(b1));
}

// ---------------- init + layer0 LN1 ----------------
__global__ void init_ln_kernel(const float* __restrict__ patch,
                               const float* __restrict__ band,
                               const float* __restrict__ summ,
                               const float* __restrict__ s, const float* __restrict__ b,
                               float* __restrict__ x,
                               bf16* __restrict__ oh, bf16* __restrict__ ol) {
    int row  = blockIdx.x * 4 + (threadIdx.x >> 5);
    int lane = threadIdx.x & 31;
    int node = row % NODES;
    int bb   = row / NODES;
    float v[4];
    float sum = 0.f;
#pragma unroll
    for (int i = 0; i < 4; i++) {
        int d = lane + 32 * i;
        float val;
        if (node < 6)       val = patch[(size_t)(bb * 6 + node) * D + d];
        else if (node < 11) val = band [(size_t)(bb * 5 + (node - 6)) * D + d];
        else                val = summ[d];
        v[i] = val;
        x[(size_t)row * D + d] = val;
        sum += val;
    }
#pragma unroll
    for (int o = 16; o; o >>= 1) sum += __shfl_xor_sync(0xffffffffu, sum, o);
    float mu = sum * (1.0f / 128.0f);
    float sq = 0.f;
#pragma unroll
    for (int i = 0; i < 4; i++) { float c = v[i] - mu; sq += c * c; }
#pragma unroll
    for (int o = 16; o; o >>= 1) sq += __shfl_xor_sync(0xffffffffu, sq, o);
    float inv = rsqrtf(sq * (1.0f / 128.0f) + 1e-5f);
#pragma unroll
    for (int i = 0; i < 4; i++) {
        int d = lane + 32 * i;
        float y = (v[i] - mu) * inv * s[d] + b[d];
        size_t o = (size_t)row * D + d;
        split_bf(y, oh[o], ol[o]);
    }
}

// ---------------- all weight packing in one kernel ----------------
__global__ void pack_all_kernel(const float* __restrict__ wq, const float* __restrict__ wk,
                                const float* __restrict__ wv, const float* __restrict__ wo,
                                const float* __restrict__ w1, const float* __restrict__ w2,
                                const float* __restrict__ bq, const float* __restrict__ bk,
                                const float* __restrict__ bv,
                                bf16* __restrict__ qh, bf16* __restrict__ ql,
                                bf16* __restrict__ oh, bf16* __restrict__ ol,
                                bf16* __restrict__ h1, bf16* __restrict__ l1,
                                bf16* __restrict__ h2, bf16* __restrict__ l2,
                                float* __restrict__ bqkv) {
    int idx = blockIdx.x * 256 + threadIdx.x;
    if (idx < 98304) { // wqkv: [l][n<384][k<128]
        int l = idx / 49152, r = idx % 49152;
        int n = r / 128, k = r % 128;
        const float* src = (n < 128) ? wq : ((n < 256) ? wk : wv);
        float v = src[(size_t)l * 16384 + k * 128 + (n & 127)];
        split_bf(v, qh[idx], ql[idx]);
    } else if (idx < 131072) { // wo: [l][n<128][k<128]
        int t = idx - 98304;
        int l = t / 16384, r = t % 16384;
        int n = r / 128, k = r % 128;
        float v = wo[(size_t)l * 16384 + k * 128 + n];
        split_bf(v, oh[t], ol[t]);
    } else if (idx < 262144) { // w1: [l][n<512][k<128]  src [l][k<128][n<512]
        int t = idx - 131072;
        int l = t / 65536, r = t % 65536;
        int n = r / 128, k = r % 128;
        float v = w1[(size_t)l * 65536 + (size_t)k * 512 + n];
        split_bf(v, h1[t], l1[t]);
    } else if (idx < 393216) { // w2: [l][n<128][k<512]  src [l][k<512][n<128]
        int t = idx - 262144;
        int l = t / 65536, r = t % 65536;
        int n = r / 512, k = r % 512;
        float v = w2[(size_t)l * 65536 + (size_t)k * 128 + n];
        split_bf(v, h2[t], l2[t]);
    } else if (idx < 393984) { // bqkv
        int t = idx - 393216;
        int l = t / 384, n = t % 384;
        const float* sb = (n < 128) ? bq : ((n < 256) ? bk : bv);
        bqkv[t] = sb[l * 128 + (n & 127)];
    }
}

// ---------------- LayerNorm + bf16 split output ----------------
__global__ void ln_split_kernel(const float* __restrict__ in, bf16* __restrict__ oh,
                                bf16* __restrict__ ol,
                                const float* __restrict__ s, const float* __restrict__ b) {
    int row  = blockIdx.x * 4 + (threadIdx.x >> 5);
    int lane = threadIdx.x & 31;
    const float* rp = in + (size_t)row * D;
    float v[4];
    float sum = 0.f;
#pragma unroll
    for (int i = 0; i < 4; i++) { v[i] = rp[lane + 32 * i]; sum += v[i]; }
#pragma unroll
    for (int o = 16; o; o >>= 1) sum += __shfl_xor_sync(0xffffffffu, sum, o);
    float mu = sum * (1.0f / 128.0f);
    float sq = 0.f;
#pragma unroll
    for (int i = 0; i < 4; i++) { float c = v[i] - mu; sq += c * c; }
#pragma unroll
    for (int o = 16; o; o >>= 1) sq += __shfl_xor_sync(0xffffffffu, sq, o);
    float inv = rsqrtf(sq * (1.0f / 128.0f) + 1e-5f);
#pragma unroll
    for (int i = 0; i < 4; i++) {
        int d = lane + 32 * i;
        float y = (v[i] - mu) * inv * s[d] + b[d];
        size_t o = (size_t)row * D + d;
        split_bf(y, oh[o], ol[o]);
    }
}

// ---------------- bf16x3 GEMM: ldmatrix + cp.async, BM=128 BN=64 BK=16 ----------------
// A split [M][K], W split [N][K]. mode 0: outf=A@W^T+bias (ldo)
// mode 1: outf = resid + A@W^T + bias (N=128); mode 2: split(gelu(..)) -> oh/ol (ldh)
// smem per stage: Ah 128*48 | Al 128*48 | Wh 64*48 | Wl 64*48 = 18432 B; 3 stages.
#define STG_B   18432
#define OFF_AL  6144
#define OFF_WH  12288
#define OFF_WL  15360
#define GEMM_SMEM (3 * STG_B)

__global__ __launch_bounds__(256) void tgemm_kernel(
    const bf16* __restrict__ Ah, const bf16* __restrict__ Al,
    const bf16* __restrict__ Wh, const bf16* __restrict__ Wl, int K,
    const float* __restrict__ bias,
    float* __restrict__ outf, int ldo,
    bf16* __restrict__ oh, bf16* __restrict__ ol, int ldh,
    const float* __restrict__ resid, int mode) {
    extern __shared__ __align__(16) char sm[];
    uint32_t sb = smem_u32(sm);
    const int tid = threadIdx.x, lane = tid & 31, wid = tid >> 5;
    const int bm = blockIdx.y * 128, bn = blockIdx.x * 64;
    const int wm = (wid & 3) * 32, wn = (wid >> 2) * 32;
    const int nst = K >> 4;

    const bf16* Abh = Ah + (size_t)bm * K;
    const bf16* Abl = Al + (size_t)bm * K;
    const bf16* Wb  = (tid >= 128) ? (Wl + (size_t)bn * K) : (Wh + (size_t)bn * K);
    const uint32_t woffs = (tid >= 128) ? OFF_WL : OFF_WH;

    // load-thread mapping (conflict-free 16B stores: granule = 3m+h mod 8 is a permutation)
    const int am = tid & 127, ahh = tid >> 7;
    const int wnr = tid & 63, whh = (tid >> 6) & 1;
    const uint32_t a_dst0 = (uint32_t)(am * 48 + ahh * 16);
    const uint32_t w_dst0 = woffs + (uint32_t)(wnr * 48 + whh * 16);
    const size_t a_src0 = (size_t)am * K + ahh * 8;
    const size_t w_src0 = (size_t)wnr * K + whh * 8;

    float acc[2][4][4];
#pragma unroll
    for (int i = 0; i < 2; i++)
#pragma unroll
        for (int j = 0; j < 4; j++)
#pragma unroll
            for (int c = 0; c < 4; c++) acc[i][j][c] = 0.f;

    // ldmatrix per-lane offsets
    const uint32_t aoff = (uint32_t)((lane & 15) * 48 + (lane >> 4) * 16);
    const uint32_t boff = (uint32_t)(((((lane >> 4) << 3) + (lane & 7)) * 48) + ((lane >> 3) & 1) * 16);

#define LOAD_STAGE(s) do { \
    uint32_t base_ = sb + ((s) % 3) * STG_B; \
    int ko_ = (s) * 16; \
    cp16(base_ + a_dst0,          Abh + a_src0 + ko_); \
    cp16(base_ + OFF_AL + a_dst0, Abl + a_src0 + ko_); \
    cp16(base_ + w_dst0,          Wb  + w_src0 + ko_); \
} while (0)

    LOAD_STAGE(0); CP_COMMIT();
    if (nst > 1) { LOAD_STAGE(1); CP_COMMIT(); }

    for (int s = 0; s < nst; s++) {
        if (s + 2 < nst)      { LOAD_STAGE(s + 2); CP_COMMIT(); CP_WAIT(2); }
        else if (s + 1 < nst) { CP_WAIT(1); }
        else                  { CP_WAIT(0); }
        __syncthreads();
        uint32_t base = sb + (s % 3) * STG_B;

        uint32_t fah[2][4], fal[2][4], fbh[2][4], fbl[2][4];
#pragma unroll
        for (int mi = 0; mi < 2; mi++) {
            uint32_t ad = base + (uint32_t)((wm + mi * 16) * 48) + aoff;
            ldsm4(fah[mi], ad);
            ldsm4(fal[mi], ad + OFF_AL);
        }
#pragma unroll
        for (int nj = 0; nj < 2; nj++) {
            uint32_t bd = base + OFF_WH + (uint32_t)((wn + nj * 16) * 48) + boff;
            ldsm4(fbh[nj], bd);
            ldsm4(fbl[nj], bd + (OFF_WL - OFF_WH));
        }
#pragma unroll
        for (int mi = 0; mi < 2; mi++)
#pragma unroll
            for (int nj = 0; nj < 2; nj++) {
                float* c0 = acc[mi][nj * 2];
                float* c1 = acc[mi][nj * 2 + 1];
                mma_bf16(c0, fah[mi], fbh[nj][0], fbh[nj][1]);
                mma_bf16(c0, fal[mi], fbh[nj][0], fbh[nj][1]);
                mma_bf16(c0, fah[mi], fbl[nj][0], fbl[nj][1]);
                mma_bf16(c1, fah[mi], fbh[nj][2], fbh[nj][3]);
                mma_bf16(c1, fal[mi], fbh[nj][2], fbh[nj][3]);
                mma_bf16(c1, fah[mi], fbl[nj][2], fbl[nj][3]);
            }
        __syncthreads();
    }

    // epilogue
#pragma unroll
    for (int mi = 0; mi < 2; mi++) {
        int r0 = bm + wm + mi * 16 + (lane >> 2);
        int r1 = r0 + 8;
#pragma unroll
        for (int ni = 0; ni < 4; ni++) {
            int col = bn + wn + ni * 8 + 2 * (lane & 3);
            float b0 = bias[col], b1 = bias[col + 1];
            float v0 = acc[mi][ni][0] + b0, v1 = acc[mi][ni][1] + b1;
            float v2 = acc[mi][ni][2] + b0, v3 = acc[mi][ni][3] + b1;
            if (mode == 0) {
                size_t o0 = (size_t)r0 * ldo + col, o1 = (size_t)r1 * ldo + col;
                *(float2*)&outf[o0] = make_float2(v0, v1);
                *(float2*)&outf[o1] = make_float2(v2, v3);
            } else if (mode == 1) {
                size_t o0 = (size_t)r0 * 128 + col, o1 = (size_t)r1 * 128 + col;
                v0 += resid[o0]; v1 += resid[o0 + 1];
                v2 += resid[o1]; v3 += resid[o1 + 1];
                *(float2*)&outf[o0] = make_float2(v0, v1);
                *(float2*)&outf[o1] = make_float2(v2, v3);
            } else {
                v0 = gelu_exact(v0); v1 = gelu_exact(v1);
                v2 = gelu_exact(v2); v3 = gelu_exact(v3);
                bf16 h0, l0, h1, l1;
                size_t o0 = (size_t)r0 * ldh + col, o1 = (size_t)r1 * ldh + col;
                split_bf(v0, h0, l0); split_bf(v1, h1, l1);
                __nv_bfloat162 ph{h0, h1}, pl{l0, l1};
                *(__nv_bfloat162*)&oh[o0] = ph;
                *(__nv_bfloat162*)&ol[o0] = pl;
                split_bf(v2, h0, l0); split_bf(v3, h1, l1);
                __nv_bfloat162 qh2{h0, h1}, ql2{l0, l1};
                *(__nv_bfloat162*)&oh[o1] = qh2;
                *(__nv_bfloat162*)&ol[o1] = ql2;
            }
        }
    }
#undef LOAD_STAGE
}

// ---------------- dense 12-node attention; msg written as bf16 split ----------------
__global__ void attn_kernel(const float* __restrict__ qkv,
                            const float* __restrict__ edge_bias,
                            bf16* __restrict__ mh, bf16* __restrict__ ml) {
    __shared__ float sq[NODES * D], sk[NODES * D], sv[NODES * D];
    __shared__ float seb[36];
    int b = blockIdx.x;
    size_t base  = (size_t)b * NODES * 384;
    size_t obase = (size_t)b * NODES * D;
    for (int i = threadIdx.x; i < NODES * D; i += 64) {
        int node = i >> 7, col = i & 127;
        sq[i] = qkv[base + node * 384 + col];
        sk[i] = qkv[base + node * 384 + 128 + col];
        sv[i] = qkv[base + node * 384 + 256 + col];
    }
    if (threadIdx.x < 36) seb[threadIdx.x] = edge_bias[threadIdx.x];
    __syncthreads();
    int tt = threadIdx.x;
    if (tt < NODES * NHEAD) {
        int dst = tt >> 2, hd = tt & 3;
        int kd = dst < 6 ? 0 : (dst < 11 ? 1 : 2);
        float logits[NODES];
        float mx = -1e30f;
        const float* qp = &sq[dst * D + hd * DH];
#pragma unroll
        for (int j = 0; j < NODES; j++) {
            int ks = j < 6 ? 0 : (j < 11 ? 1 : 2);
            const float* kp = &sk[j * D + hd * DH];
            float dot = 0.f;
#pragma unroll
            for (int d = 0; d < DH; d++) dot = fmaf(qp[d], kp[d], dot);
            float lg = dot * SCALE + seb[(ks * 3 + kd) * NHEAD + hd];
            logits[j] = lg;
            mx = fmaxf(mx, lg);
        }
        float z = 0.f;
#pragma unroll
        for (int j = 0; j < NODES; j++) { logits[j] = expf(logits[j] - mx); z += logits[j]; }
        float inv = 1.0f / z;
        float out[DH] = {};
#pragma unroll
        for (int j = 0; j < NODES; j++) {
            float a = logits[j] * inv;
            const float* vp = &sv[j * D + hd * DH];
#pragma unroll
            for (int d = 0; d < DH; d++) out[d] = fmaf(a, vp[d], out[d]);
        }
#pragma unroll
        for (int d = 0; d < DH; d++) {
            size_t o = obase + dst * D + hd * DH + d;
            split_bf(out[d], mh[o], ml[o]);
        }
    }
}

// ---------------- final: gate/pool + proj + LN + gelu ----------------
__global__ void final_kernel(const float* __restrict__ x,
                             const float* __restrict__ gate_w, const float* __restrict__ gate_b,
                             const float* __restrict__ proj_w, const float* __restrict__ proj_b,
                             const float* __restrict__ pln_s, const float* __restrict__ pln_b,
                             float* __restrict__ out) {
    __shared__ float sx[NODES * D];
    __shared__ float sgate[NODES];
    __shared__ float comb[2 * D];
    __shared__ float red[4];
    int b = blockIdx.x, tid = threadIdx.x;
    for (int i = tid; i < NODES * D; i += 128) sx[i] = x[(size_t)b * NODES * D + i];
    __syncthreads();
    if (tid < NODES) {
        float acc = gate_b[0];
#pragma unroll 8
        for (int d = 0; d < D; d++) acc = fmaf(sx[tid * D + d], gate_w[d], acc);
        sgate[tid] = 1.0f / (1.0f + expf(-acc));
    }
    __syncthreads();
    float pooled = 0.f;
#pragma unroll
    for (int n = 0; n < NODES; n++) pooled = fmaf(sx[n * D + tid], sgate[n], pooled);
    comb[tid]     = sx[11 * D + tid];
    comb[D + tid] = pooled;
    __syncthreads();
    float y = proj_b[tid];
#pragma unroll 8
    for (int c = 0; c < 2 * D; c++) y = fmaf(comb[c], proj_w[c * D + tid], y);
    float sum = y;
#pragma unroll
    for (int o = 16; o; o >>= 1) sum += __shfl_xor_sync(0xffffffffu, sum, o);
    if ((tid & 31) == 0) red[tid >> 5] = sum;
    __syncthreads();
    float mu = (red[0] + red[1] + red[2] + red[3]) * (1.0f / 128.0f);
    float c0 = y - mu;
    float cs = c0 * c0;
#pragma unroll
    for (int o = 16; o; o >>= 1) cs += __shfl_xor_sync(0xffffffffu, cs, o);
    __syncthreads();
    if ((tid & 31) == 0) red[tid >> 5] = cs;
    __syncthreads();
    float var = (red[0] + red[1] + red[2] + red[3]) * (1.0f / 128.0f);
    float yn = c0 * rsqrtf(var + 1e-5f) * pln_s[tid] + pln_b[tid];
    out[(size_t)b * D + tid] = gelu_exact(yn);
}

// ---------------- host orchestration ----------------
extern "C" void kernel_launch(void* const* d_in, const int* in_sizes, int n_in,
                              void* d_out, int out_size) {
    const float* patch   = (const float*)d_in[0];
    const float* band    = (const float*)d_in[1];
    const float* summ    = (const float*)d_in[2];
    const float* ln1_s   = (const float*)d_in[3];
    const float* ln1_b   = (const float*)d_in[4];
    const float* wq      = (const float*)d_in[5];
    const float* bq      = (const float*)d_in[6];
    const float* wk      = (const float*)d_in[7];
    const float* bk      = (const float*)d_in[8];
    const float* wv      = (const float*)d_in[9];
    const float* bv      = (const float*)d_in[10];
    const float* wo      = (const float*)d_in[11];
    const float* bo      = (const float*)d_in[12];
    const float* edge_b  = (const float*)d_in[13];
    const float* ln2_s   = (const float*)d_in[14];
    const float* ln2_b   = (const float*)d_in[15];
    const float* w1      = (const float*)d_in[16];
    const float* b1      = (const float*)d_in[17];
    const float* w2      = (const float*)d_in[18];
    const float* b2      = (const float*)d_in[19];
    const float* gate_w  = (const float*)d_in[20];
    const float* gate_b  = (const float*)d_in[21];
    const float* proj_w  = (const float*)d_in[22];
    const float* proj_b  = (const float*)d_in[23];
    const float* pln_s   = (const float*)d_in[24];
    const float* pln_b   = (const float*)d_in[25];
    float* out = (float*)d_out;

    float *x, *qkv, *bqkv;
    bf16 *hh, *hl, *mh, *ml, *th, *tl;
    bf16 *wqkvh, *wqkvl, *woh, *wol, *w1h, *w1l, *w2h, *w2l;
    cudaGetSymbolAddress((void**)&x,     g_x);
    cudaGetSymbolAddress((void**)&qkv,   g_qkv);
    cudaGetSymbolAddress((void**)&bqkv,  g_bqkv);
    cudaGetSymbolAddress((void**)&hh,    g_hh);
    cudaGetSymbolAddress((void**)&hl,    g_hl);
    cudaGetSymbolAddress((void**)&mh,    g_mh);
    cudaGetSymbolAddress((void**)&ml,    g_ml);
    cudaGetSymbolAddress((void**)&th,    g_th);
    cudaGetSymbolAddress((void**)&tl,    g_tl);
    cudaGetSymbolAddress((void**)&wqkvh, g_wqkvh);
    cudaGetSymbolAddress((void**)&wqkvl, g_wqkvl);
    cudaGetSymbolAddress((void**)&woh,   g_woh);
    cudaGetSymbolAddress((void**)&wol,   g_wol);
    cudaGetSymbolAddress((void**)&w1h,   g_w1h);
    cudaGetSymbolAddress((void**)&w1l,   g_w1l);
    cudaGetSymbolAddress((void**)&w2h,   g_w2h);
    cudaGetSymbolAddress((void**)&w2l,   g_w2l);

    static int smem_set = 0;
    if (!smem_set) {
        cudaFuncSetAttribute(tgemm_kernel, cudaFuncAttributeMaxDynamicSharedMemorySize, GEMM_SMEM);
        smem_set = 1;
    }

    init_ln_kernel<<<NTOK / 4, 128>>>(patch, band, summ, ln1_s, ln1_b, x, hh, hl);
    pack_all_kernel<<<(393984 + 255) / 256, 256>>>(wq, wk, wv, wo, w1, w2, bq, bk, bv,
                                                   wqkvh, wqkvl, woh, wol, w1h, w1l, w2h, w2l, bqkv);

    const int MT = NTOK / 128; // 192
    for (int l = 0; l < 2; l++) {
        // QKV (mode 0): N=384
        tgemm_kernel<<<dim3(6, MT), 256, GEMM_SMEM>>>(
            hh, hl, wqkvh + (size_t)l * 384 * 128, wqkvl + (size_t)l * 384 * 128, 128,
            bqkv + l * 384, qkv, 384, nullptr, nullptr, 0, nullptr, 0);
        attn_kernel<<<BATCH, 64>>>(qkv, edge_b + l * 36, mh, ml);
        // O-proj + residual (mode 1): N=128
        tgemm_kernel<<<dim3(2, MT), 256, GEMM_SMEM>>>(
            mh, ml, woh + (size_t)l * 128 * 128, wol + (size_t)l * 128 * 128, 128,
            bo + l * 128, x, 128, nullptr, nullptr, 0, x, 1);
        ln_split_kernel<<<NTOK / 4, 128>>>(x, hh, hl, ln2_s + l * 128, ln2_b + l * 128);
        // FFN1 + GELU (mode 2): N=512
        tgemm_kernel<<<dim3(8, MT), 256, GEMM_SMEM>>>(
            hh, hl, w1h + (size_t)l * 512 * 128, w1l + (size_t)l * 512 * 128, 128,
            b1 + l * 512, nullptr, 0, th, tl, 512, nullptr, 2);
        // FFN2 + residual (mode 1): N=128, K=512
        tgemm_kernel<<<dim3(2, MT), 256, GEMM_SMEM>>>(
            th, tl, w2h + (size_t)l * 128 * 512, w2l + (size_t)l * 128 * 512, 512,
            b2 + l * 128, x, 128, nullptr, nullptr, 0, x, 1);
        if (l == 0)
            ln_split_kernel<<<NTOK / 4, 128>>>(x, hh, hl, ln1_s + 128, ln1_b + 128);
    }

    final_kernel<<<BATCH, 128>>>(x, gate_w, gate_b, proj_w, proj_b, pln_s, pln_b, out);
}

// round 6
// speedup vs baseline: 1.0904x; 1.0904x over previous
#include <cuda_runtime.h>
#include <cuda_bf16.h>
#include <math.h>
#include <stdint.h>

#define BATCH      2048
#define NODES      12
#define NTOK       (BATCH * NODES)     // 24576
#define D          128
#define F          512
#define NHEAD      4
#define DH         32
#define SCALE      0.17677669529663687f

typedef __nv_bfloat16 bf16;

// ---------------- scratch (device globals; no allocation) ----------------
__device__ __align__(16) float g_x   [NTOK * D];
__device__ __align__(16) float g_qkv [NTOK * 384];
__device__ __align__(16) bf16 g_hh[NTOK * D],  g_hl[NTOK * D];
__device__ __align__(16) bf16 g_mh[NTOK * D],  g_ml[NTOK * D];
__device__ __align__(16) bf16 g_th[NTOK * F],  g_tl[NTOK * F];
__device__ __align__(16) bf16 g_wqkvh[2 * 384 * D], g_wqkvl[2 * 384 * D]; // [l][n][k]
__device__ __align__(16) bf16 g_woh[2 * D * D],     g_wol[2 * D * D];
__device__ __align__(16) bf16 g_w1h[2 * F * D],     g_w1l[2 * F * D];
__device__ __align__(16) bf16 g_w2h[2 * D * F],     g_w2l[2 * D * F];
__device__ float g_bqkv[2 * 384];

__device__ __forceinline__ float gelu_exact(float x) {
    return 0.5f * x * (1.0f + erff(x * 0.7071067811865476f));
}
__device__ __forceinline__ void split_bf(float x, bf16& h, bf16& l) {
    h = __float2bfloat16(x);
    l = __float2bfloat16(x - __bfloat162float(h));
}
__device__ __forceinline__ uint32_t smem_u32(const void* p) {
    uint32_t a;
    asm("{ .reg .u64 t; cvta.to.shared.u64 t, %1; cvt.u32.u64 %0, t; }" : "=r"(a) : "l"(p));
    return a;
}
__device__ __forceinline__ void cp16(uint32_t dst, const void* src) {
    asm volatile("cp.async.ca.shared.global [%0], [%1], 16;" :: "r"(dst), "l"(src));
}
#define CP_COMMIT() asm volatile("cp.async.commit_group;" ::: "memory")
#define CP_WAIT(n)  asm volatile("cp.async.wait_group %0;" :: "n"(n) : "memory")

__device__ __forceinline__ void ldsm4(uint32_t* r, uint32_t addr) {
    asm volatile("ldmatrix.sync.aligned.m8n8.x4.shared.b16 {%0,%1,%2,%3}, [%4];"
        : "=r"(r[0]), "=r"(r[1]), "=r"(r[2]), "=r"(r[3]) : "r"(addr));
}
__device__ __forceinline__ void mma_bf16(float* c, const uint32_t* a, uint32_t b0, uint32_t b1) {
    asm volatile(
        "mma.sync.aligned.m16n8k16.row.col.f32.bf16.bf16.f32 "
        "{%0,%1,%2,%3}, {%4,%5,%6,%7}, {%8,%9}, {%0,%1,%2,%3};"
        : "+f"(c[0]), "+f"(c[1]), "+f"(c[2]), "+f"(c[3])
        : "r"(a[0]), "r"(a[1]), "r"(a[2]), "r"(a[3]), "r"(b0), "r"(b1));
}

// ---------------- init + layer0 LN1 ----------------
__global__ void init_ln_kernel(const float* __restrict__ patch,
                               const float* __restrict__ band,
                               const float* __restrict__ summ,
                               const float* __restrict__ s, const float* __restrict__ b,
                               float* __restrict__ x,
                               bf16* __restrict__ oh, bf16* __restrict__ ol) {
    int row  = blockIdx.x * 4 + (threadIdx.x >> 5);
    int lane = threadIdx.x & 31;
    int node = row % NODES;
    int bb   = row / NODES;
    float v[4];
    float sum = 0.f;
#pragma unroll
    for (int i = 0; i < 4; i++) {
        int d = lane + 32 * i;
        float val;
        if (node < 6)       val = patch[(size_t)(bb * 6 + node) * D + d];
        else if (node < 11) val = band [(size_t)(bb * 5 + (node - 6)) * D + d];
        else                val = summ[d];
        v[i] = val;
        x[(size_t)row * D + d] = val;
        sum += val;
    }
#pragma unroll
    for (int o = 16; o; o >>= 1) sum += __shfl_xor_sync(0xffffffffu, sum, o);
    float mu = sum * (1.0f / 128.0f);
    float sq = 0.f;
#pragma unroll
    for (int i = 0; i < 4; i++) { float c = v[i] - mu; sq += c * c; }
#pragma unroll
    for (int o = 16; o; o >>= 1) sq += __shfl_xor_sync(0xffffffffu, sq, o);
    float inv = rsqrtf(sq * (1.0f / 128.0f) + 1e-5f);
#pragma unroll
    for (int i = 0; i < 4; i++) {
        int d = lane + 32 * i;
        float y = (v[i] - mu) * inv * s[d] + b[d];
        size_t o = (size_t)row * D + d;
        split_bf(y, oh[o], ol[o]);
    }
}

// ---------------- weight packing (two kernels so QKV GEMM is launch #4) ----------------
__global__ void pack_qkvw_kernel(const float* __restrict__ wq, const float* __restrict__ wk,
                                 const float* __restrict__ wv,
                                 const float* __restrict__ bq, const float* __restrict__ bk,
                                 const float* __restrict__ bv,
                                 bf16* __restrict__ qh, bf16* __restrict__ ql,
                                 float* __restrict__ bqkv) {
    int idx = blockIdx.x * 256 + threadIdx.x;
    if (idx < 98304) { // wqkv: [l][n<384][k<128]
        int l = idx / 49152, r = idx % 49152;
        int n = r / 128, k = r % 128;
        const float* src = (n < 128) ? wq : ((n < 256) ? wk : wv);
        float v = src[(size_t)l * 16384 + k * 128 + (n & 127)];
        split_bf(v, qh[idx], ql[idx]);
    }
    if (idx < 768) {
        int l = idx / 384, n = idx % 384;
        const float* sb = (n < 128) ? bq : ((n < 256) ? bk : bv);
        bqkv[idx] = sb[l * 128 + (n & 127)];
    }
}
__global__ void pack_rest_kernel(const float* __restrict__ wo,
                                 const float* __restrict__ w1, const float* __restrict__ w2,
                                 bf16* __restrict__ oh, bf16* __restrict__ ol,
                                 bf16* __restrict__ h1, bf16* __restrict__ l1,
                                 bf16* __restrict__ h2, bf16* __restrict__ l2) {
    int idx = blockIdx.x * 256 + threadIdx.x;
    if (idx < 32768) { // wo: [l][n<128][k<128]
        int l = idx / 16384, r = idx % 16384;
        int n = r / 128, k = r % 128;
        float v = wo[(size_t)l * 16384 + k * 128 + n];
        split_bf(v, oh[idx], ol[idx]);
    } else if (idx < 163840) { // w1: [l][n<512][k<128]  src [l][k<128][n<512]
        int t = idx - 32768;
        int l = t / 65536, r = t % 65536;
        int n = r / 128, k = r % 128;
        float v = w1[(size_t)l * 65536 + (size_t)k * 512 + n];
        split_bf(v, h1[t], l1[t]);
    } else if (idx < 294912) { // w2: [l][n<128][k<512]  src [l][k<512][n<128]
        int t = idx - 163840;
        int l = t / 65536, r = t % 65536;
        int n = r / 512, k = r % 512;
        float v = w2[(size_t)l * 65536 + (size_t)k * 128 + n];
        split_bf(v, h2[t], l2[t]);
    }
}

// ---------------- LayerNorm + bf16 split output ----------------
__global__ void ln_split_kernel(const float* __restrict__ in, bf16* __restrict__ oh,
                                bf16* __restrict__ ol,
                                const float* __restrict__ s, const float* __restrict__ b) {
    int row  = blockIdx.x * 4 + (threadIdx.x >> 5);
    int lane = threadIdx.x & 31;
    const float* rp = in + (size_t)row * D;
    float v[4];
    float sum = 0.f;
#pragma unroll
    for (int i = 0; i < 4; i++) { v[i] = rp[lane + 32 * i]; sum += v[i]; }
#pragma unroll
    for (int o = 16; o; o >>= 1) sum += __shfl_xor_sync(0xffffffffu, sum, o);
    float mu = sum * (1.0f / 128.0f);
    float sq = 0.f;
#pragma unroll
    for (int i = 0; i < 4; i++) { float c = v[i] - mu; sq += c * c; }
#pragma unroll
    for (int o = 16; o; o >>= 1) sq += __shfl_xor_sync(0xffffffffu, sq, o);
    float inv = rsqrtf(sq * (1.0f / 128.0f) + 1e-5f);
#pragma unroll
    for (int i = 0; i < 4; i++) {
        int d = lane + 32 * i;
        float y = (v[i] - mu) * inv * s[d] + b[d];
        size_t o = (size_t)row * D + d;
        split_bf(y, oh[o], ol[o]);
    }
}

// ---------------- bf16x3 GEMM: ldmatrix + cp.async, BM=128 BN=64 BK=16 ----------------
#define STG_B   18432
#define OFF_AL  6144
#define OFF_WH  12288
#define OFF_WL  15360
#define GEMM_SMEM (3 * STG_B)

__global__ __launch_bounds__(256) void tgemm_kernel(
    const bf16* __restrict__ Ah, const bf16* __restrict__ Al,
    const bf16* __restrict__ Wh, const bf16* __restrict__ Wl, int K,
    const float* __restrict__ bias,
    float* __restrict__ outf, int ldo,
    bf16* __restrict__ oh, bf16* __restrict__ ol, int ldh,
    const float* __restrict__ resid, int mode) {
    extern __shared__ __align__(16) char sm[];
    uint32_t sb = smem_u32(sm);
    const int tid = threadIdx.x, lane = tid & 31, wid = tid >> 5;
    const int bm = blockIdx.y * 128, bn = blockIdx.x * 64;
    const int wm = (wid & 3) * 32, wn = (wid >> 2) * 32;
    const int nst = K >> 4;

    const bf16* Abh = Ah + (size_t)bm * K;
    const bf16* Abl = Al + (size_t)bm * K;
    const bf16* Wb  = (tid >= 128) ? (Wl + (size_t)bn * K) : (Wh + (size_t)bn * K);
    const uint32_t woffs = (tid >= 128) ? OFF_WL : OFF_WH;

    const int am = tid & 127, ahh = tid >> 7;
    const int wnr = tid & 63, whh = (tid >> 6) & 1;
    const uint32_t a_dst0 = (uint32_t)(am * 48 + ahh * 16);
    const uint32_t w_dst0 = woffs + (uint32_t)(wnr * 48 + whh * 16);
    const size_t a_src0 = (size_t)am * K + ahh * 8;
    const size_t w_src0 = (size_t)wnr * K + whh * 8;

    float acc[2][4][4];
#pragma unroll
    for (int i = 0; i < 2; i++)
#pragma unroll
        for (int j = 0; j < 4; j++)
#pragma unroll
            for (int c = 0; c < 4; c++) acc[i][j][c] = 0.f;

    const uint32_t aoff = (uint32_t)((lane & 15) * 48 + (lane >> 4) * 16);
    const uint32_t boff = (uint32_t)(((((lane >> 4) << 3) + (lane & 7)) * 48) + ((lane >> 3) & 1) * 16);

#define LOAD_STAGE(s) do { \
    uint32_t base_ = sb + ((s) % 3) * STG_B; \
    int ko_ = (s) * 16; \
    cp16(base_ + a_dst0,          Abh + a_src0 + ko_); \
    cp16(base_ + OFF_AL + a_dst0, Abl + a_src0 + ko_); \
    cp16(base_ + w_dst0,          Wb  + w_src0 + ko_); \
} while (0)

    LOAD_STAGE(0); CP_COMMIT();
    if (nst > 1) { LOAD_STAGE(1); CP_COMMIT(); }

    for (int s = 0; s < nst; s++) {
        if (s + 2 < nst)      { LOAD_STAGE(s + 2); CP_COMMIT(); CP_WAIT(2); }
        else if (s + 1 < nst) { CP_WAIT(1); }
        else                  { CP_WAIT(0); }
        __syncthreads();
        uint32_t base = sb + (s % 3) * STG_B;

        uint32_t fah[2][4], fal[2][4], fbh[2][4], fbl[2][4];
#pragma unroll
        for (int mi = 0; mi < 2; mi++) {
            uint32_t ad = base + (uint32_t)((wm + mi * 16) * 48) + aoff;
            ldsm4(fah[mi], ad);
            ldsm4(fal[mi], ad + OFF_AL);
        }
#pragma unroll
        for (int nj = 0; nj < 2; nj++) {
            uint32_t bd = base + OFF_WH + (uint32_t)((wn + nj * 16) * 48) + boff;
            ldsm4(fbh[nj], bd);
            ldsm4(fbl[nj], bd + (OFF_WL - OFF_WH));
        }
#pragma unroll
        for (int mi = 0; mi < 2; mi++)
#pragma unroll
            for (int nj = 0; nj < 2; nj++) {
                float* c0 = acc[mi][nj * 2];
                float* c1 = acc[mi][nj * 2 + 1];
                mma_bf16(c0, fah[mi], fbh[nj][0], fbh[nj][1]);
                mma_bf16(c0, fal[mi], fbh[nj][0], fbh[nj][1]);
                mma_bf16(c0, fah[mi], fbl[nj][0], fbl[nj][1]);
                mma_bf16(c1, fah[mi], fbh[nj][2], fbh[nj][3]);
                mma_bf16(c1, fal[mi], fbh[nj][2], fbh[nj][3]);
                mma_bf16(c1, fah[mi], fbl[nj][2], fbl[nj][3]);
            }
        __syncthreads();
    }

#pragma unroll
    for (int mi = 0; mi < 2; mi++) {
        int r0 = bm + wm + mi * 16 + (lane >> 2);
        int r1 = r0 + 8;
#pragma unroll
        for (int ni = 0; ni < 4; ni++) {
            int col = bn + wn + ni * 8 + 2 * (lane & 3);
            float b0 = bias[col], b1 = bias[col + 1];
            float v0 = acc[mi][ni][0] + b0, v1 = acc[mi][ni][1] + b1;
            float v2 = acc[mi][ni][2] + b0, v3 = acc[mi][ni][3] + b1;
            if (mode == 0) {
                size_t o0 = (size_t)r0 * ldo + col, o1 = (size_t)r1 * ldo + col;
                *(float2*)&outf[o0] = make_float2(v0, v1);
                *(float2*)&outf[o1] = make_float2(v2, v3);
            } else if (mode == 1) {
                size_t o0 = (size_t)r0 * 128 + col, o1 = (size_t)r1 * 128 + col;
                v0 += resid[o0]; v1 += resid[o0 + 1];
                v2 += resid[o1]; v3 += resid[o1 + 1];
                *(float2*)&outf[o0] = make_float2(v0, v1);
                *(float2*)&outf[o1] = make_float2(v2, v3);
            } else {
                v0 = gelu_exact(v0); v1 = gelu_exact(v1);
                v2 = gelu_exact(v2); v3 = gelu_exact(v3);
                bf16 h0, l0, h1, l1;
                size_t o0 = (size_t)r0 * ldh + col, o1 = (size_t)r1 * ldh + col;
                split_bf(v0, h0, l0); split_bf(v1, h1, l1);
                __nv_bfloat162 ph{h0, h1}, pl{l0, l1};
                *(__nv_bfloat162*)&oh[o0] = ph;
                *(__nv_bfloat162*)&ol[o0] = pl;
                split_bf(v2, h0, l0); split_bf(v3, h1, l1);
                __nv_bfloat162 qh2{h0, h1}, ql2{l0, l1};
                *(__nv_bfloat162*)&oh[o1] = qh2;
                *(__nv_bfloat162*)&ol[o1] = ql2;
            }
        }
    }
#undef LOAD_STAGE
}

// ---------------- dense 12-node attention, float4-vectorized ----------------
__global__ __launch_bounds__(64) void attn_kernel(const float* __restrict__ qkv,
                                                  const float* __restrict__ edge_bias,
                                                  bf16* __restrict__ mh, bf16* __restrict__ ml) {
    __shared__ float4 sk[NODES * 32];
    __shared__ float4 sv[NODES * 32];
    __shared__ float seb[36];
    int b = blockIdx.x;
    const float4* q4 = (const float4*)(qkv + (size_t)b * NODES * 384);
    for (int i = threadIdx.x; i < NODES * 32; i += 64) {
        int node = i >> 5, c = i & 31;
        sk[i] = q4[node * 96 + 32 + c];
        sv[i] = q4[node * 96 + 64 + c];
    }
    if (threadIdx.x < 36) seb[threadIdx.x] = edge_bias[threadIdx.x];
    __syncthreads();
    int tt = threadIdx.x;
    if (tt >= NODES * NHEAD) return;
    int dst = tt >> 2, hd = tt & 3;
    int kd = dst < 6 ? 0 : (dst < 11 ? 1 : 2);

    float4 q[8];
    const float4* qp = q4 + dst * 96 + hd * 8;
#pragma unroll
    for (int i = 0; i < 8; i++) q[i] = qp[i];

    float logits[NODES];
    float mx = -1e30f;
#pragma unroll
    for (int j = 0; j < NODES; j++) {
        const float4* kp = &sk[j * 32 + hd * 8];
        float d0 = 0.f, d1 = 0.f, d2 = 0.f, d3 = 0.f;
#pragma unroll
        for (int i = 0; i < 8; i++) {
            float4 kv = kp[i];
            d0 = fmaf(q[i].x, kv.x, d0);
            d1 = fmaf(q[i].y, kv.y, d1);
            d2 = fmaf(q[i].z, kv.z, d2);
            d3 = fmaf(q[i].w, kv.w, d3);
        }
        int ks = j < 6 ? 0 : (j < 11 ? 1 : 2);
        float lg = ((d0 + d1) + (d2 + d3)) * SCALE + seb[(ks * 3 + kd) * NHEAD + hd];
        logits[j] = lg;
        mx = fmaxf(mx, lg);
    }
    float z = 0.f;
#pragma unroll
    for (int j = 0; j < NODES; j++) { logits[j] = __expf(logits[j] - mx); z += logits[j]; }
    float inv = 1.0f / z;

    float4 out[8];
#pragma unroll
    for (int i = 0; i < 8; i++) out[i] = make_float4(0.f, 0.f, 0.f, 0.f);
#pragma unroll
    for (int j = 0; j < NODES; j++) {
        float a = logits[j] * inv;
        const float4* vp = &sv[j * 32 + hd * 8];
#pragma unroll
        for (int i = 0; i < 8; i++) {
            float4 vv = vp[i];
            out[i].x = fmaf(a, vv.x, out[i].x);
            out[i].y = fmaf(a, vv.y, out[i].y);
            out[i].z = fmaf(a, vv.z, out[i].z);
            out[i].w = fmaf(a, vv.w, out[i].w);
        }
    }
    size_t ob = (size_t)b * NODES * D + dst * D + hd * DH;
#pragma unroll
    for (int i = 0; i < 8; i++) {
        bf16 h0, l0, h1, l1, h2, l2, h3, l3;
        split_bf(out[i].x, h0, l0); split_bf(out[i].y, h1, l1);
        split_bf(out[i].z, h2, l2); split_bf(out[i].w, h3, l3);
        __nv_bfloat162 pa{h0, h1}, pb{h2, h3}, pc{l0, l1}, pd{l2, l3};
        uint2 uh{*(uint32_t*)&pa, *(uint32_t*)&pb};
        uint2 ul{*(uint32_t*)&pc, *(uint32_t*)&pd};
        *(uint2*)(mh + ob + i * 4) = uh;
        *(uint2*)(ml + ob + i * 4) = ul;
    }
}

// ---------------- final: gate/pool + proj + LN + gelu ----------------
__global__ void final_kernel(const float* __restrict__ x,
                             const float* __restrict__ gate_w, const float* __restrict__ gate_b,
                             const float* __restrict__ proj_w, const float* __restrict__ proj_b,
                             const float* __restrict__ pln_s, const float* __restrict__ pln_b,
                             float* __restrict__ out) {
    __shared__ float sx[NODES * D];
    __shared__ float sgate[NODES];
    __shared__ float comb[2 * D];
    __shared__ float red[4];
    int b = blockIdx.x, tid = threadIdx.x;
    for (int i = tid; i < NODES * D; i += 128) sx[i] = x[(size_t)b * NODES * D + i];
    __syncthreads();
    if (tid < NODES) {
        float acc = gate_b[0];
#pragma unroll 8
        for (int d = 0; d < D; d++) acc = fmaf(sx[tid * D + d], gate_w[d], acc);
        sgate[tid] = 1.0f / (1.0f + __expf(-acc));
    }
    __syncthreads();
    float pooled = 0.f;
#pragma unroll
    for (int n = 0; n < NODES; n++) pooled = fmaf(sx[n * D + tid], sgate[n], pooled);
    comb[tid]     = sx[11 * D + tid];
    comb[D + tid] = pooled;
    __syncthreads();
    float y = proj_b[tid];
#pragma unroll 8
    for (int c = 0; c < 2 * D; c++) y = fmaf(comb[c], proj_w[c * D + tid], y);
    float sum = y;
#pragma unroll
    for (int o = 16; o; o >>= 1) sum += __shfl_xor_sync(0xffffffffu, sum, o);
    if ((tid & 31) == 0) red[tid >> 5] = sum;
    __syncthreads();
    float mu = (red[0] + red[1] + red[2] + red[3]) * (1.0f / 128.0f);
    float c0 = y - mu;
    float cs = c0 * c0;
#pragma unroll
    for (int o = 16; o; o >>= 1) cs += __shfl_xor_sync(0xffffffffu, cs, o);
    __syncthreads();
    if ((tid & 31) == 0) red[tid >> 5] = cs;
    __syncthreads();
    float var = (red[0] + red[1] + red[2] + red[3]) * (1.0f / 128.0f);
    float yn = c0 * rsqrtf(var + 1e-5f) * pln_s[tid] + pln_b[tid];
    out[(size_t)b * D + tid] = gelu_exact(yn);
}

// ---------------- host orchestration ----------------
extern "C" void kernel_launch(void* const* d_in, const int* in_sizes, int n_in,
                              void* d_out, int out_size) {
    const float* patch   = (const float*)d_in[0];
    const float* band    = (const float*)d_in[1];
    const float* summ    = (const float*)d_in[2];
    const float* ln1_s   = (const float*)d_in[3];
    const float* ln1_b   = (const float*)d_in[4];
    const float* wq      = (const float*)d_in[5];
    const float* bq      = (const float*)d_in[6];
    const float* wk      = (const float*)d_in[7];
    const float* bk      = (const float*)d_in[8];
    const float* wv      = (const float*)d_in[9];
    const float* bv      = (const float*)d_in[10];
    const float* wo      = (const float*)d_in[11];
    const float* bo      = (const float*)d_in[12];
    const float* edge_b  = (const float*)d_in[13];
    const float* ln2_s   = (const float*)d_in[14];
    const float* ln2_b   = (const float*)d_in[15];
    const float* w1      = (const float*)d_in[16];
    const float* b1      = (const float*)d_in[17];
    const float* w2      = (const float*)d_in[18];
    const float* b2      = (const float*)d_in[19];
    const float* gate_w  = (const float*)d_in[20];
    const float* gate_b  = (const float*)d_in[21];
    const float* proj_w  = (const float*)d_in[22];
    const float* proj_b  = (const float*)d_in[23];
    const float* pln_s   = (const float*)d_in[24];
    const float* pln_b   = (const float*)d_in[25];
    float* out = (float*)d_out;

    float *x, *qkv, *bqkv;
    bf16 *hh, *hl, *mh, *ml, *th, *tl;
    bf16 *wqkvh, *wqkvl, *woh, *wol, *w1h, *w1l, *w2h, *w2l;
    cudaGetSymbolAddress((void**)&x,     g_x);
    cudaGetSymbolAddress((void**)&qkv,   g_qkv);
    cudaGetSymbolAddress((void**)&bqkv,  g_bqkv);
    cudaGetSymbolAddress((void**)&hh,    g_hh);
    cudaGetSymbolAddress((void**)&hl,    g_hl);
    cudaGetSymbolAddress((void**)&mh,    g_mh);
    cudaGetSymbolAddress((void**)&ml,    g_ml);
    cudaGetSymbolAddress((void**)&th,    g_th);
    cudaGetSymbolAddress((void**)&tl,    g_tl);
    cudaGetSymbolAddress((void**)&wqkvh, g_wqkvh);
    cudaGetSymbolAddress((void**)&wqkvl, g_wqkvl);
    cudaGetSymbolAddress((void**)&woh,   g_woh);
    cudaGetSymbolAddress((void**)&wol,   g_wol);
    cudaGetSymbolAddress((void**)&w1h,   g_w1h);
    cudaGetSymbolAddress((void**)&w1l,   g_w1l);
    cudaGetSymbolAddress((void**)&w2h,   g_w2h);
    cudaGetSymbolAddress((void**)&w2l,   g_w2l);

    static int smem_set = 0;
    if (!smem_set) {
        cudaFuncSetAttribute(tgemm_kernel, cudaFuncAttributeMaxDynamicSharedMemorySize, GEMM_SMEM);
        smem_set = 1;
    }

    // launches 1-3 (so the QKV GEMM is launch #4 for ncu -s 5 capture window)
    init_ln_kernel<<<NTOK / 4, 128>>>(patch, band, summ, ln1_s, ln1_b, x, hh, hl);
    pack_qkvw_kernel<<<(98304 + 255) / 256, 256>>>(wq, wk, wv, bq, bk, bv, wqkvh, wqkvl, bqkv);
    pack_rest_kernel<<<(294912 + 255) / 256, 256>>>(wo, w1, w2, woh, wol, w1h, w1l, w2h, w2l);

    const int MT = NTOK / 128; // 192
    for (int l = 0; l < 2; l++) {
        // QKV (mode 0): N=384
        tgemm_kernel<<<dim3(6, MT), 256, GEMM_SMEM>>>(
            hh, hl, wqkvh + (size_t)l * 384 * 128, wqkvl + (size_t)l * 384 * 128, 128,
            bqkv + l * 384, qkv, 384, nullptr, nullptr, 0, nullptr, 0);
        attn_kernel<<<BATCH, 64>>>(qkv, edge_b + l * 36, mh, ml);
        // O-proj + residual (mode 1): N=128
        tgemm_kernel<<<dim3(2, MT), 256, GEMM_SMEM>>>(
            mh, ml, woh + (size_t)l * 128 * 128, wol + (size_t)l * 128 * 128, 128,
            bo + l * 128, x, 128, nullptr, nullptr, 0, x, 1);
        ln_split_kernel<<<NTOK / 4, 128>>>(x, hh, hl, ln2_s + l * 128, ln2_b + l * 128);
        // FFN1 + GELU (mode 2): N=512
        tgemm_kernel<<<dim3(8, MT), 256, GEMM_SMEM>>>(
            hh, hl, w1h + (size_t)l * 512 * 128, w1l + (size_t)l * 512 * 128, 128,
            b1 + l * 512, nullptr, 0, th, tl, 512, nullptr, 2);
        // FFN2 + residual (mode 1): N=128, K=512
        tgemm_kernel<<<dim3(2, MT), 256, GEMM_SMEM>>>(
            th, tl, w2h + (size_t)l * 128 * 512, w2l + (size_t)l * 128 * 512, 512,
            b2 + l * 128, x, 128, nullptr, nullptr, 0, x, 1);
        if (l == 0)
            ln_split_kernel<<<NTOK / 4, 128>>>(x, hh, hl, ln1_s + 128, ln1_b + 128);
    }

    final_kernel<<<BATCH, 128>>>(x, gate_w, gate_b, proj_w, proj_b, pln_s, pln_b, out);
}

// round 7
// speedup vs baseline: 1.1643x; 1.0678x over previous
#include <cuda_runtime.h>
#include <cuda_bf16.h>
#include <math.h>
#include <stdint.h>

#define BATCH      2048
#define NODES      12
#define NTOK       (BATCH * NODES)     // 24576
#define D          128
#define F          512
#define NHEAD      4
#define DH         32
#define SCALE      0.17677669529663687f

typedef __nv_bfloat16 bf16;

// ---------------- scratch (device globals; no allocation) ----------------
__device__ __align__(16) float g_x   [NTOK * D];
__device__ __align__(16) float g_qkv [NTOK * 384];
__device__ __align__(16) bf16 g_hh[NTOK * D],  g_hl[NTOK * D];
__device__ __align__(16) bf16 g_mh[NTOK * D],  g_ml[NTOK * D];
__device__ __align__(16) bf16 g_th[NTOK * F],  g_tl[NTOK * F];
__device__ __align__(16) bf16 g_wqkvh[2 * 384 * D], g_wqkvl[2 * 384 * D]; // [l][n][k]
__device__ __align__(16) bf16 g_woh[2 * D * D],     g_wol[2 * D * D];
__device__ __align__(16) bf16 g_w1h[2 * F * D],     g_w1l[2 * F * D];
__device__ __align__(16) bf16 g_w2h[2 * D * F],     g_w2l[2 * D * F];
__device__ float g_bqkv[2 * 384];

__device__ __forceinline__ float gelu_exact(float x) {
    return 0.5f * x * (1.0f + erff(x * 0.7071067811865476f));
}
__device__ __forceinline__ void split_bf(float x, bf16& h, bf16& l) {
    h = __float2bfloat16(x);
    l = __float2bfloat16(x - __bfloat162float(h));
}
__device__ __forceinline__ uint32_t smem_u32(const void* p) {
    uint32_t a;
    asm("{ .reg .u64 t; cvta.to.shared.u64 t, %1; cvt.u32.u64 %0, t; }" : "=r"(a) : "l"(p));
    return a;
}
__device__ __forceinline__ void cp16(uint32_t dst, const void* src) {
    asm volatile("cp.async.ca.shared.global [%0], [%1], 16;" :: "r"(dst), "l"(src));
}
#define CP_COMMIT() asm volatile("cp.async.commit_group;" ::: "memory")
#define CP_WAIT(n)  asm volatile("cp.async.wait_group %0;" :: "n"(n) : "memory")

__device__ __forceinline__ void ldsm4(uint32_t* r, uint32_t addr) {
    asm volatile("ldmatrix.sync.aligned.m8n8.x4.shared.b16 {%0,%1,%2,%3}, [%4];"
        : "=r"(r[0]), "=r"(r[1]), "=r"(r[2]), "=r"(r[3]) : "r"(addr));
}
__device__ __forceinline__ void mma_bf16(float* c, const uint32_t* a, uint32_t b0, uint32_t b1) {
    asm volatile(
        "mma.sync.aligned.m16n8k16.row.col.f32.bf16.bf16.f32 "
        "{%0,%1,%2,%3}, {%4,%5,%6,%7}, {%8,%9}, {%0,%1,%2,%3};"
        : "+f"(c[0]), "+f"(c[1]), "+f"(c[2]), "+f"(c[3])
        : "r"(a[0]), "r"(a[1]), "r"(a[2]), "r"(a[3]), "r"(b0), "r"(b1));
}

// ---------------- init + layer0 LN1 ----------------
__global__ void init_ln_kernel(const float* __restrict__ patch,
                               const float* __restrict__ band,
                               const float* __restrict__ summ,
                               const float* __restrict__ s, const float* __restrict__ b,
                               float* __restrict__ x,
                               bf16* __restrict__ oh, bf16* __restrict__ ol) {
    int row  = blockIdx.x * 4 + (threadIdx.x >> 5);
    int lane = threadIdx.x & 31;
    int node = row % NODES;
    int bb   = row / NODES;
    float v[4];
    float sum = 0.f;
#pragma unroll
    for (int i = 0; i < 4; i++) {
        int d = lane + 32 * i;
        float val;
        if (node < 6)       val = patch[(size_t)(bb * 6 + node) * D + d];
        else if (node < 11) val = band [(size_t)(bb * 5 + (node - 6)) * D + d];
        else                val = summ[d];
        v[i] = val;
        x[(size_t)row * D + d] = val;
        sum += val;
    }
#pragma unroll
    for (int o = 16; o; o >>= 1) sum += __shfl_xor_sync(0xffffffffu, sum, o);
    float mu = sum * (1.0f / 128.0f);
    float sq = 0.f;
#pragma unroll
    for (int i = 0; i < 4; i++) { float c = v[i] - mu; sq += c * c; }
#pragma unroll
    for (int o = 16; o; o >>= 1) sq += __shfl_xor_sync(0xffffffffu, sq, o);
    float inv = rsqrtf(sq * (1.0f / 128.0f) + 1e-5f);
#pragma unroll
    for (int i = 0; i < 4; i++) {
        int d = lane + 32 * i;
        float y = (v[i] - mu) * inv * s[d] + b[d];
        size_t o = (size_t)row * D + d;
        split_bf(y, oh[o], ol[o]);
    }
}

// ---------------- weight packing (two kernels so QKV GEMM is launch #4) ----------------
__global__ void pack_qkvw_kernel(const float* __restrict__ wq, const float* __restrict__ wk,
                                 const float* __restrict__ wv,
                                 const float* __restrict__ bq, const float* __restrict__ bk,
                                 const float* __restrict__ bv,
                                 bf16* __restrict__ qh, bf16* __restrict__ ql,
                                 float* __restrict__ bqkv) {
    int idx = blockIdx.x * 256 + threadIdx.x;
    if (idx < 98304) { // wqkv: [l][n<384][k<128]
        int l = idx / 49152, r = idx % 49152;
        int n = r / 128, k = r % 128;
        const float* src = (n < 128) ? wq : ((n < 256) ? wk : wv);
        float v = src[(size_t)l * 16384 + k * 128 + (n & 127)];
        split_bf(v, qh[idx], ql[idx]);
    }
    if (idx < 768) {
        int l = idx / 384, n = idx % 384;
        const float* sb = (n < 128) ? bq : ((n < 256) ? bk : bv);
        bqkv[idx] = sb[l * 128 + (n & 127)];
    }
}
__global__ void pack_rest_kernel(const float* __restrict__ wo,
                                 const float* __restrict__ w1, const float* __restrict__ w2,
                                 bf16* __restrict__ oh, bf16* __restrict__ ol,
                                 bf16* __restrict__ h1, bf16* __restrict__ l1,
                                 bf16* __restrict__ h2, bf16* __restrict__ l2) {
    int idx = blockIdx.x * 256 + threadIdx.x;
    if (idx < 32768) { // wo: [l][n<128][k<128]
        int l = idx / 16384, r = idx % 16384;
        int n = r / 128, k = r % 128;
        float v = wo[(size_t)l * 16384 + k * 128 + n];
        split_bf(v, oh[idx], ol[idx]);
    } else if (idx < 163840) { // w1: [l][n<512][k<128]  src [l][k<128][n<512]
        int t = idx - 32768;
        int l = t / 65536, r = t % 65536;
        int n = r / 128, k = r % 128;
        float v = w1[(size_t)l * 65536 + (size_t)k * 512 + n];
        split_bf(v, h1[t], l1[t]);
    } else if (idx < 294912) { // w2: [l][n<128][k<512]  src [l][k<512][n<128]
        int t = idx - 163840;
        int l = t / 65536, r = t % 65536;
        int n = r / 512, k = r % 512;
        float v = w2[(size_t)l * 65536 + (size_t)k * 128 + n];
        split_bf(v, h2[t], l2[t]);
    }
}

// ---------------- LayerNorm + bf16 split output ----------------
__global__ void ln_split_kernel(const float* __restrict__ in, bf16* __restrict__ oh,
                                bf16* __restrict__ ol,
                                const float* __restrict__ s, const float* __restrict__ b) {
    int row  = blockIdx.x * 4 + (threadIdx.x >> 5);
    int lane = threadIdx.x & 31;
    const float* rp = in + (size_t)row * D;
    float v[4];
    float sum = 0.f;
#pragma unroll
    for (int i = 0; i < 4; i++) { v[i] = rp[lane + 32 * i]; sum += v[i]; }
#pragma unroll
    for (int o = 16; o; o >>= 1) sum += __shfl_xor_sync(0xffffffffu, sum, o);
    float mu = sum * (1.0f / 128.0f);
    float sq = 0.f;
#pragma unroll
    for (int i = 0; i < 4; i++) { float c = v[i] - mu; sq += c * c; }
#pragma unroll
    for (int o = 16; o; o >>= 1) sq += __shfl_xor_sync(0xffffffffu, sq, o);
    float inv = rsqrtf(sq * (1.0f / 128.0f) + 1e-5f);
#pragma unroll
    for (int i = 0; i < 4; i++) {
        int d = lane + 32 * i;
        float y = (v[i] - mu) * inv * s[d] + b[d];
        size_t o = (size_t)row * D + d;
        split_bf(y, oh[o], ol[o]);
    }
}

// ---------------- bf16x3 GEMM: BM=128 BN=128 BK=16, 512 thr, coalesced cp.async ----------
// smem stage: Ah(128x48B) | Al | Wh | Wl  = 24576 B; 3 stages = 73728 B
#define STG_B   24576
#define OFF_AL  6144
#define OFF_WH  12288
#define OFF_WL  18432
#define GEMM_SMEM (3 * STG_B)

__global__ __launch_bounds__(512) void tgemm_kernel(
    const bf16* __restrict__ Ah, const bf16* __restrict__ Al,
    const bf16* __restrict__ Wh, const bf16* __restrict__ Wl, int K,
    const float* __restrict__ bias,
    float* __restrict__ outf, int ldo,
    bf16* __restrict__ oh, bf16* __restrict__ ol, int ldh,
    const float* __restrict__ resid, int mode) {
    extern __shared__ __align__(16) char sm[];
    uint32_t sb = smem_u32(sm);
    const int tid = threadIdx.x, lane = tid & 31, wid = tid >> 5;
    const int bm = blockIdx.y * 128, bn = blockIdx.x * 128;
    const int wm = (wid & 3) * 32, wn = (wid >> 2) * 32;
    const int nst = K >> 4;

    // coalesced load mapping: pair-threads fetch contiguous 32B of one row.
    // tid<256 -> A rows, tid>=256 -> W rows; each thread does hi then lo.
    const int lrow = (tid & 255) >> 1;       // 0..127
    const int lhalf = tid & 1;               // 0..1
    const bool isA = tid < 256;
    const bf16* srcH = isA ? (Ah + (size_t)(bm + lrow) * K + lhalf * 8)
                           : (Wh + (size_t)(bn + lrow) * K + lhalf * 8);
    const bf16* srcL = isA ? (Al + (size_t)(bm + lrow) * K + lhalf * 8)
                           : (Wl + (size_t)(bn + lrow) * K + lhalf * 8);
    const uint32_t dstH = (isA ? 0u : (uint32_t)OFF_WH) + (uint32_t)(lrow * 48 + lhalf * 16);
    const uint32_t dstL = dstH + OFF_AL;     // Al is +6144 from Ah; Wl is +6144 from Wh

    float acc[2][4][4];
#pragma unroll
    for (int i = 0; i < 2; i++)
#pragma unroll
        for (int j = 0; j < 4; j++)
#pragma unroll
            for (int c = 0; c < 4; c++) acc[i][j][c] = 0.f;

    const uint32_t aoff = (uint32_t)((lane & 15) * 48 + (lane >> 4) * 16);
    const uint32_t boff = (uint32_t)(((((lane >> 4) << 3) + (lane & 7)) * 48) + ((lane >> 3) & 1) * 16);

#define LOAD_STAGE(s) do { \
    uint32_t base_ = sb + ((s) % 3) * STG_B; \
    int ko_ = (s) * 16; \
    cp16(base_ + dstH, srcH + ko_); \
    cp16(base_ + dstL, srcL + ko_); \
} while (0)

    LOAD_STAGE(0); CP_COMMIT();
    if (nst > 1) { LOAD_STAGE(1); CP_COMMIT(); }

    for (int s = 0; s < nst; s++) {
        if (s + 2 < nst)      { LOAD_STAGE(s + 2); CP_COMMIT(); CP_WAIT(2); }
        else if (s + 1 < nst) { CP_WAIT(1); }
        else                  { CP_WAIT(0); }
        __syncthreads();
        uint32_t base = sb + (s % 3) * STG_B;

        uint32_t fah[2][4], fal[2][4], fbh[2][4], fbl[2][4];
#pragma unroll
        for (int mi = 0; mi < 2; mi++) {
            uint32_t ad = base + (uint32_t)((wm + mi * 16) * 48) + aoff;
            ldsm4(fah[mi], ad);
            ldsm4(fal[mi], ad + OFF_AL);
        }
#pragma unroll
        for (int nj = 0; nj < 2; nj++) {
            uint32_t bd = base + OFF_WH + (uint32_t)((wn + nj * 16) * 48) + boff;
            ldsm4(fbh[nj], bd);
            ldsm4(fbl[nj], bd + (OFF_WL - OFF_WH));
        }
#pragma unroll
        for (int mi = 0; mi < 2; mi++)
#pragma unroll
            for (int nj = 0; nj < 2; nj++) {
                float* c0 = acc[mi][nj * 2];
                float* c1 = acc[mi][nj * 2 + 1];
                mma_bf16(c0, fah[mi], fbh[nj][0], fbh[nj][1]);
                mma_bf16(c0, fal[mi], fbh[nj][0], fbh[nj][1]);
                mma_bf16(c0, fah[mi], fbl[nj][0], fbl[nj][1]);
                mma_bf16(c1, fah[mi], fbh[nj][2], fbh[nj][3]);
                mma_bf16(c1, fal[mi], fbh[nj][2], fbh[nj][3]);
                mma_bf16(c1, fah[mi], fbl[nj][2], fbl[nj][3]);
            }
        __syncthreads();
    }

#pragma unroll
    for (int mi = 0; mi < 2; mi++) {
        int r0 = bm + wm + mi * 16 + (lane >> 2);
        int r1 = r0 + 8;
#pragma unroll
        for (int ni = 0; ni < 4; ni++) {
            int col = bn + wn + ni * 8 + 2 * (lane & 3);
            float b0 = bias[col], b1 = bias[col + 1];
            float v0 = acc[mi][ni][0] + b0, v1 = acc[mi][ni][1] + b1;
            float v2 = acc[mi][ni][2] + b0, v3 = acc[mi][ni][3] + b1;
            if (mode == 0) {
                size_t o0 = (size_t)r0 * ldo + col, o1 = (size_t)r1 * ldo + col;
                *(float2*)&outf[o0] = make_float2(v0, v1);
                *(float2*)&outf[o1] = make_float2(v2, v3);
            } else if (mode == 1) {
                size_t o0 = (size_t)r0 * 128 + col, o1 = (size_t)r1 * 128 + col;
                v0 += resid[o0]; v1 += resid[o0 + 1];
                v2 += resid[o1]; v3 += resid[o1 + 1];
                *(float2*)&outf[o0] = make_float2(v0, v1);
                *(float2*)&outf[o1] = make_float2(v2, v3);
            } else {
                v0 = gelu_exact(v0); v1 = gelu_exact(v1);
                v2 = gelu_exact(v2); v3 = gelu_exact(v3);
                bf16 h0, l0, h1, l1;
                size_t o0 = (size_t)r0 * ldh + col, o1 = (size_t)r1 * ldh + col;
                split_bf(v0, h0, l0); split_bf(v1, h1, l1);
                __nv_bfloat162 ph{h0, h1}, pl{l0, l1};
                *(__nv_bfloat162*)&oh[o0] = ph;
                *(__nv_bfloat162*)&ol[o0] = pl;
                split_bf(v2, h0, l0); split_bf(v3, h1, l1);
                __nv_bfloat162 qh2{h0, h1}, ql2{l0, l1};
                *(__nv_bfloat162*)&oh[o1] = qh2;
                *(__nv_bfloat162*)&ol[o1] = ql2;
            }
        }
    }
#undef LOAD_STAGE
}

// ---------------- dense 12-node attention, float4-vectorized ----------------
__global__ __launch_bounds__(64) void attn_kernel(const float* __restrict__ qkv,
                                                  const float* __restrict__ edge_bias,
                                                  bf16* __restrict__ mh, bf16* __restrict__ ml) {
    __shared__ float4 sk[NODES * 32];
    __shared__ float4 sv[NODES * 32];
    __shared__ float seb[36];
    int b = blockIdx.x;
    const float4* q4 = (const float4*)(qkv + (size_t)b * NODES * 384);
    for (int i = threadIdx.x; i < NODES * 32; i += 64) {
        int node = i >> 5, c = i & 31;
        sk[i] = q4[node * 96 + 32 + c];
        sv[i] = q4[node * 96 + 64 + c];
    }
    if (threadIdx.x < 36) seb[threadIdx.x] = edge_bias[threadIdx.x];
    __syncthreads();
    int tt = threadIdx.x;
    if (tt >= NODES * NHEAD) return;
    int dst = tt >> 2, hd = tt & 3;
    int kd = dst < 6 ? 0 : (dst < 11 ? 1 : 2);

    float4 q[8];
    const float4* qp = q4 + dst * 96 + hd * 8;
#pragma unroll
    for (int i = 0; i < 8; i++) q[i] = qp[i];

    float logits[NODES];
    float mx = -1e30f;
#pragma unroll
    for (int j = 0; j < NODES; j++) {
        const float4* kp = &sk[j * 32 + hd * 8];
        float d0 = 0.f, d1 = 0.f, d2 = 0.f, d3 = 0.f;
#pragma unroll
        for (int i = 0; i < 8; i++) {
            float4 kv = kp[i];
            d0 = fmaf(q[i].x, kv.x, d0);
            d1 = fmaf(q[i].y, kv.y, d1);
            d2 = fmaf(q[i].z, kv.z, d2);
            d3 = fmaf(q[i].w, kv.w, d3);
        }
        int ks = j < 6 ? 0 : (j < 11 ? 1 : 2);
        float lg = ((d0 + d1) + (d2 + d3)) * SCALE + seb[(ks * 3 + kd) * NHEAD + hd];
        logits[j] = lg;
        mx = fmaxf(mx, lg);
    }
    float z = 0.f;
#pragma unroll
    for (int j = 0; j < NODES; j++) { logits[j] = __expf(logits[j] - mx); z += logits[j]; }
    float inv = 1.0f / z;

    float4 out[8];
#pragma unroll
    for (int i = 0; i < 8; i++) out[i] = make_float4(0.f, 0.f, 0.f, 0.f);
#pragma unroll
    for (int j = 0; j < NODES; j++) {
        float a = logits[j] * inv;
        const float4* vp = &sv[j * 32 + hd * 8];
#pragma unroll
        for (int i = 0; i < 8; i++) {
            float4 vv = vp[i];
            out[i].x = fmaf(a, vv.x, out[i].x);
            out[i].y = fmaf(a, vv.y, out[i].y);
            out[i].z = fmaf(a, vv.z, out[i].z);
            out[i].w = fmaf(a, vv.w, out[i].w);
        }
    }
    size_t ob = (size_t)b * NODES * D + dst * D + hd * DH;
#pragma unroll
    for (int i = 0; i < 8; i++) {
        bf16 h0, l0, h1, l1, h2, l2, h3, l3;
        split_bf(out[i].x, h0, l0); split_bf(out[i].y, h1, l1);
        split_bf(out[i].z, h2, l2); split_bf(out[i].w, h3, l3);
        __nv_bfloat162 pa{h0, h1}, pb{h2, h3}, pc{l0, l1}, pd{l2, l3};
        uint2 uh{*(uint32_t*)&pa, *(uint32_t*)&pb};
        uint2 ul{*(uint32_t*)&pc, *(uint32_t*)&pd};
        *(uint2*)(mh + ob + i * 4) = uh;
        *(uint2*)(ml + ob + i * 4) = ul;
    }
}

// ---------------- final: gate/pool + proj + LN + gelu ----------------
__global__ void final_kernel(const float* __restrict__ x,
                             const float* __restrict__ gate_w, const float* __restrict__ gate_b,
                             const float* __restrict__ proj_w, const float* __restrict__ proj_b,
                             const float* __restrict__ pln_s, const float* __restrict__ pln_b,
                             float* __restrict__ out) {
    __shared__ float sx[NODES * D];
    __shared__ float sgate[NODES];
    __shared__ float comb[2 * D];
    __shared__ float red[4];
    int b = blockIdx.x, tid = threadIdx.x;
    for (int i = tid; i < NODES * D; i += 128) sx[i] = x[(size_t)b * NODES * D + i];
    __syncthreads();
    if (tid < NODES) {
        float acc = gate_b[0];
#pragma unroll 8
        for (int d = 0; d < D; d++) acc = fmaf(sx[tid * D + d], gate_w[d], acc);
        sgate[tid] = 1.0f / (1.0f + __expf(-acc));
    }
    __syncthreads();
    float pooled = 0.f;
#pragma unroll
    for (int n = 0; n < NODES; n++) pooled = fmaf(sx[n * D + tid], sgate[n], pooled);
    comb[tid]     = sx[11 * D + tid];
    comb[D + tid] = pooled;
    __syncthreads();
    float y = proj_b[tid];
#pragma unroll 8
    for (int c = 0; c < 2 * D; c++) y = fmaf(comb[c], proj_w[c * D + tid], y);
    float sum = y;
#pragma unroll
    for (int o = 16; o; o >>= 1) sum += __shfl_xor_sync(0xffffffffu, sum, o);
    if ((tid & 31) == 0) red[tid >> 5] = sum;
    __syncthreads();
    float mu = (red[0] + red[1] + red[2] + red[3]) * (1.0f / 128.0f);
    float c0 = y - mu;
    float cs = c0 * c0;
#pragma unroll
    for (int o = 16; o; o >>= 1) cs += __shfl_xor_sync(0xffffffffu, cs, o);
    __syncthreads();
    if ((tid & 31) == 0) red[tid >> 5] = cs;
    __syncthreads();
    float var = (red[0] + red[1] + red[2] + red[3]) * (1.0f / 128.0f);
    float yn = c0 * rsqrtf(var + 1e-5f) * pln_s[tid] + pln_b[tid];
    out[(size_t)b * D + tid] = gelu_exact(yn);
}

// ---------------- host orchestration ----------------
extern "C" void kernel_launch(void* const* d_in, const int* in_sizes, int n_in,
                              void* d_out, int out_size) {
    const float* patch   = (const float*)d_in[0];
    const float* band    = (const float*)d_in[1];
    const float* summ    = (const float*)d_in[2];
    const float* ln1_s   = (const float*)d_in[3];
    const float* ln1_b   = (const float*)d_in[4];
    const float* wq      = (const float*)d_in[5];
    const float* bq      = (const float*)d_in[6];
    const float* wk      = (const float*)d_in[7];
    const float* bk      = (const float*)d_in[8];
    const float* wv      = (const float*)d_in[9];
    const float* bv      = (const float*)d_in[10];
    const float* wo      = (const float*)d_in[11];
    const float* bo      = (const float*)d_in[12];
    const float* edge_b  = (const float*)d_in[13];
    const float* ln2_s   = (const float*)d_in[14];
    const float* ln2_b   = (const float*)d_in[15];
    const float* w1      = (const float*)d_in[16];
    const float* b1      = (const float*)d_in[17];
    const float* w2      = (const float*)d_in[18];
    const float* b2      = (const float*)d_in[19];
    const float* gate_w  = (const float*)d_in[20];
    const float* gate_b  = (const float*)d_in[21];
    const float* proj_w  = (const float*)d_in[22];
    const float* proj_b  = (const float*)d_in[23];
    const float* pln_s   = (const float*)d_in[24];
    const float* pln_b   = (const float*)d_in[25];
    float* out = (float*)d_out;

    float *x, *qkv, *bqkv;
    bf16 *hh, *hl, *mh, *ml, *th, *tl;
    bf16 *wqkvh, *wqkvl, *woh, *wol, *w1h, *w1l, *w2h, *w2l;
    cudaGetSymbolAddress((void**)&x,     g_x);
    cudaGetSymbolAddress((void**)&qkv,   g_qkv);
    cudaGetSymbolAddress((void**)&bqkv,  g_bqkv);
    cudaGetSymbolAddress((void**)&hh,    g_hh);
    cudaGetSymbolAddress((void**)&hl,    g_hl);
    cudaGetSymbolAddress((void**)&mh,    g_mh);
    cudaGetSymbolAddress((void**)&ml,    g_ml);
    cudaGetSymbolAddress((void**)&th,    g_th);
    cudaGetSymbolAddress((void**)&tl,    g_tl);
    cudaGetSymbolAddress((void**)&wqkvh, g_wqkvh);
    cudaGetSymbolAddress((void**)&wqkvl, g_wqkvl);
    cudaGetSymbolAddress((void**)&woh,   g_woh);
    cudaGetSymbolAddress((void**)&wol,   g_wol);
    cudaGetSymbolAddress((void**)&w1h,   g_w1h);
    cudaGetSymbolAddress((void**)&w1l,   g_w1l);
    cudaGetSymbolAddress((void**)&w2h,   g_w2h);
    cudaGetSymbolAddress((void**)&w2l,   g_w2l);

    static int smem_set = 0;
    if (!smem_set) {
        cudaFuncSetAttribute(tgemm_kernel, cudaFuncAttributeMaxDynamicSharedMemorySize, GEMM_SMEM);
        smem_set = 1;
    }

    // launches 1-3 (so the QKV GEMM is launch #4 for ncu capture)
    init_ln_kernel<<<NTOK / 4, 128>>>(patch, band, summ, ln1_s, ln1_b, x, hh, hl);
    pack_qkvw_kernel<<<(98304 + 255) / 256, 256>>>(wq, wk, wv, bq, bk, bv, wqkvh, wqkvl, bqkv);
    pack_rest_kernel<<<(294912 + 255) / 256, 256>>>(wo, w1, w2, woh, wol, w1h, w1l, w2h, w2l);

    const int MT = NTOK / 128; // 192
    for (int l = 0; l < 2; l++) {
        // QKV (mode 0): N=384
        tgemm_kernel<<<dim3(3, MT), 512, GEMM_SMEM>>>(
            hh, hl, wqkvh + (size_t)l * 384 * 128, wqkvl + (size_t)l * 384 * 128, 128,
            bqkv + l * 384, qkv, 384, nullptr, nullptr, 0, nullptr, 0);
        attn_kernel<<<BATCH, 64>>>(qkv, edge_b + l * 36, mh, ml);
        // O-proj + residual (mode 1): N=128
        tgemm_kernel<<<dim3(1, MT), 512, GEMM_SMEM>>>(
            mh, ml, woh + (size_t)l * 128 * 128, wol + (size_t)l * 128 * 128, 128,
            bo + l * 128, x, 128, nullptr, nullptr, 0, x, 1);
        ln_split_kernel<<<NTOK / 4, 128>>>(x, hh, hl, ln2_s + l * 128, ln2_b + l * 128);
        // FFN1 + GELU (mode 2): N=512
        tgemm_kernel<<<dim3(4, MT), 512, GEMM_SMEM>>>(
            hh, hl, w1h + (size_t)l * 512 * 128, w1l + (size_t)l * 512 * 128, 128,
            b1 + l * 512, nullptr, 0, th, tl, 512, nullptr, 2);
        // FFN2 + residual (mode 1): N=128, K=512
        tgemm_kernel<<<dim3(1, MT), 512, GEMM_SMEM>>>(
            th, tl, w2h + (size_t)l * 128 * 512, w2l + (size_t)l * 128 * 512, 512,
            b2 + l * 128, x, 128, nullptr, nullptr, 0, x, 1);
        if (l == 0)
            ln_split_kernel<<<NTOK / 4, 128>>>(x, hh, hl, ln1_s + 128, ln1_b + 128);
    }

    final_kernel<<<BATCH, 128>>>(x, gate_w, gate_b, proj_w, proj_b, pln_s, pln_b, out);
}

// round 8
// speedup vs baseline: 1.2153x; 1.0439x over previous
#include <cuda_runtime.h>
#include <cuda_bf16.h>
#include <math.h>
#include <stdint.h>

#define BATCH      2048
#define NODES      12
#define NTOK       (BATCH * NODES)     // 24576
#define D          128
#define F          512
#define NHEAD      4
#define DH         32
#define SCALE      0.17677669529663687f

typedef __nv_bfloat16 bf16;

// ---------------- scratch (device globals; no allocation) ----------------
__device__ __align__(16) float g_x   [NTOK * D];
__device__ __align__(16) float g_qkv [NTOK * 384];
__device__ __align__(16) bf16 g_hh[NTOK * D],  g_hl[NTOK * D];
__device__ __align__(16) bf16 g_mh[NTOK * D],  g_ml[NTOK * D];
__device__ __align__(16) bf16 g_th[NTOK * F],  g_tl[NTOK * F];
__device__ __align__(16) bf16 g_wqkvh[2 * 384 * D], g_wqkvl[2 * 384 * D]; // [l][n][k]
__device__ __align__(16) bf16 g_woh[2 * D * D],     g_wol[2 * D * D];
__device__ __align__(16) bf16 g_w1h[2 * F * D],     g_w1l[2 * F * D];
__device__ __align__(16) bf16 g_w2h[2 * D * F],     g_w2l[2 * D * F];
__device__ float g_bqkv[2 * 384];

__device__ __forceinline__ float gelu_exact(float x) {
    return 0.5f * x * (1.0f + erff(x * 0.7071067811865476f));
}
__device__ __forceinline__ void split_bf(float x, bf16& h, bf16& l) {
    h = __float2bfloat16(x);
    l = __float2bfloat16(x - __bfloat162float(h));
}
__device__ __forceinline__ uint32_t smem_u32(const void* p) {
    uint32_t a;
    asm("{ .reg .u64 t; cvta.to.shared.u64 t, %1; cvt.u32.u64 %0, t; }" : "=r"(a) : "l"(p));
    return a;
}
__device__ __forceinline__ void cp16(uint32_t dst, const void* src) {
    asm volatile("cp.async.ca.shared.global [%0], [%1], 16;" :: "r"(dst), "l"(src));
}
#define CP_COMMIT() asm volatile("cp.async.commit_group;" ::: "memory")
#define CP_WAIT(n)  asm volatile("cp.async.wait_group %0;" :: "n"(n) : "memory")

__device__ __forceinline__ void ldsm4(uint32_t* r, uint32_t addr) {
    asm volatile("ldmatrix.sync.aligned.m8n8.x4.shared.b16 {%0,%1,%2,%3}, [%4];"
        : "=r"(r[0]), "=r"(r[1]), "=r"(r[2]), "=r"(r[3]) : "r"(addr));
}
__device__ __forceinline__ void mma_bf16(float* c, const uint32_t* a, uint32_t b0, uint32_t b1) {
    asm volatile(
        "mma.sync.aligned.m16n8k16.row.col.f32.bf16.bf16.f32 "
        "{%0,%1,%2,%3}, {%4,%5,%6,%7}, {%8,%9}, {%0,%1,%2,%3};"
        : "+f"(c[0]), "+f"(c[1]), "+f"(c[2]), "+f"(c[3])
        : "r"(a[0]), "r"(a[1]), "r"(a[2]), "r"(a[3]), "r"(b0), "r"(b1));
}

// ---------------- init + layer0 LN1 ----------------
__global__ void init_ln_kernel(const float* __restrict__ patch,
                               const float* __restrict__ band,
                               const float* __restrict__ summ,
                               const float* __restrict__ s, const float* __restrict__ b,
                               float* __restrict__ x,
                               bf16* __restrict__ oh, bf16* __restrict__ ol) {
    int row  = blockIdx.x * 4 + (threadIdx.x >> 5);
    int lane = threadIdx.x & 31;
    int node = row % NODES;
    int bb   = row / NODES;
    float v[4];
    float sum = 0.f;
#pragma unroll
    for (int i = 0; i < 4; i++) {
        int d = lane + 32 * i;
        float val;
        if (node < 6)       val = patch[(size_t)(bb * 6 + node) * D + d];
        else if (node < 11) val = band [(size_t)(bb * 5 + (node - 6)) * D + d];
        else                val = summ[d];
        v[i] = val;
        x[(size_t)row * D + d] = val;
        sum += val;
    }
#pragma unroll
    for (int o = 16; o; o >>= 1) sum += __shfl_xor_sync(0xffffffffu, sum, o);
    float mu = sum * (1.0f / 128.0f);
    float sq = 0.f;
#pragma unroll
    for (int i = 0; i < 4; i++) { float c = v[i] - mu; sq += c * c; }
#pragma unroll
    for (int o = 16; o; o >>= 1) sq += __shfl_xor_sync(0xffffffffu, sq, o);
    float inv = rsqrtf(sq * (1.0f / 128.0f) + 1e-5f);
#pragma unroll
    for (int i = 0; i < 4; i++) {
        int d = lane + 32 * i;
        float y = (v[i] - mu) * inv * s[d] + b[d];
        size_t o = (size_t)row * D + d;
        split_bf(y, oh[o], ol[o]);
    }
}

// ---------------- weight packing ----------------
__global__ void pack_qkvw_kernel(const float* __restrict__ wq, const float* __restrict__ wk,
                                 const float* __restrict__ wv,
                                 const float* __restrict__ bq, const float* __restrict__ bk,
                                 const float* __restrict__ bv,
                                 bf16* __restrict__ qh, bf16* __restrict__ ql,
                                 float* __restrict__ bqkv) {
    int idx = blockIdx.x * 256 + threadIdx.x;
    if (idx < 98304) { // wqkv: [l][n<384][k<128]
        int l = idx / 49152, r = idx % 49152;
        int n = r / 128, k = r % 128;
        const float* src = (n < 128) ? wq : ((n < 256) ? wk : wv);
        float v = src[(size_t)l * 16384 + k * 128 + (n & 127)];
        split_bf(v, qh[idx], ql[idx]);
    }
    if (idx < 768) {
        int l = idx / 384, n = idx % 384;
        const float* sb = (n < 128) ? bq : ((n < 256) ? bk : bv);
        bqkv[idx] = sb[l * 128 + (n & 127)];
    }
}
__global__ void pack_rest_kernel(const float* __restrict__ wo,
                                 const float* __restrict__ w1, const float* __restrict__ w2,
                                 bf16* __restrict__ oh, bf16* __restrict__ ol,
                                 bf16* __restrict__ h1, bf16* __restrict__ l1,
                                 bf16* __restrict__ h2, bf16* __restrict__ l2) {
    int idx = blockIdx.x * 256 + threadIdx.x;
    if (idx < 32768) { // wo: [l][n<128][k<128]
        int l = idx / 16384, r = idx % 16384;
        int n = r / 128, k = r % 128;
        float v = wo[(size_t)l * 16384 + k * 128 + n];
        split_bf(v, oh[idx], ol[idx]);
    } else if (idx < 163840) { // w1: [l][n<512][k<128]  src [l][k<128][n<512]
        int t = idx - 32768;
        int l = t / 65536, r = t % 65536;
        int n = r / 128, k = r % 128;
        float v = w1[(size_t)l * 65536 + (size_t)k * 512 + n];
        split_bf(v, h1[t], l1[t]);
    } else if (idx < 294912) { // w2: [l][n<128][k<512]  src [l][k<512][n<128]
        int t = idx - 163840;
        int l = t / 65536, r = t % 65536;
        int n = r / 512, k = r % 512;
        float v = w2[(size_t)l * 65536 + (size_t)k * 128 + n];
        split_bf(v, h2[t], l2[t]);
    }
}

// ---------------- bf16x3 GEMM: BM=128 BN=128 BK=16, 512 thr, 2 CTAs/SM ----------
// mode 0: outf = A@W^T + bias (ldo)
// mode 1: v = acc+bias+resid -> outf (N=128); if ln_s: fused rowwise LN -> oh/ol
// mode 2: split(gelu(acc+bias)) -> oh/ol (ldh)
#define STG_B   24576
#define OFF_AL  6144
#define OFF_WH  12288
#define OFF_WL  18432
#define GEMM_SMEM (3 * STG_B)

__global__ __launch_bounds__(512, 2) void tgemm_kernel(
    const bf16* __restrict__ Ah, const bf16* __restrict__ Al,
    const bf16* __restrict__ Wh, const bf16* __restrict__ Wl, int K,
    const float* __restrict__ bias,
    float* __restrict__ outf, int ldo,
    bf16* __restrict__ oh, bf16* __restrict__ ol, int ldh,
    const float* __restrict__ resid,
    const float* __restrict__ ln_s, const float* __restrict__ ln_b, int mode) {
    extern __shared__ __align__(16) char sm[];
    uint32_t sb = smem_u32(sm);
    const int tid = threadIdx.x, lane = tid & 31, wid = tid >> 5;
    const int bm = blockIdx.y * 128, bn = blockIdx.x * 128;
    const int wm = (wid & 3) * 32, wn = (wid >> 2) * 32;
    const int nst = K >> 4;

    // coalesced load mapping: pair-threads fetch contiguous 32B of one row.
    const int lrow = (tid & 255) >> 1;
    const int lhalf = tid & 1;
    const bool isA = tid < 256;
    const bf16* srcH = isA ? (Ah + (size_t)(bm + lrow) * K + lhalf * 8)
                           : (Wh + (size_t)(bn + lrow) * K + lhalf * 8);
    const bf16* srcL = isA ? (Al + (size_t)(bm + lrow) * K + lhalf * 8)
                           : (Wl + (size_t)(bn + lrow) * K + lhalf * 8);
    const uint32_t dstH = (isA ? 0u : (uint32_t)OFF_WH) + (uint32_t)(lrow * 48 + lhalf * 16);
    const uint32_t dstL = dstH + OFF_AL;

    float acc[2][4][4];
#pragma unroll
    for (int i = 0; i < 2; i++)
#pragma unroll
        for (int j = 0; j < 4; j++)
#pragma unroll
            for (int c = 0; c < 4; c++) acc[i][j][c] = 0.f;

    const uint32_t aoff = (uint32_t)((lane & 15) * 48 + (lane >> 4) * 16);
    const uint32_t boff = (uint32_t)(((((lane >> 4) << 3) + (lane & 7)) * 48) + ((lane >> 3) & 1) * 16);

#define LOAD_STAGE(s) do { \
    uint32_t base_ = sb + ((s) % 3) * STG_B; \
    int ko_ = (s) * 16; \
    cp16(base_ + dstH, srcH + ko_); \
    cp16(base_ + dstL, srcL + ko_); \
} while (0)

    LOAD_STAGE(0); CP_COMMIT();
    if (nst > 1) { LOAD_STAGE(1); CP_COMMIT(); }

    for (int s = 0; s < nst; s++) {
        if (s + 2 < nst)      { LOAD_STAGE(s + 2); CP_COMMIT(); CP_WAIT(2); }
        else if (s + 1 < nst) { CP_WAIT(1); }
        else                  { CP_WAIT(0); }
        __syncthreads();
        uint32_t base = sb + (s % 3) * STG_B;

        uint32_t fah[2][4], fal[2][4];
#pragma unroll
        for (int mi = 0; mi < 2; mi++) {
            uint32_t ad = base + (uint32_t)((wm + mi * 16) * 48) + aoff;
            ldsm4(fah[mi], ad);
            ldsm4(fal[mi], ad + OFF_AL);
        }
#pragma unroll
        for (int nj = 0; nj < 2; nj++) {
            uint32_t fbh[4], fbl[4];
            uint32_t bd = base + OFF_WH + (uint32_t)((wn + nj * 16) * 48) + boff;
            ldsm4(fbh, bd);
            ldsm4(fbl, bd + (OFF_WL - OFF_WH));
#pragma unroll
            for (int mi = 0; mi < 2; mi++) {
                float* c0 = acc[mi][nj * 2];
                float* c1 = acc[mi][nj * 2 + 1];
                mma_bf16(c0, fah[mi], fbh[0], fbh[1]);
                mma_bf16(c0, fal[mi], fbh[0], fbh[1]);
                mma_bf16(c0, fah[mi], fbl[0], fbl[1]);
                mma_bf16(c1, fah[mi], fbh[2], fbh[3]);
                mma_bf16(c1, fal[mi], fbh[2], fbh[3]);
                mma_bf16(c1, fah[mi], fbl[2], fbl[3]);
            }
        }
        __syncthreads();
    }

    if (mode == 1) {
        // residual add, write x, stage tile in smem for fused LN
        float* smf = (float*)sm;  // 128x128 f32 = 64KB <= 72KB
#pragma unroll
        for (int mi = 0; mi < 2; mi++) {
            int lr0 = wm + mi * 16 + (lane >> 2);
            int lr1 = lr0 + 8;
#pragma unroll
            for (int ni = 0; ni < 4; ni++) {
                int col = wn + ni * 8 + 2 * (lane & 3);
                float b0 = bias[col], b1 = bias[col + 1];
                size_t o0 = (size_t)(bm + lr0) * 128 + col, o1 = (size_t)(bm + lr1) * 128 + col;
                float v0 = acc[mi][ni][0] + b0 + resid[o0];
                float v1 = acc[mi][ni][1] + b1 + resid[o0 + 1];
                float v2 = acc[mi][ni][2] + b0 + resid[o1];
                float v3 = acc[mi][ni][3] + b1 + resid[o1 + 1];
                *(float2*)&outf[o0] = make_float2(v0, v1);
                *(float2*)&outf[o1] = make_float2(v2, v3);
                smf[lr0 * 128 + col] = v0; smf[lr0 * 128 + col + 1] = v1;
                smf[lr1 * 128 + col] = v2; smf[lr1 * 128 + col + 1] = v3;
            }
        }
        if (ln_s) {
            __syncthreads();
            float4 s4 = *(const float4*)(ln_s + lane * 4);
            float4 b4 = *(const float4*)(ln_b + lane * 4);
#pragma unroll
            for (int t = 0; t < 8; t++) {
                int rr = wid * 8 + t;
                float4 v = ((const float4*)smf)[rr * 32 + lane];
                float sum = (v.x + v.y) + (v.z + v.w);
                float sq  = fmaf(v.x, v.x, fmaf(v.y, v.y, fmaf(v.z, v.z, v.w * v.w)));
#pragma unroll
                for (int o = 16; o; o >>= 1) {
                    sum += __shfl_xor_sync(0xffffffffu, sum, o);
                    sq  += __shfl_xor_sync(0xffffffffu, sq, o);
                }
                float mu  = sum * (1.0f / 128.0f);
                float var = sq * (1.0f / 128.0f) - mu * mu;
                float inv = rsqrtf(var + 1e-5f);
                float y0 = (v.x - mu) * inv * s4.x + b4.x;
                float y1 = (v.y - mu) * inv * s4.y + b4.y;
                float y2 = (v.z - mu) * inv * s4.z + b4.z;
                float y3 = (v.w - mu) * inv * s4.w + b4.w;
                bf16 h0, l0, h1, l1, h2, l2, h3, l3;
                split_bf(y0, h0, l0); split_bf(y1, h1, l1);
                split_bf(y2, h2, l2); split_bf(y3, h3, l3);
                __nv_bfloat162 ph0{h0, h1}, ph1{h2, h3}, pl0{l0, l1}, pl1{l2, l3};
                uint2 uh{*(uint32_t*)&ph0, *(uint32_t*)&ph1};
                uint2 ul{*(uint32_t*)&pl0, *(uint32_t*)&pl1};
                size_t ob = (size_t)(bm + rr) * 128 + lane * 4;
                *(uint2*)(oh + ob) = uh;
                *(uint2*)(ol + ob) = ul;
            }
        }
        return;
    }

#pragma unroll
    for (int mi = 0; mi < 2; mi++) {
        int r0 = bm + wm + mi * 16 + (lane >> 2);
        int r1 = r0 + 8;
#pragma unroll
        for (int ni = 0; ni < 4; ni++) {
            int col = bn + wn + ni * 8 + 2 * (lane & 3);
            float b0 = bias[col], b1 = bias[col + 1];
            float v0 = acc[mi][ni][0] + b0, v1 = acc[mi][ni][1] + b1;
            float v2 = acc[mi][ni][2] + b0, v3 = acc[mi][ni][3] + b1;
            if (mode == 0) {
                size_t o0 = (size_t)r0 * ldo + col, o1 = (size_t)r1 * ldo + col;
                *(float2*)&outf[o0] = make_float2(v0, v1);
                *(float2*)&outf[o1] = make_float2(v2, v3);
            } else {
                v0 = gelu_exact(v0); v1 = gelu_exact(v1);
                v2 = gelu_exact(v2); v3 = gelu_exact(v3);
                bf16 h0, l0, h1, l1;
                size_t o0 = (size_t)r0 * ldh + col, o1 = (size_t)r1 * ldh + col;
                split_bf(v0, h0, l0); split_bf(v1, h1, l1);
                __nv_bfloat162 ph{h0, h1}, pl{l0, l1};
                *(__nv_bfloat162*)&oh[o0] = ph;
                *(__nv_bfloat162*)&ol[o0] = pl;
                split_bf(v2, h0, l0); split_bf(v3, h1, l1);
                __nv_bfloat162 qh2{h0, h1}, ql2{l0, l1};
                *(__nv_bfloat162*)&oh[o1] = qh2;
                *(__nv_bfloat162*)&ol[o1] = ql2;
            }
        }
    }
#undef LOAD_STAGE
}

// ---------------- dense 12-node attention, float4-vectorized ----------------
__global__ __launch_bounds__(64) void attn_kernel(const float* __restrict__ qkv,
                                                  const float* __restrict__ edge_bias,
                                                  bf16* __restrict__ mh, bf16* __restrict__ ml) {
    __shared__ float4 sk[NODES * 32];
    __shared__ float4 sv[NODES * 32];
    __shared__ float seb[36];
    int b = blockIdx.x;
    const float4* q4 = (const float4*)(qkv + (size_t)b * NODES * 384);
    for (int i = threadIdx.x; i < NODES * 32; i += 64) {
        int node = i >> 5, c = i & 31;
        sk[i] = q4[node * 96 + 32 + c];
        sv[i] = q4[node * 96 + 64 + c];
    }
    if (threadIdx.x < 36) seb[threadIdx.x] = edge_bias[threadIdx.x];
    __syncthreads();
    int tt = threadIdx.x;
    if (tt >= NODES * NHEAD) return;
    int dst = tt >> 2, hd = tt & 3;
    int kd = dst < 6 ? 0 : (dst < 11 ? 1 : 2);

    float4 q[8];
    const float4* qp = q4 + dst * 96 + hd * 8;
#pragma unroll
    for (int i = 0; i < 8; i++) q[i] = qp[i];

    float logits[NODES];
    float mx = -1e30f;
#pragma unroll
    for (int j = 0; j < NODES; j++) {
        const float4* kp = &sk[j * 32 + hd * 8];
        float d0 = 0.f, d1 = 0.f, d2 = 0.f, d3 = 0.f;
#pragma unroll
        for (int i = 0; i < 8; i++) {
            float4 kv = kp[i];
            d0 = fmaf(q[i].x, kv.x, d0);
            d1 = fmaf(q[i].y, kv.y, d1);
            d2 = fmaf(q[i].z, kv.z, d2);
            d3 = fmaf(q[i].w, kv.w, d3);
        }
        int ks = j < 6 ? 0 : (j < 11 ? 1 : 2);
        float lg = ((d0 + d1) + (d2 + d3)) * SCALE + seb[(ks * 3 + kd) * NHEAD + hd];
        logits[j] = lg;
        mx = fmaxf(mx, lg);
    }
    float z = 0.f;
#pragma unroll
    for (int j = 0; j < NODES; j++) { logits[j] = __expf(logits[j] - mx); z += logits[j]; }
    float inv = 1.0f / z;

    float4 out[8];
#pragma unroll
    for (int i = 0; i < 8; i++) out[i] = make_float4(0.f, 0.f, 0.f, 0.f);
#pragma unroll
    for (int j = 0; j < NODES; j++) {
        float a = logits[j] * inv;
        const float4* vp = &sv[j * 32 + hd * 8];
#pragma unroll
        for (int i = 0; i < 8; i++) {
            float4 vv = vp[i];
            out[i].x = fmaf(a, vv.x, out[i].x);
            out[i].y = fmaf(a, vv.y, out[i].y);
            out[i].z = fmaf(a, vv.z, out[i].z);
            out[i].w = fmaf(a, vv.w, out[i].w);
        }
    }
    size_t ob = (size_t)b * NODES * D + dst * D + hd * DH;
#pragma unroll
    for (int i = 0; i < 8; i++) {
        bf16 h0, l0, h1, l1, h2, l2, h3, l3;
        split_bf(out[i].x, h0, l0); split_bf(out[i].y, h1, l1);
        split_bf(out[i].z, h2, l2); split_bf(out[i].w, h3, l3);
        __nv_bfloat162 pa{h0, h1}, pb{h2, h3}, pc{l0, l1}, pd{l2, l3};
        uint2 uh{*(uint32_t*)&pa, *(uint32_t*)&pb};
        uint2 ul{*(uint32_t*)&pc, *(uint32_t*)&pd};
        *(uint2*)(mh + ob + i * 4) = uh;
        *(uint2*)(ml + ob + i * 4) = ul;
    }
}

// ---------------- final: gate/pool + proj + LN + gelu ----------------
__global__ void final_kernel(const float* __restrict__ x,
                             const float* __restrict__ gate_w, const float* __restrict__ gate_b,
                             const float* __restrict__ proj_w, const float* __restrict__ proj_b,
                             const float* __restrict__ pln_s, const float* __restrict__ pln_b,
                             float* __restrict__ out) {
    __shared__ float sx[NODES * D];
    __shared__ float sgate[NODES];
    __shared__ float comb[2 * D];
    __shared__ float red[4];
    int b = blockIdx.x, tid = threadIdx.x;
    for (int i = tid; i < NODES * D; i += 128) sx[i] = x[(size_t)b * NODES * D + i];
    __syncthreads();
    if (tid < NODES) {
        float acc = gate_b[0];
#pragma unroll 8
        for (int d = 0; d < D; d++) acc = fmaf(sx[tid * D + d], gate_w[d], acc);
        sgate[tid] = 1.0f / (1.0f + __expf(-acc));
    }
    __syncthreads();
    float pooled = 0.f;
#pragma unroll
    for (int n = 0; n < NODES; n++) pooled = fmaf(sx[n * D + tid], sgate[n], pooled);
    comb[tid]     = sx[11 * D + tid];
    comb[D + tid] = pooled;
    __syncthreads();
    float y = proj_b[tid];
#pragma unroll 8
    for (int c = 0; c < 2 * D; c++) y = fmaf(comb[c], proj_w[c * D + tid], y);
    float sum = y;
#pragma unroll
    for (int o = 16; o; o >>= 1) sum += __shfl_xor_sync(0xffffffffu, sum, o);
    if ((tid & 31) == 0) red[tid >> 5] = sum;
    __syncthreads();
    float mu = (red[0] + red[1] + red[2] + red[3]) * (1.0f / 128.0f);
    float c0 = y - mu;
    float cs = c0 * c0;
#pragma unroll
    for (int o = 16; o; o >>= 1) cs += __shfl_xor_sync(0xffffffffu, cs, o);
    __syncthreads();
    if ((tid & 31) == 0) red[tid >> 5] = cs;
    __syncthreads();
    float var = (red[0] + red[1] + red[2] + red[3]) * (1.0f / 128.0f);
    float yn = c0 * rsqrtf(var + 1e-5f) * pln_s[tid] + pln_b[tid];
    out[(size_t)b * D + tid] = gelu_exact(yn);
}

// ---------------- host orchestration ----------------
extern "C" void kernel_launch(void* const* d_in, const int* in_sizes, int n_in,
                              void* d_out, int out_size) {
    const float* patch   = (const float*)d_in[0];
    const float* band    = (const float*)d_in[1];
    const float* summ    = (const float*)d_in[2];
    const float* ln1_s   = (const float*)d_in[3];
    const float* ln1_b   = (const float*)d_in[4];
    const float* wq      = (const float*)d_in[5];
    const float* bq      = (const float*)d_in[6];
    const float* wk      = (const float*)d_in[7];
    const float* bk      = (const float*)d_in[8];
    const float* wv      = (const float*)d_in[9];
    const float* bv      = (const float*)d_in[10];
    const float* wo      = (const float*)d_in[11];
    const float* bo      = (const float*)d_in[12];
    const float* edge_b  = (const float*)d_in[13];
    const float* ln2_s   = (const float*)d_in[14];
    const float* ln2_b   = (const float*)d_in[15];
    const float* w1      = (const float*)d_in[16];
    const float* b1      = (const float*)d_in[17];
    const float* w2      = (const float*)d_in[18];
    const float* b2      = (const float*)d_in[19];
    const float* gate_w  = (const float*)d_in[20];
    const float* gate_b  = (const float*)d_in[21];
    const float* proj_w  = (const float*)d_in[22];
    const float* proj_b  = (const float*)d_in[23];
    const float* pln_s   = (const float*)d_in[24];
    const float* pln_b   = (const float*)d_in[25];
    float* out = (float*)d_out;

    float *x, *qkv, *bqkv;
    bf16 *hh, *hl, *mh, *ml, *th, *tl;
    bf16 *wqkvh, *wqkvl, *woh, *wol, *w1h, *w1l, *w2h, *w2l;
    cudaGetSymbolAddress((void**)&x,     g_x);
    cudaGetSymbolAddress((void**)&qkv,   g_qkv);
    cudaGetSymbolAddress((void**)&bqkv,  g_bqkv);
    cudaGetSymbolAddress((void**)&hh,    g_hh);
    cudaGetSymbolAddress((void**)&hl,    g_hl);
    cudaGetSymbolAddress((void**)&mh,    g_mh);
    cudaGetSymbolAddress((void**)&ml,    g_ml);
    cudaGetSymbolAddress((void**)&th,    g_th);
    cudaGetSymbolAddress((void**)&tl,    g_tl);
    cudaGetSymbolAddress((void**)&wqkvh, g_wqkvh);
    cudaGetSymbolAddress((void**)&wqkvl, g_wqkvl);
    cudaGetSymbolAddress((void**)&woh,   g_woh);
    cudaGetSymbolAddress((void**)&wol,   g_wol);
    cudaGetSymbolAddress((void**)&w1h,   g_w1h);
    cudaGetSymbolAddress((void**)&w1l,   g_w1l);
    cudaGetSymbolAddress((void**)&w2h,   g_w2h);
    cudaGetSymbolAddress((void**)&w2l,   g_w2l);

    static int smem_set = 0;
    if (!smem_set) {
        cudaFuncSetAttribute(tgemm_kernel, cudaFuncAttributeMaxDynamicSharedMemorySize, GEMM_SMEM);
        smem_set = 1;
    }

    init_ln_kernel<<<NTOK / 4, 128>>>(patch, band, summ, ln1_s, ln1_b, x, hh, hl);
    pack_qkvw_kernel<<<(98304 + 255) / 256, 256>>>(wq, wk, wv, bq, bk, bv, wqkvh, wqkvl, bqkv);
    pack_rest_kernel<<<(294912 + 255) / 256, 256>>>(wo, w1, w2, woh, wol, w1h, w1l, w2h, w2l);

    const int MT = NTOK / 128; // 192
    for (int l = 0; l < 2; l++) {
        // QKV (mode 0): N=384
        tgemm_kernel<<<dim3(3, MT), 512, GEMM_SMEM>>>(
            hh, hl, wqkvh + (size_t)l * 384 * 128, wqkvl + (size_t)l * 384 * 128, 128,
            bqkv + l * 384, qkv, 384, nullptr, nullptr, 0, nullptr, nullptr, nullptr, 0);
        attn_kernel<<<BATCH, 64>>>(qkv, edge_b + l * 36, mh, ml);
        // O-proj + residual + fused LN2 (mode 1): N=128
        tgemm_kernel<<<dim3(1, MT), 512, GEMM_SMEM>>>(
            mh, ml, woh + (size_t)l * 128 * 128, wol + (size_t)l * 128 * 128, 128,
            bo + l * 128, x, 128, hh, hl, 128, x, ln2_s + l * 128, ln2_b + l * 128, 1);
        // FFN1 + GELU (mode 2): N=512
        tgemm_kernel<<<dim3(4, MT), 512, GEMM_SMEM>>>(
            hh, hl, w1h + (size_t)l * 512 * 128, w1l + (size_t)l * 512 * 128, 128,
            b1 + l * 512, nullptr, 0, th, tl, 512, nullptr, nullptr, nullptr, 2);
        // FFN2 + residual (+ fused next-layer LN1) (mode 1): N=128, K=512
        const float* nls = (l == 0) ? (ln1_s + 128) : nullptr;
        const float* nlb = (l == 0) ? (ln1_b + 128) : nullptr;
        tgemm_kernel<<<dim3(1, MT), 512, GEMM_SMEM>>>(
            th, tl, w2h + (size_t)l * 128 * 512, w2l + (size_t)l * 128 * 512, 512,
            b2 + l * 128, x, 128, hh, hl, 128, x, nls, nlb, 1);
    }

    final_kernel<<<BATCH, 128>>>(x, gate_w, gate_b, proj_w, proj_b, pln_s, pln_b, out);
}

// round 9
// speedup vs baseline: 1.2876x; 1.0594x over previous
#include <cuda_runtime.h>
#include <cuda_bf16.h>
#include <math.h>
#include <stdint.h>

#define BATCH      2048
#define NODES      12
#define NTOK       (BATCH * NODES)     // 24576
#define D          128
#define F          512
#define NHEAD      4
#define DH         32
#define SCALE      0.17677669529663687f

typedef __nv_bfloat16 bf16;

// ---------------- scratch (device globals; no allocation) ----------------
__device__ __align__(16) float g_x   [NTOK * D];
__device__ __align__(16) float g_qkv [NTOK * 384];
__device__ __align__(16) bf16 g_hh[NTOK * D],  g_hl[NTOK * D];
__device__ __align__(16) bf16 g_mh[NTOK * D],  g_ml[NTOK * D];
__device__ __align__(16) bf16 g_th[NTOK * F],  g_tl[NTOK * F];
__device__ __align__(16) bf16 g_wqkvh[2 * 384 * D], g_wqkvl[2 * 384 * D]; // [l][n][k]
__device__ __align__(16) bf16 g_woh[2 * D * D],     g_wol[2 * D * D];
__device__ __align__(16) bf16 g_w1h[2 * F * D],     g_w1l[2 * F * D];
__device__ __align__(16) bf16 g_w2h[2 * D * F],     g_w2l[2 * D * F];
__device__ float g_bqkv[2 * 384];

__device__ __forceinline__ float gelu_exact(float x) {
    return 0.5f * x * (1.0f + erff(x * 0.7071067811865476f));
}
__device__ __forceinline__ void split_bf(float x, bf16& h, bf16& l) {
    h = __float2bfloat16(x);
    l = __float2bfloat16(x - __bfloat162float(h));
}
__device__ __forceinline__ uint32_t smem_u32(const void* p) {
    uint32_t a;
    asm("{ .reg .u64 t; cvta.to.shared.u64 t, %1; cvt.u32.u64 %0, t; }" : "=r"(a) : "l"(p));
    return a;
}
__device__ __forceinline__ void cp16(uint32_t dst, const void* src) {
    asm volatile("cp.async.ca.shared.global [%0], [%1], 16;" :: "r"(dst), "l"(src));
}
#define CP_COMMIT() asm volatile("cp.async.commit_group;" ::: "memory")
#define CP_WAIT(n)  asm volatile("cp.async.wait_group %0;" :: "n"(n) : "memory")

__device__ __forceinline__ void ldsm4(uint32_t* r, uint32_t addr) {
    asm volatile("ldmatrix.sync.aligned.m8n8.x4.shared.b16 {%0,%1,%2,%3}, [%4];"
        : "=r"(r[0]), "=r"(r[1]), "=r"(r[2]), "=r"(r[3]) : "r"(addr));
}
__device__ __forceinline__ void mma_bf16(float* c, const uint32_t* a, uint32_t b0, uint32_t b1) {
    asm volatile(
        "mma.sync.aligned.m16n8k16.row.col.f32.bf16.bf16.f32 "
        "{%0,%1,%2,%3}, {%4,%5,%6,%7}, {%8,%9}, {%0,%1,%2,%3};"
        : "+f"(c[0]), "+f"(c[1]), "+f"(c[2]), "+f"(c[3])
        : "r"(a[0]), "r"(a[1]), "r"(a[2]), "r"(a[3]), "r"(b0), "r"(b1));
}

// ---------------- init + layer0 LN1 ----------------
__global__ void init_ln_kernel(const float* __restrict__ patch,
                               const float* __restrict__ band,
                               const float* __restrict__ summ,
                               const float* __restrict__ s, const float* __restrict__ b,
                               float* __restrict__ x,
                               bf16* __restrict__ oh, bf16* __restrict__ ol) {
    int row  = blockIdx.x * 4 + (threadIdx.x >> 5);
    int lane = threadIdx.x & 31;
    int node = row % NODES;
    int bb   = row / NODES;
    float v[4];
    float sum = 0.f;
#pragma unroll
    for (int i = 0; i < 4; i++) {
        int d = lane + 32 * i;
        float val;
        if (node < 6)       val = patch[(size_t)(bb * 6 + node) * D + d];
        else if (node < 11) val = band [(size_t)(bb * 5 + (node - 6)) * D + d];
        else                val = summ[d];
        v[i] = val;
        x[(size_t)row * D + d] = val;
        sum += val;
    }
#pragma unroll
    for (int o = 16; o; o >>= 1) sum += __shfl_xor_sync(0xffffffffu, sum, o);
    float mu = sum * (1.0f / 128.0f);
    float sq = 0.f;
#pragma unroll
    for (int i = 0; i < 4; i++) { float c = v[i] - mu; sq += c * c; }
#pragma unroll
    for (int o = 16; o; o >>= 1) sq += __shfl_xor_sync(0xffffffffu, sq, o);
    float inv = rsqrtf(sq * (1.0f / 128.0f) + 1e-5f);
#pragma unroll
    for (int i = 0; i < 4; i++) {
        int d = lane + 32 * i;
        float y = (v[i] - mu) * inv * s[d] + b[d];
        size_t o = (size_t)row * D + d;
        split_bf(y, oh[o], ol[o]);
    }
}

// ---------------- weight packing ----------------
__global__ void pack_qkvw_kernel(const float* __restrict__ wq, const float* __restrict__ wk,
                                 const float* __restrict__ wv,
                                 const float* __restrict__ bq, const float* __restrict__ bk,
                                 const float* __restrict__ bv,
                                 bf16* __restrict__ qh, bf16* __restrict__ ql,
                                 float* __restrict__ bqkv) {
    int idx = blockIdx.x * 256 + threadIdx.x;
    if (idx < 98304) { // wqkv: [l][n<384][k<128]
        int l = idx / 49152, r = idx % 49152;
        int n = r / 128, k = r % 128;
        const float* src = (n < 128) ? wq : ((n < 256) ? wk : wv);
        float v = src[(size_t)l * 16384 + k * 128 + (n & 127)];
        split_bf(v, qh[idx], ql[idx]);
    }
    if (idx < 768) {
        int l = idx / 384, n = idx % 384;
        const float* sb = (n < 128) ? bq : ((n < 256) ? bk : bv);
        bqkv[idx] = sb[l * 128 + (n & 127)];
    }
}
__global__ void pack_rest_kernel(const float* __restrict__ wo,
                                 const float* __restrict__ w1, const float* __restrict__ w2,
                                 bf16* __restrict__ oh, bf16* __restrict__ ol,
                                 bf16* __restrict__ h1, bf16* __restrict__ l1,
                                 bf16* __restrict__ h2, bf16* __restrict__ l2) {
    int idx = blockIdx.x * 256 + threadIdx.x;
    if (idx < 32768) { // wo: [l][n<128][k<128]
        int l = idx / 16384, r = idx % 16384;
        int n = r / 128, k = r % 128;
        float v = wo[(size_t)l * 16384 + k * 128 + n];
        split_bf(v, oh[idx], ol[idx]);
    } else if (idx < 163840) { // w1: [l][n<512][k<128]  src [l][k<128][n<512]
        int t = idx - 32768;
        int l = t / 65536, r = t % 65536;
        int n = r / 128, k = r % 128;
        float v = w1[(size_t)l * 65536 + (size_t)k * 512 + n];
        split_bf(v, h1[t], l1[t]);
    } else if (idx < 294912) { // w2: [l][n<128][k<512]  src [l][k<512][n<128]
        int t = idx - 163840;
        int l = t / 65536, r = t % 65536;
        int n = r / 512, k = r % 512;
        float v = w2[(size_t)l * 65536 + (size_t)k * 128 + n];
        split_bf(v, h2[t], l2[t]);
    }
}

// ---------------- bf16x3 GEMM: BM=128 BN=128 BK=16, 256 thr (8 warps of 32x64) ----------
// 4-stage cp.async pipeline; 2 CTAs/SM.
// mode 0: outf = A@W^T + bias (ldo)
// mode 1: v = acc+bias+resid -> outf (N=128); if ln_s: fused rowwise LN -> oh/ol
// mode 2: split(gelu(acc+bias)) -> oh/ol (ldh)
#define STG_B   24576
#define GEMM_SMEM (4 * STG_B)

__global__ __launch_bounds__(256, 2) void tgemm_kernel(
    const bf16* __restrict__ Ah, const bf16* __restrict__ Al,
    const bf16* __restrict__ Wh, const bf16* __restrict__ Wl, int K,
    const float* __restrict__ bias,
    float* __restrict__ outf, int ldo,
    bf16* __restrict__ oh, bf16* __restrict__ ol, int ldh,
    const float* __restrict__ resid,
    const float* __restrict__ ln_s, const float* __restrict__ ln_b, int mode) {
    extern __shared__ __align__(16) char sm[];
    uint32_t sb = smem_u32(sm);
    const int tid = threadIdx.x, lane = tid & 31, wid = tid >> 5;
    const int bm = blockIdx.y * 128, bn = blockIdx.x * 128;
    const int wm = (wid & 3) * 32, wn = (wid >> 2) * 64;   // 4x2 warps, 32x64 tiles
    const int nst = K >> 4;

    // loader mapping: quarter q selects matrix (Ah,Al,Wh,Wl); 64 threads per quarter
    // handle 256 16B-transfers (128 rows x 2 halves), pair-coalesced.
    const int q = tid >> 6;
    const int li = tid & 63;
    const bf16* base_src = (q == 0) ? (Ah + (size_t)bm * K)
                          : (q == 1) ? (Al + (size_t)bm * K)
                          : (q == 2) ? (Wh + (size_t)bn * K)
                                     : (Wl + (size_t)bn * K);
    uint32_t dsts[4]; size_t srcs[4];
#pragma unroll
    for (int j = 0; j < 4; j++) {
        int t2 = li + 64 * j;
        int row = t2 >> 1, hf = t2 & 1;
        dsts[j] = (uint32_t)(q * 6144 + row * 48 + hf * 16);
        srcs[j] = (size_t)row * K + hf * 8;
    }

    float acc[2][8][4];
#pragma unroll
    for (int i = 0; i < 2; i++)
#pragma unroll
        for (int j = 0; j < 8; j++)
#pragma unroll
            for (int c = 0; c < 4; c++) acc[i][j][c] = 0.f;

    const uint32_t aoff = (uint32_t)((lane & 15) * 48 + (lane >> 4) * 16);
    const uint32_t boff = (uint32_t)(((((lane >> 4) << 3) + (lane & 7)) * 48) + ((lane >> 3) & 1) * 16);

#define LOAD_STAGE(s) do { \
    uint32_t base_ = sb + ((s) & 3) * STG_B; \
    int ko_ = (s) * 16; \
    cp16(base_ + dsts[0], base_src + srcs[0] + ko_); \
    cp16(base_ + dsts[1], base_src + srcs[1] + ko_); \
    cp16(base_ + dsts[2], base_src + srcs[2] + ko_); \
    cp16(base_ + dsts[3], base_src + srcs[3] + ko_); \
} while (0)

    LOAD_STAGE(0); CP_COMMIT();
    if (nst > 1) { LOAD_STAGE(1); CP_COMMIT(); }
    if (nst > 2) { LOAD_STAGE(2); CP_COMMIT(); }

    for (int s = 0; s < nst; s++) {
        if (s + 3 < nst) { LOAD_STAGE(s + 3); CP_COMMIT(); CP_WAIT(3); }
        else {
            int rem = nst - 1 - s;
            if (rem == 2) CP_WAIT(2);
            else if (rem == 1) CP_WAIT(1);
            else CP_WAIT(0);
        }
        __syncthreads();
        uint32_t base = sb + (s & 3) * STG_B;

        uint32_t fah[2][4], fal[2][4];
#pragma unroll
        for (int mi = 0; mi < 2; mi++) {
            uint32_t ad = base + (uint32_t)((wm + mi * 16) * 48) + aoff;
            ldsm4(fah[mi], ad);
            ldsm4(fal[mi], ad + 6144);
        }
#pragma unroll
        for (int nj = 0; nj < 4; nj++) {
            uint32_t fbh[4], fbl[4];
            uint32_t bd = base + 12288u + (uint32_t)((wn + nj * 16) * 48) + boff;
            ldsm4(fbh, bd);
            ldsm4(fbl, bd + 6144);
#pragma unroll
            for (int mi = 0; mi < 2; mi++) {
                float* c0 = acc[mi][nj * 2];
                float* c1 = acc[mi][nj * 2 + 1];
                mma_bf16(c0, fah[mi], fbh[0], fbh[1]);
                mma_bf16(c0, fal[mi], fbh[0], fbh[1]);
                mma_bf16(c0, fah[mi], fbl[0], fbl[1]);
                mma_bf16(c1, fah[mi], fbh[2], fbh[3]);
                mma_bf16(c1, fal[mi], fbh[2], fbh[3]);
                mma_bf16(c1, fah[mi], fbl[2], fbl[3]);
            }
        }
        __syncthreads();
    }

    if (mode == 1) {
        // residual add, write x, stage tile in smem for fused LN
        float* smf = (float*)sm;  // 128x128 f32 = 64KB <= 96KB
#pragma unroll
        for (int mi = 0; mi < 2; mi++) {
            int lr0 = wm + mi * 16 + (lane >> 2);
            int lr1 = lr0 + 8;
#pragma unroll
            for (int ni = 0; ni < 8; ni++) {
                int col = wn + ni * 8 + 2 * (lane & 3);
                float b0 = bias[col], b1 = bias[col + 1];
                size_t o0 = (size_t)(bm + lr0) * 128 + col, o1 = (size_t)(bm + lr1) * 128 + col;
                float v0 = acc[mi][ni][0] + b0 + resid[o0];
                float v1 = acc[mi][ni][1] + b1 + resid[o0 + 1];
                float v2 = acc[mi][ni][2] + b0 + resid[o1];
                float v3 = acc[mi][ni][3] + b1 + resid[o1 + 1];
                *(float2*)&outf[o0] = make_float2(v0, v1);
                *(float2*)&outf[o1] = make_float2(v2, v3);
                smf[lr0 * 128 + col] = v0; smf[lr0 * 128 + col + 1] = v1;
                smf[lr1 * 128 + col] = v2; smf[lr1 * 128 + col + 1] = v3;
            }
        }
        if (ln_s) {
            __syncthreads();
            float4 s4 = *(const float4*)(ln_s + lane * 4);
            float4 b4 = *(const float4*)(ln_b + lane * 4);
#pragma unroll
            for (int t = 0; t < 16; t++) {
                int rr = wid * 16 + t;
                float4 v = ((const float4*)smf)[rr * 32 + lane];
                float sum = (v.x + v.y) + (v.z + v.w);
                float sq  = fmaf(v.x, v.x, fmaf(v.y, v.y, fmaf(v.z, v.z, v.w * v.w)));
#pragma unroll
                for (int o = 16; o; o >>= 1) {
                    sum += __shfl_xor_sync(0xffffffffu, sum, o);
                    sq  += __shfl_xor_sync(0xffffffffu, sq, o);
                }
                float mu  = sum * (1.0f / 128.0f);
                float var = sq * (1.0f / 128.0f) - mu * mu;
                float inv = rsqrtf(var + 1e-5f);
                float y0 = (v.x - mu) * inv * s4.x + b4.x;
                float y1 = (v.y - mu) * inv * s4.y + b4.y;
                float y2 = (v.z - mu) * inv * s4.z + b4.z;
                float y3 = (v.w - mu) * inv * s4.w + b4.w;
                bf16 h0, l0, h1, l1, h2, l2, h3, l3;
                split_bf(y0, h0, l0); split_bf(y1, h1, l1);
                split_bf(y2, h2, l2); split_bf(y3, h3, l3);
                __nv_bfloat162 ph0{h0, h1}, ph1{h2, h3}, pl0{l0, l1}, pl1{l2, l3};
                uint2 uh{*(uint32_t*)&ph0, *(uint32_t*)&ph1};
                uint2 ul{*(uint32_t*)&pl0, *(uint32_t*)&pl1};
                size_t ob = (size_t)(bm + rr) * 128 + lane * 4;
                *(uint2*)(oh + ob) = uh;
                *(uint2*)(ol + ob) = ul;
            }
        }
        return;
    }

#pragma unroll
    for (int mi = 0; mi < 2; mi++) {
        int r0 = bm + wm + mi * 16 + (lane >> 2);
        int r1 = r0 + 8;
#pragma unroll
        for (int ni = 0; ni < 8; ni++) {
            int col = bn + wn + ni * 8 + 2 * (lane & 3);
            float b0 = bias[col], b1 = bias[col + 1];
            float v0 = acc[mi][ni][0] + b0, v1 = acc[mi][ni][1] + b1;
            float v2 = acc[mi][ni][2] + b0, v3 = acc[mi][ni][3] + b1;
            if (mode == 0) {
                size_t o0 = (size_t)r0 * ldo + col, o1 = (size_t)r1 * ldo + col;
                *(float2*)&outf[o0] = make_float2(v0, v1);
                *(float2*)&outf[o1] = make_float2(v2, v3);
            } else {
                v0 = gelu_exact(v0); v1 = gelu_exact(v1);
                v2 = gelu_exact(v2); v3 = gelu_exact(v3);
                bf16 h0, l0, h1, l1;
                size_t o0 = (size_t)r0 * ldh + col, o1 = (size_t)r1 * ldh + col;
                split_bf(v0, h0, l0); split_bf(v1, h1, l1);
                __nv_bfloat162 ph{h0, h1}, pl{l0, l1};
                *(__nv_bfloat162*)&oh[o0] = ph;
                *(__nv_bfloat162*)&ol[o0] = pl;
                split_bf(v2, h0, l0); split_bf(v3, h1, l1);
                __nv_bfloat162 qh2{h0, h1}, ql2{l0, l1};
                *(__nv_bfloat162*)&oh[o1] = qh2;
                *(__nv_bfloat162*)&ol[o1] = ql2;
            }
        }
    }
#undef LOAD_STAGE
}

// ---------------- dense 12-node attention, float4-vectorized ----------------
__global__ __launch_bounds__(64) void attn_kernel(const float* __restrict__ qkv,
                                                  const float* __restrict__ edge_bias,
                                                  bf16* __restrict__ mh, bf16* __restrict__ ml) {
    __shared__ float4 sk[NODES * 32];
    __shared__ float4 sv[NODES * 32];
    __shared__ float seb[36];
    int b = blockIdx.x;
    const float4* q4 = (const float4*)(qkv + (size_t)b * NODES * 384);
    for (int i = threadIdx.x; i < NODES * 32; i += 64) {
        int node = i >> 5, c = i & 31;
        sk[i] = q4[node * 96 + 32 + c];
        sv[i] = q4[node * 96 + 64 + c];
    }
    if (threadIdx.x < 36) seb[threadIdx.x] = edge_bias[threadIdx.x];
    __syncthreads();
    int tt = threadIdx.x;
    if (tt >= NODES * NHEAD) return;
    int dst = tt >> 2, hd = tt & 3;
    int kd = dst < 6 ? 0 : (dst < 11 ? 1 : 2);

    float4 q[8];
    const float4* qp = q4 + dst * 96 + hd * 8;
#pragma unroll
    for (int i = 0; i < 8; i++) q[i] = qp[i];

    float logits[NODES];
    float mx = -1e30f;
#pragma unroll
    for (int j = 0; j < NODES; j++) {
        const float4* kp = &sk[j * 32 + hd * 8];
        float d0 = 0.f, d1 = 0.f, d2 = 0.f, d3 = 0.f;
#pragma unroll
        for (int i = 0; i < 8; i++) {
            float4 kv = kp[i];
            d0 = fmaf(q[i].x, kv.x, d0);
            d1 = fmaf(q[i].y, kv.y, d1);
            d2 = fmaf(q[i].z, kv.z, d2);
            d3 = fmaf(q[i].w, kv.w, d3);
        }
        int ks = j < 6 ? 0 : (j < 11 ? 1 : 2);
        float lg = ((d0 + d1) + (d2 + d3)) * SCALE + seb[(ks * 3 + kd) * NHEAD + hd];
        logits[j] = lg;
        mx = fmaxf(mx, lg);
    }
    float z = 0.f;
#pragma unroll
    for (int j = 0; j < NODES; j++) { logits[j] = __expf(logits[j] - mx); z += logits[j]; }
    float inv = 1.0f / z;

    float4 out[8];
#pragma unroll
    for (int i = 0; i < 8; i++) out[i] = make_float4(0.f, 0.f, 0.f, 0.f);
#pragma unroll
    for (int j = 0; j < NODES; j++) {
        float a = logits[j] * inv;
        const float4* vp = &sv[j * 32 + hd * 8];
#pragma unroll
        for (int i = 0; i < 8; i++) {
            float4 vv = vp[i];
            out[i].x = fmaf(a, vv.x, out[i].x);
            out[i].y = fmaf(a, vv.y, out[i].y);
            out[i].z = fmaf(a, vv.z, out[i].z);
            out[i].w = fmaf(a, vv.w, out[i].w);
        }
    }
    size_t ob = (size_t)b * NODES * D + dst * D + hd * DH;
#pragma unroll
    for (int i = 0; i < 8; i++) {
        bf16 h0, l0, h1, l1, h2, l2, h3, l3;
        split_bf(out[i].x, h0, l0); split_bf(out[i].y, h1, l1);
        split_bf(out[i].z, h2, l2); split_bf(out[i].w, h3, l3);
        __nv_bfloat162 pa{h0, h1}, pb{h2, h3}, pc{l0, l1}, pd{l2, l3};
        uint2 uh{*(uint32_t*)&pa, *(uint32_t*)&pb};
        uint2 ul{*(uint32_t*)&pc, *(uint32_t*)&pd};
        *(uint2*)(mh + ob + i * 4) = uh;
        *(uint2*)(ml + ob + i * 4) = ul;
    }
}

// ---------------- final: gate/pool + proj + LN + gelu ----------------
__global__ void final_kernel(const float* __restrict__ x,
                             const float* __restrict__ gate_w, const float* __restrict__ gate_b,
                             const float* __restrict__ proj_w, const float* __restrict__ proj_b,
                             const float* __restrict__ pln_s, const float* __restrict__ pln_b,
                             float* __restrict__ out) {
    __shared__ float sx[NODES * D];
    __shared__ float sgate[NODES];
    __shared__ float comb[2 * D];
    __shared__ float red[4];
    int b = blockIdx.x, tid = threadIdx.x;
    for (int i = tid; i < NODES * D; i += 128) sx[i] = x[(size_t)b * NODES * D + i];
    __syncthreads();
    if (tid < NODES) {
        float acc = gate_b[0];
#pragma unroll 8
        for (int d = 0; d < D; d++) acc = fmaf(sx[tid * D + d], gate_w[d], acc);
        sgate[tid] = 1.0f / (1.0f + __expf(-acc));
    }
    __syncthreads();
    float pooled = 0.f;
#pragma unroll
    for (int n = 0; n < NODES; n++) pooled = fmaf(sx[n * D + tid], sgate[n], pooled);
    comb[tid]     = sx[11 * D + tid];
    comb[D + tid] = pooled;
    __syncthreads();
    float y = proj_b[tid];
#pragma unroll 8
    for (int c = 0; c < 2 * D; c++) y = fmaf(comb[c], proj_w[c * D + tid], y);
    float sum = y;
#pragma unroll
    for (int o = 16; o; o >>= 1) sum += __shfl_xor_sync(0xffffffffu, sum, o);
    if ((tid & 31) == 0) red[tid >> 5] = sum;
    __syncthreads();
    float mu = (red[0] + red[1] + red[2] + red[3]) * (1.0f / 128.0f);
    float c0 = y - mu;
    float cs = c0 * c0;
#pragma unroll
    for (int o = 16; o; o >>= 1) cs += __shfl_xor_sync(0xffffffffu, cs, o);
    __syncthreads();
    if ((tid & 31) == 0) red[tid >> 5] = cs;
    __syncthreads();
    float var = (red[0] + red[1] + red[2] + red[3]) * (1.0f / 128.0f);
    float yn = c0 * rsqrtf(var + 1e-5f) * pln_s[tid] + pln_b[tid];
    out[(size_t)b * D + tid] = gelu_exact(yn);
}

// ---------------- host orchestration ----------------
extern "C" void kernel_launch(void* const* d_in, const int* in_sizes, int n_in,
                              void* d_out, int out_size) {
    const float* patch   = (const float*)d_in[0];
    const float* band    = (const float*)d_in[1];
    const float* summ    = (const float*)d_in[2];
    const float* ln1_s   = (const float*)d_in[3];
    const float* ln1_b   = (const float*)d_in[4];
    const float* wq      = (const float*)d_in[5];
    const float* bq      = (const float*)d_in[6];
    const float* wk      = (const float*)d_in[7];
    const float* bk      = (const float*)d_in[8];
    const float* wv      = (const float*)d_in[9];
    const float* bv      = (const float*)d_in[10];
    const float* wo      = (const float*)d_in[11];
    const float* bo      = (const float*)d_in[12];
    const float* edge_b  = (const float*)d_in[13];
    const float* ln2_s   = (const float*)d_in[14];
    const float* ln2_b   = (const float*)d_in[15];
    const float* w1      = (const float*)d_in[16];
    const float* b1      = (const float*)d_in[17];
    const float* w2      = (const float*)d_in[18];
    const float* b2      = (const float*)d_in[19];
    const float* gate_w  = (const float*)d_in[20];
    const float* gate_b  = (const float*)d_in[21];
    const float* proj_w  = (const float*)d_in[22];
    const float* proj_b  = (const float*)d_in[23];
    const float* pln_s   = (const float*)d_in[24];
    const float* pln_b   = (const float*)d_in[25];
    float* out = (float*)d_out;

    float *x, *qkv, *bqkv;
    bf16 *hh, *hl, *mh, *ml, *th, *tl;
    bf16 *wqkvh, *wqkvl, *woh, *wol, *w1h, *w1l, *w2h, *w2l;
    cudaGetSymbolAddress((void**)&x,     g_x);
    cudaGetSymbolAddress((void**)&qkv,   g_qkv);
    cudaGetSymbolAddress((void**)&bqkv,  g_bqkv);
    cudaGetSymbolAddress((void**)&hh,    g_hh);
    cudaGetSymbolAddress((void**)&hl,    g_hl);
    cudaGetSymbolAddress((void**)&mh,    g_mh);
    cudaGetSymbolAddress((void**)&ml,    g_ml);
    cudaGetSymbolAddress((void**)&th,    g_th);
    cudaGetSymbolAddress((void**)&tl,    g_tl);
    cudaGetSymbolAddress((void**)&wqkvh, g_wqkvh);
    cudaGetSymbolAddress((void**)&wqkvl, g_wqkvl);
    cudaGetSymbolAddress((void**)&woh,   g_woh);
    cudaGetSymbolAddress((void**)&wol,   g_wol);
    cudaGetSymbolAddress((void**)&w1h,   g_w1h);
    cudaGetSymbolAddress((void**)&w1l,   g_w1l);
    cudaGetSymbolAddress((void**)&w2h,   g_w2h);
    cudaGetSymbolAddress((void**)&w2l,   g_w2l);

    static int smem_set = 0;
    if (!smem_set) {
        cudaFuncSetAttribute(tgemm_kernel, cudaFuncAttributeMaxDynamicSharedMemorySize, GEMM_SMEM);
        smem_set = 1;
    }

    init_ln_kernel<<<NTOK / 4, 128>>>(patch, band, summ, ln1_s, ln1_b, x, hh, hl);
    pack_qkvw_kernel<<<(98304 + 255) / 256, 256>>>(wq, wk, wv, bq, bk, bv, wqkvh, wqkvl, bqkv);
    pack_rest_kernel<<<(294912 + 255) / 256, 256>>>(wo, w1, w2, woh, wol, w1h, w1l, w2h, w2l);

    const int MT = NTOK / 128; // 192
    for (int l = 0; l < 2; l++) {
        // QKV (mode 0): N=384
        tgemm_kernel<<<dim3(3, MT), 256, GEMM_SMEM>>>(
            hh, hl, wqkvh + (size_t)l * 384 * 128, wqkvl + (size_t)l * 384 * 128, 128,
            bqkv + l * 384, qkv, 384, nullptr, nullptr, 0, nullptr, nullptr, nullptr, 0);
        attn_kernel<<<BATCH, 64>>>(qkv, edge_b + l * 36, mh, ml);
        // O-proj + residual + fused LN2 (mode 1): N=128
        tgemm_kernel<<<dim3(1, MT), 256, GEMM_SMEM>>>(
            mh, ml, woh + (size_t)l * 128 * 128, wol + (size_t)l * 128 * 128, 128,
            bo + l * 128, x, 128, hh, hl, 128, x, ln2_s + l * 128, ln2_b + l * 128, 1);
        // FFN1 + GELU (mode 2): N=512
        tgemm_kernel<<<dim3(4, MT), 256, GEMM_SMEM>>>(
            hh, hl, w1h + (size_t)l * 512 * 128, w1l + (size_t)l * 512 * 128, 128,
            b1 + l * 512, nullptr, 0, th, tl, 512, nullptr, nullptr, nullptr, 2);
        // FFN2 + residual (+ fused next-layer LN1) (mode 1): N=128, K=512
        const float* nls = (l == 0) ? (ln1_s + 128) : nullptr;
        const float* nlb = (l == 0) ? (ln1_b + 128) : nullptr;
        tgemm_kernel<<<dim3(1, MT), 256, GEMM_SMEM>>>(
            th, tl, w2h + (size_t)l * 128 * 512, w2l + (size_t)l * 128 * 512, 512,
            b2 + l * 128, x, 128, hh, hl, 128, x, nls, nlb, 1);
    }

    final_kernel<<<BATCH, 128>>>(x, gate_w, gate_b, proj_w, proj_b, pln_s, pln_b, out);
}

// round 10
// speedup vs baseline: 1.6212x; 1.2591x over previous
#include <cuda_runtime.h>
#include <cuda_fp16.h>
#include <math.h>
#include <stdint.h>

#define BATCH      2048
#define NODES      12
#define NTOK       (BATCH * NODES)     // 24576
#define D          128
#define F          512
#define NHEAD      4
#define DH         32
#define SCALE      0.17677669529663687f

typedef __half fp16;

// ---------------- scratch (device globals; no allocation) ----------------
__device__ __align__(16) float g_x   [NTOK * D];
__device__ __align__(16) float g_qkv [NTOK * 384];
__device__ __align__(16) fp16 g_hh[NTOK * D],  g_hl[NTOK * D];
__device__ __align__(16) fp16 g_mh[NTOK * D],  g_ml[NTOK * D];
__device__ __align__(16) fp16 g_th[NTOK * F],  g_tl[NTOK * F];
__device__ __align__(16) fp16 g_wqkv[2 * 384 * D];   // [l][n][k] single fp16
__device__ __align__(16) fp16 g_wo  [2 * D * D];
__device__ __align__(16) fp16 g_w1  [2 * F * D];
__device__ __align__(16) fp16 g_w2  [2 * D * F];
__device__ float g_bqkv[2 * 384];

__device__ __forceinline__ float gelu_exact(float x) {
    return 0.5f * x * (1.0f + erff(x * 0.7071067811865476f));
}
__device__ __forceinline__ void split_h(float x, fp16& h, fp16& l) {
    h = __float2half_rn(x);
    l = __float2half_rn(x - __half2float(h));
}
__device__ __forceinline__ uint32_t smem_u32(const void* p) {
    uint32_t a;
    asm("{ .reg .u64 t; cvta.to.shared.u64 t, %1; cvt.u32.u64 %0, t; }" : "=r"(a) : "l"(p));
    return a;
}
__device__ __forceinline__ void cp16(uint32_t dst, const void* src) {
    asm volatile("cp.async.ca.shared.global [%0], [%1], 16;" :: "r"(dst), "l"(src));
}
#define CP_COMMIT() asm volatile("cp.async.commit_group;" ::: "memory")
#define CP_WAIT(n)  asm volatile("cp.async.wait_group %0;" :: "n"(n) : "memory")

__device__ __forceinline__ void ldsm4(uint32_t* r, uint32_t addr) {
    asm volatile("ldmatrix.sync.aligned.m8n8.x4.shared.b16 {%0,%1,%2,%3}, [%4];"
        : "=r"(r[0]), "=r"(r[1]), "=r"(r[2]), "=r"(r[3]) : "r"(addr));
}
__device__ __forceinline__ void mma_f16(float* c, const uint32_t* a, uint32_t b0, uint32_t b1) {
    asm volatile(
        "mma.sync.aligned.m16n8k16.row.col.f32.f16.f16.f32 "
        "{%0,%1,%2,%3}, {%4,%5,%6,%7}, {%8,%9}, {%0,%1,%2,%3};"
        : "+f"(c[0]), "+f"(c[1]), "+f"(c[2]), "+f"(c[3])
        : "r"(a[0]), "r"(a[1]), "r"(a[2]), "r"(a[3]), "r"(b0), "r"(b1));
}

// ---------------- init + layer0 LN1 ----------------
__global__ void init_ln_kernel(const float* __restrict__ patch,
                               const float* __restrict__ band,
                               const float* __restrict__ summ,
                               const float* __restrict__ s, const float* __restrict__ b,
                               float* __restrict__ x,
                               fp16* __restrict__ oh, fp16* __restrict__ ol) {
    int row  = blockIdx.x * 4 + (threadIdx.x >> 5);
    int lane = threadIdx.x & 31;
    int node = row % NODES;
    int bb   = row / NODES;
    float v[4];
    float sum = 0.f;
#pragma unroll
    for (int i = 0; i < 4; i++) {
        int d = lane + 32 * i;
        float val;
        if (node < 6)       val = patch[(size_t)(bb * 6 + node) * D + d];
        else if (node < 11) val = band [(size_t)(bb * 5 + (node - 6)) * D + d];
        else                val = summ[d];
        v[i] = val;
        x[(size_t)row * D + d] = val;
        sum += val;
    }
#pragma unroll
    for (int o = 16; o; o >>= 1) sum += __shfl_xor_sync(0xffffffffu, sum, o);
    float mu = sum * (1.0f / 128.0f);
    float sq = 0.f;
#pragma unroll
    for (int i = 0; i < 4; i++) { float c = v[i] - mu; sq += c * c; }
#pragma unroll
    for (int o = 16; o; o >>= 1) sq += __shfl_xor_sync(0xffffffffu, sq, o);
    float inv = rsqrtf(sq * (1.0f / 128.0f) + 1e-5f);
#pragma unroll
    for (int i = 0; i < 4; i++) {
        int d = lane + 32 * i;
        float y = (v[i] - mu) * inv * s[d] + b[d];
        size_t o = (size_t)row * D + d;
        split_h(y, oh[o], ol[o]);
    }
}

// ---------------- weight packing (single fp16, [n][k] layout) ----------------
__global__ void pack_qkvw_kernel(const float* __restrict__ wq, const float* __restrict__ wk,
                                 const float* __restrict__ wv,
                                 const float* __restrict__ bq, const float* __restrict__ bk,
                                 const float* __restrict__ bv,
                                 fp16* __restrict__ qw, float* __restrict__ bqkv) {
    int idx = blockIdx.x * 256 + threadIdx.x;
    if (idx < 98304) { // wqkv: [l][n<384][k<128]
        int l = idx / 49152, r = idx % 49152;
        int n = r / 128, k = r % 128;
        const float* src = (n < 128) ? wq : ((n < 256) ? wk : wv);
        qw[idx] = __float2half_rn(src[(size_t)l * 16384 + k * 128 + (n & 127)]);
    }
    if (idx < 768) {
        int l = idx / 384, n = idx % 384;
        const float* sb = (n < 128) ? bq : ((n < 256) ? bk : bv);
        bqkv[idx] = sb[l * 128 + (n & 127)];
    }
}
__global__ void pack_rest_kernel(const float* __restrict__ wo,
                                 const float* __restrict__ w1, const float* __restrict__ w2,
                                 fp16* __restrict__ ow, fp16* __restrict__ w1w,
                                 fp16* __restrict__ w2w) {
    int idx = blockIdx.x * 256 + threadIdx.x;
    if (idx < 32768) { // wo: [l][n<128][k<128]
        int l = idx / 16384, r = idx % 16384;
        int n = r / 128, k = r % 128;
        ow[idx] = __float2half_rn(wo[(size_t)l * 16384 + k * 128 + n]);
    } else if (idx < 163840) { // w1: [l][n<512][k<128]  src [l][k<128][n<512]
        int t = idx - 32768;
        int l = t / 65536, r = t % 65536;
        int n = r / 128, k = r % 128;
        w1w[t] = __float2half_rn(w1[(size_t)l * 65536 + (size_t)k * 512 + n]);
    } else if (idx < 294912) { // w2: [l][n<128][k<512]  src [l][k<512][n<128]
        int t = idx - 163840;
        int l = t / 65536, r = t % 65536;
        int n = r / 512, k = r % 512;
        w2w[t] = __float2half_rn(w2[(size_t)l * 65536 + (size_t)k * 128 + n]);
    }
}

// ---------------- fp16x2 GEMM: BM=128 BN=128 BK=16, 256 thr (8 warps of 32x64) --------
// A split hi/lo fp16, W single fp16. D = Ah@W^T + Al@W^T. 4-stage cp.async; 2 CTAs/SM.
// mode 0: outf = D + bias (ldo)
// mode 1: v = D+bias+resid -> outf (N=128); if ln_s: fused rowwise LN -> oh/ol
// mode 2: split(gelu(D+bias)) -> oh/ol (ldh)
#define STG_B   18432
#define GEMM_SMEM (4 * STG_B)

__global__ __launch_bounds__(256, 2) void tgemm_kernel(
    const fp16* __restrict__ Ah, const fp16* __restrict__ Al,
    const fp16* __restrict__ W, int K,
    const float* __restrict__ bias,
    float* __restrict__ outf, int ldo,
    fp16* __restrict__ oh, fp16* __restrict__ ol, int ldh,
    const float* __restrict__ resid,
    const float* __restrict__ ln_s, const float* __restrict__ ln_b, int mode) {
    extern __shared__ __align__(16) char sm[];
    uint32_t sb = smem_u32(sm);
    const int tid = threadIdx.x, lane = tid & 31, wid = tid >> 5;
    const int bm = blockIdx.y * 128, bn = blockIdx.x * 128;
    const int wm = (wid & 3) * 32, wn = (wid >> 2) * 64;   // 4x2 warps, 32x64 tiles
    const int nst = K >> 4;

    // loader: each thread does 3 cp16 per stage (Ah, Al, W), pair-coalesced rows.
    const int lrow = tid >> 1, lhf = tid & 1;
    const fp16* p0 = Ah + (size_t)(bm + lrow) * K + lhf * 8;
    const fp16* p1 = Al + (size_t)(bm + lrow) * K + lhf * 8;
    const fp16* p2 = W  + (size_t)(bn + lrow) * K + lhf * 8;
    const uint32_t d0 = (uint32_t)(lrow * 48 + lhf * 16);

    float acc[2][8][4];
#pragma unroll
    for (int i = 0; i < 2; i++)
#pragma unroll
        for (int j = 0; j < 8; j++)
#pragma unroll
            for (int c = 0; c < 4; c++) acc[i][j][c] = 0.f;

    const uint32_t aoff = (uint32_t)((lane & 15) * 48 + (lane >> 4) * 16);
    const uint32_t boff = (uint32_t)(((((lane >> 4) << 3) + (lane & 7)) * 48) + ((lane >> 3) & 1) * 16);

#define LOAD_STAGE(s) do { \
    uint32_t base_ = sb + ((s) & 3) * STG_B; \
    int ko_ = (s) * 16; \
    cp16(base_ + d0,          p0 + ko_); \
    cp16(base_ + 6144 + d0,   p1 + ko_); \
    cp16(base_ + 12288 + d0,  p2 + ko_); \
} while (0)

    LOAD_STAGE(0); CP_COMMIT();
    if (nst > 1) { LOAD_STAGE(1); CP_COMMIT(); }
    if (nst > 2) { LOAD_STAGE(2); CP_COMMIT(); }

    for (int s = 0; s < nst; s++) {
        if (s + 3 < nst) { LOAD_STAGE(s + 3); CP_COMMIT(); CP_WAIT(3); }
        else {
            int rem = nst - 1 - s;
            if (rem == 2) CP_WAIT(2);
            else if (rem == 1) CP_WAIT(1);
            else CP_WAIT(0);
        }
        __syncthreads();
        uint32_t base = sb + (s & 3) * STG_B;

        uint32_t fah[2][4], fal[2][4];
#pragma unroll
        for (int mi = 0; mi < 2; mi++) {
            uint32_t ad = base + (uint32_t)((wm + mi * 16) * 48) + aoff;
            ldsm4(fah[mi], ad);
            ldsm4(fal[mi], ad + 6144);
        }
#pragma unroll
        for (int nj = 0; nj < 4; nj++) {
            uint32_t fw[4];
            ldsm4(fw, base + 12288u + (uint32_t)((wn + nj * 16) * 48) + boff);
#pragma unroll
            for (int mi = 0; mi < 2; mi++) {
                float* c0 = acc[mi][nj * 2];
                float* c1 = acc[mi][nj * 2 + 1];
                mma_f16(c0, fah[mi], fw[0], fw[1]);
                mma_f16(c0, fal[mi], fw[0], fw[1]);
                mma_f16(c1, fah[mi], fw[2], fw[3]);
                mma_f16(c1, fal[mi], fw[2], fw[3]);
            }
        }
        __syncthreads();
    }

    if (mode == 1) {
        // residual add, write x, stage tile in smem for fused LN
        float* smf = (float*)sm;  // 128x128 f32 = 64KB <= 72KB
#pragma unroll
        for (int mi = 0; mi < 2; mi++) {
            int lr0 = wm + mi * 16 + (lane >> 2);
            int lr1 = lr0 + 8;
#pragma unroll
            for (int ni = 0; ni < 8; ni++) {
                int col = wn + ni * 8 + 2 * (lane & 3);
                float b0 = bias[col], b1 = bias[col + 1];
                size_t o0 = (size_t)(bm + lr0) * 128 + col, o1 = (size_t)(bm + lr1) * 128 + col;
                float v0 = acc[mi][ni][0] + b0 + resid[o0];
                float v1 = acc[mi][ni][1] + b1 + resid[o0 + 1];
                float v2 = acc[mi][ni][2] + b0 + resid[o1];
                float v3 = acc[mi][ni][3] + b1 + resid[o1 + 1];
                *(float2*)&outf[o0] = make_float2(v0, v1);
                *(float2*)&outf[o1] = make_float2(v2, v3);
                smf[lr0 * 128 + col] = v0; smf[lr0 * 128 + col + 1] = v1;
                smf[lr1 * 128 + col] = v2; smf[lr1 * 128 + col + 1] = v3;
            }
        }
        if (ln_s) {
            __syncthreads();
            float4 s4 = *(const float4*)(ln_s + lane * 4);
            float4 b4 = *(const float4*)(ln_b + lane * 4);
#pragma unroll
            for (int t = 0; t < 16; t++) {
                int rr = wid * 16 + t;
                float4 v = ((const float4*)smf)[rr * 32 + lane];
                float sum = (v.x + v.y) + (v.z + v.w);
                float sq  = fmaf(v.x, v.x, fmaf(v.y, v.y, fmaf(v.z, v.z, v.w * v.w)));
#pragma unroll
                for (int o = 16; o; o >>= 1) {
                    sum += __shfl_xor_sync(0xffffffffu, sum, o);
                    sq  += __shfl_xor_sync(0xffffffffu, sq, o);
                }
                float mu  = sum * (1.0f / 128.0f);
                float var = sq * (1.0f / 128.0f) - mu * mu;
                float inv = rsqrtf(var + 1e-5f);
                float y0 = (v.x - mu) * inv * s4.x + b4.x;
                float y1 = (v.y - mu) * inv * s4.y + b4.y;
                float y2 = (v.z - mu) * inv * s4.z + b4.z;
                float y3 = (v.w - mu) * inv * s4.w + b4.w;
                fp16 h0, l0, h1, l1, h2, l2, h3, l3;
                split_h(y0, h0, l0); split_h(y1, h1, l1);
                split_h(y2, h2, l2); split_h(y3, h3, l3);
                __half2 ph0 = __halves2half2(h0, h1), ph1 = __halves2half2(h2, h3);
                __half2 pl0 = __halves2half2(l0, l1), pl1 = __halves2half2(l2, l3);
                uint2 uh{*(uint32_t*)&ph0, *(uint32_t*)&ph1};
                uint2 ul{*(uint32_t*)&pl0, *(uint32_t*)&pl1};
                size_t ob = (size_t)(bm + rr) * 128 + lane * 4;
                *(uint2*)(oh + ob) = uh;
                *(uint2*)(ol + ob) = ul;
            }
        }
        return;
    }

#pragma unroll
    for (int mi = 0; mi < 2; mi++) {
        int r0 = bm + wm + mi * 16 + (lane >> 2);
        int r1 = r0 + 8;
#pragma unroll
        for (int ni = 0; ni < 8; ni++) {
            int col = bn + wn + ni * 8 + 2 * (lane & 3);
            float b0 = bias[col], b1 = bias[col + 1];
            float v0 = acc[mi][ni][0] + b0, v1 = acc[mi][ni][1] + b1;
            float v2 = acc[mi][ni][2] + b0, v3 = acc[mi][ni][3] + b1;
            if (mode == 0) {
                size_t o0 = (size_t)r0 * ldo + col, o1 = (size_t)r1 * ldo + col;
                *(float2*)&outf[o0] = make_float2(v0, v1);
                *(float2*)&outf[o1] = make_float2(v2, v3);
            } else {
                v0 = gelu_exact(v0); v1 = gelu_exact(v1);
                v2 = gelu_exact(v2); v3 = gelu_exact(v3);
                fp16 h0, l0, h1, l1;
                size_t o0 = (size_t)r0 * ldh + col, o1 = (size_t)r1 * ldh + col;
                split_h(v0, h0, l0); split_h(v1, h1, l1);
                __half2 ph = __halves2half2(h0, h1), pl = __halves2half2(l0, l1);
                *(__half2*)&oh[o0] = ph;
                *(__half2*)&ol[o0] = pl;
                split_h(v2, h0, l0); split_h(v3, h1, l1);
                __half2 qh2 = __halves2half2(h0, h1), ql2 = __halves2half2(l0, l1);
                *(__half2*)&oh[o1] = qh2;
                *(__half2*)&ol[o1] = ql2;
            }
        }
    }
#undef LOAD_STAGE
}

// ---------------- dense 12-node attention, float4-vectorized ----------------
__global__ __launch_bounds__(64) void attn_kernel(const float* __restrict__ qkv,
                                                  const float* __restrict__ edge_bias,
                                                  fp16* __restrict__ mh, fp16* __restrict__ ml) {
    __shared__ float4 sk[NODES * 32];
    __shared__ float4 sv[NODES * 32];
    __shared__ float seb[36];
    int b = blockIdx.x;
    const float4* q4 = (const float4*)(qkv + (size_t)b * NODES * 384);
    for (int i = threadIdx.x; i < NODES * 32; i += 64) {
        int node = i >> 5, c = i & 31;
        sk[i] = q4[node * 96 + 32 + c];
        sv[i] = q4[node * 96 + 64 + c];
    }
    if (threadIdx.x < 36) seb[threadIdx.x] = edge_bias[threadIdx.x];
    __syncthreads();
    int tt = threadIdx.x;
    if (tt >= NODES * NHEAD) return;
    int dst = tt >> 2, hd = tt & 3;
    int kd = dst < 6 ? 0 : (dst < 11 ? 1 : 2);

    float4 q[8];
    const float4* qp = q4 + dst * 96 + hd * 8;
#pragma unroll
    for (int i = 0; i < 8; i++) q[i] = qp[i];

    float logits[NODES];
    float mx = -1e30f;
#pragma unroll
    for (int j = 0; j < NODES; j++) {
        const float4* kp = &sk[j * 32 + hd * 8];
        float d0 = 0.f, d1 = 0.f, d2 = 0.f, d3 = 0.f;
#pragma unroll
        for (int i = 0; i < 8; i++) {
            float4 kv = kp[i];
            d0 = fmaf(q[i].x, kv.x, d0);
            d1 = fmaf(q[i].y, kv.y, d1);
            d2 = fmaf(q[i].z, kv.z, d2);
            d3 = fmaf(q[i].w, kv.w, d3);
        }
        int ks = j < 6 ? 0 : (j < 11 ? 1 : 2);
        float lg = ((d0 + d1) + (d2 + d3)) * SCALE + seb[(ks * 3 + kd) * NHEAD + hd];
        logits[j] = lg;
        mx = fmaxf(mx, lg);
    }
    float z = 0.f;
#pragma unroll
    for (int j = 0; j < NODES; j++) { logits[j] = __expf(logits[j] - mx); z += logits[j]; }
    float inv = 1.0f / z;

    float4 out[8];
#pragma unroll
    for (int i = 0; i < 8; i++) out[i] = make_float4(0.f, 0.f, 0.f, 0.f);
#pragma unroll
    for (int j = 0; j < NODES; j++) {
        float a = logits[j] * inv;
        const float4* vp = &sv[j * 32 + hd * 8];
#pragma unroll
        for (int i = 0; i < 8; i++) {
            float4 vv = vp[i];
            out[i].x = fmaf(a, vv.x, out[i].x);
            out[i].y = fmaf(a, vv.y, out[i].y);
            out[i].z = fmaf(a, vv.z, out[i].z);
            out[i].w = fmaf(a, vv.w, out[i].w);
        }
    }
    size_t ob = (size_t)b * NODES * D + dst * D + hd * DH;
#pragma unroll
    for (int i = 0; i < 8; i++) {
        fp16 h0, l0, h1, l1, h2, l2, h3, l3;
        split_h(out[i].x, h0, l0); split_h(out[i].y, h1, l1);
        split_h(out[i].z, h2, l2); split_h(out[i].w, h3, l3);
        __half2 pa = __halves2half2(h0, h1), pb = __halves2half2(h2, h3);
        __half2 pc = __halves2half2(l0, l1), pd = __halves2half2(l2, l3);
        uint2 uh{*(uint32_t*)&pa, *(uint32_t*)&pb};
        uint2 ul{*(uint32_t*)&pc, *(uint32_t*)&pd};
        *(uint2*)(mh + ob + i * 4) = uh;
        *(uint2*)(ml + ob + i * 4) = ul;
    }
}

// ---------------- final: gate/pool + proj + LN + gelu ----------------
__global__ void final_kernel(const float* __restrict__ x,
                             const float* __restrict__ gate_w, const float* __restrict__ gate_b,
                             const float* __restrict__ proj_w, const float* __restrict__ proj_b,
                             const float* __restrict__ pln_s, const float* __restrict__ pln_b,
                             float* __restrict__ out) {
    __shared__ float sx[NODES * D];
    __shared__ float sgate[NODES];
    __shared__ float comb[2 * D];
    __shared__ float red[4];
    int b = blockIdx.x, tid = threadIdx.x;
    for (int i = tid; i < NODES * D; i += 128) sx[i] = x[(size_t)b * NODES * D + i];
    __syncthreads();
    if (tid < NODES) {
        float acc = gate_b[0];
#pragma unroll 8
        for (int d = 0; d < D; d++) acc = fmaf(sx[tid * D + d], gate_w[d], acc);
        sgate[tid] = 1.0f / (1.0f + __expf(-acc));
    }
    __syncthreads();
    float pooled = 0.f;
#pragma unroll
    for (int n = 0; n < NODES; n++) pooled = fmaf(sx[n * D + tid], sgate[n], pooled);
    comb[tid]     = sx[11 * D + tid];
    comb[D + tid] = pooled;
    __syncthreads();
    float y = proj_b[tid];
#pragma unroll 8
    for (int c = 0; c < 2 * D; c++) y = fmaf(comb[c], proj_w[c * D + tid], y);
    float sum = y;
#pragma unroll
    for (int o = 16; o; o >>= 1) sum += __shfl_xor_sync(0xffffffffu, sum, o);
    if ((tid & 31) == 0) red[tid >> 5] = sum;
    __syncthreads();
    float mu = (red[0] + red[1] + red[2] + red[3]) * (1.0f / 128.0f);
    float c0 = y - mu;
    float cs = c0 * c0;
#pragma unroll
    for (int o = 16; o; o >>= 1) cs += __shfl_xor_sync(0xffffffffu, cs, o);
    __syncthreads();
    if ((tid & 31) == 0) red[tid >> 5] = cs;
    __syncthreads();
    float var = (red[0] + red[1] + red[2] + red[3]) * (1.0f / 128.0f);
    float yn = c0 * rsqrtf(var + 1e-5f) * pln_s[tid] + pln_b[tid];
    out[(size_t)b * D + tid] = gelu_exact(yn);
}

// ---------------- host orchestration ----------------
extern "C" void kernel_launch(void* const* d_in, const int* in_sizes, int n_in,
                              void* d_out, int out_size) {
    const float* patch   = (const float*)d_in[0];
    const float* band    = (const float*)d_in[1];
    const float* summ    = (const float*)d_in[2];
    const float* ln1_s   = (const float*)d_in[3];
    const float* ln1_b   = (const float*)d_in[4];
    const float* wq      = (const float*)d_in[5];
    const float* bq      = (const float*)d_in[6];
    const float* wk      = (const float*)d_in[7];
    const float* bk      = (const float*)d_in[8];
    const float* wv      = (const float*)d_in[9];
    const float* bv      = (const float*)d_in[10];
    const float* wo      = (const float*)d_in[11];
    const float* bo      = (const float*)d_in[12];
    const float* edge_b  = (const float*)d_in[13];
    const float* ln2_s   = (const float*)d_in[14];
    const float* ln2_b   = (const float*)d_in[15];
    const float* w1      = (const float*)d_in[16];
    const float* b1      = (const float*)d_in[17];
    const float* w2      = (const float*)d_in[18];
    const float* b2      = (const float*)d_in[19];
    const float* gate_w  = (const float*)d_in[20];
    const float* gate_b  = (const float*)d_in[21];
    const float* proj_w  = (const float*)d_in[22];
    const float* proj_b  = (const float*)d_in[23];
    const float* pln_s   = (const float*)d_in[24];
    const float* pln_b   = (const float*)d_in[25];
    float* out = (float*)d_out;

    float *x, *qkv, *bqkv;
    fp16 *hh, *hl, *mh, *ml, *th, *tl;
    fp16 *wqkvw, *wow, *w1w, *w2w;
    cudaGetSymbolAddress((void**)&x,     g_x);
    cudaGetSymbolAddress((void**)&qkv,   g_qkv);
    cudaGetSymbolAddress((void**)&bqkv,  g_bqkv);
    cudaGetSymbolAddress((void**)&hh,    g_hh);
    cudaGetSymbolAddress((void**)&hl,    g_hl);
    cudaGetSymbolAddress((void**)&mh,    g_mh);
    cudaGetSymbolAddress((void**)&ml,    g_ml);
    cudaGetSymbolAddress((void**)&th,    g_th);
    cudaGetSymbolAddress((void**)&tl,    g_tl);
    cudaGetSymbolAddress((void**)&wqkvw, g_wqkv);
    cudaGetSymbolAddress((void**)&wow,   g_wo);
    cudaGetSymbolAddress((void**)&w1w,   g_w1);
    cudaGetSymbolAddress((void**)&w2w,   g_w2);

    static int smem_set = 0;
    if (!smem_set) {
        cudaFuncSetAttribute(tgemm_kernel, cudaFuncAttributeMaxDynamicSharedMemorySize, GEMM_SMEM);
        smem_set = 1;
    }

    init_ln_kernel<<<NTOK / 4, 128>>>(patch, band, summ, ln1_s, ln1_b, x, hh, hl);
    pack_qkvw_kernel<<<(98304 + 255) / 256, 256>>>(wq, wk, wv, bq, bk, bv, wqkvw, bqkv);
    pack_rest_kernel<<<(294912 + 255) / 256, 256>>>(wo, w1, w2, wow, w1w, w2w);

    const int MT = NTOK / 128; // 192
    for (int l = 0; l < 2; l++) {
        // QKV (mode 0): N=384
        tgemm_kernel<<<dim3(3, MT), 256, GEMM_SMEM>>>(
            hh, hl, wqkvw + (size_t)l * 384 * 128, 128,
            bqkv + l * 384, qkv, 384, nullptr, nullptr, 0, nullptr, nullptr, nullptr, 0);
        attn_kernel<<<BATCH, 64>>>(qkv, edge_b + l * 36, mh, ml);
        // O-proj + residual + fused LN2 (mode 1): N=128
        tgemm_kernel<<<dim3(1, MT), 256, GEMM_SMEM>>>(
            mh, ml, wow + (size_t)l * 128 * 128, 128,
            bo + l * 128, x, 128, hh, hl, 128, x, ln2_s + l * 128, ln2_b + l * 128, 1);
        // FFN1 + GELU (mode 2): N=512
        tgemm_kernel<<<dim3(4, MT), 256, GEMM_SMEM>>>(
            hh, hl, w1w + (size_t)l * 512 * 128, 128,
            b1 + l * 512, nullptr, 0, th, tl, 512, nullptr, nullptr, nullptr, 2);
        // FFN2 + residual (+ fused next-layer LN1) (mode 1): N=128, K=512
        const float* nls = (l == 0) ? (ln1_s + 128) : nullptr;
        const float* nlb = (l == 0) ? (ln1_b + 128) : nullptr;
        tgemm_kernel<<<dim3(1, MT), 256, GEMM_SMEM>>>(
            th, tl, w2w + (size_t)l * 128 * 512, 512,
            b2 + l * 128, x, 128, hh, hl, 128, x, nls, nlb, 1);
    }

    final_kernel<<<BATCH, 128>>>(x, gate_w, gate_b, proj_w, proj_b, pln_s, pln_b, out);
}

// round 11
// speedup vs baseline: 2.0001x; 1.2337x over previous
#include <cuda_runtime.h>
#include <cuda_fp16.h>
#include <math.h>
#include <stdint.h>

#define BATCH      2048
#define NODES      12
#define NTOK       (BATCH * NODES)     // 24576
#define D          128
#define F          512
#define NHEAD      4
#define DH         32
#define SCALE      0.17677669529663687f

typedef __half fp16;

// ---------------- scratch (device globals; no allocation) ----------------
__device__ __align__(16) float g_x   [NTOK * D];
__device__ __align__(16) float g_qkv [NTOK * 384];
__device__ __align__(16) fp16 g_h [NTOK * D];
__device__ __align__(16) fp16 g_m [NTOK * D];
__device__ __align__(16) fp16 g_t [NTOK * F];
__device__ __align__(16) fp16 g_wqkv[2 * 384 * D];   // [l][n][k]
__device__ __align__(16) fp16 g_wo  [2 * D * D];
__device__ __align__(16) fp16 g_w1  [2 * F * D];
__device__ __align__(16) fp16 g_w2  [2 * D * F];
__device__ float g_bqkv[2 * 384];

__device__ __forceinline__ float gelu_exact(float x) {
    return 0.5f * x * (1.0f + erff(x * 0.7071067811865476f));
}
__device__ __forceinline__ uint32_t smem_u32(const void* p) {
    uint32_t a;
    asm("{ .reg .u64 t; cvta.to.shared.u64 t, %1; cvt.u32.u64 %0, t; }" : "=r"(a) : "l"(p));
    return a;
}
__device__ __forceinline__ void cp16(uint32_t dst, const void* src) {
    asm volatile("cp.async.ca.shared.global [%0], [%1], 16;" :: "r"(dst), "l"(src));
}
#define CP_COMMIT() asm volatile("cp.async.commit_group;" ::: "memory")
#define CP_WAIT(n)  asm volatile("cp.async.wait_group %0;" :: "n"(n) : "memory")

__device__ __forceinline__ void ldsm4(uint32_t* r, uint32_t addr) {
    asm volatile("ldmatrix.sync.aligned.m8n8.x4.shared.b16 {%0,%1,%2,%3}, [%4];"
        : "=r"(r[0]), "=r"(r[1]), "=r"(r[2]), "=r"(r[3]) : "r"(addr));
}
__device__ __forceinline__ void mma_f16(float* c, const uint32_t* a, uint32_t b0, uint32_t b1) {
    asm volatile(
        "mma.sync.aligned.m16n8k16.row.col.f32.f16.f16.f32 "
        "{%0,%1,%2,%3}, {%4,%5,%6,%7}, {%8,%9}, {%0,%1,%2,%3};"
        : "+f"(c[0]), "+f"(c[1]), "+f"(c[2]), "+f"(c[3])
        : "r"(a[0]), "r"(a[1]), "r"(a[2]), "r"(a[3]), "r"(b0), "r"(b1));
}

// ---------------- init + layer0 LN1 ----------------
__global__ void init_ln_kernel(const float* __restrict__ patch,
                               const float* __restrict__ band,
                               const float* __restrict__ summ,
                               const float* __restrict__ s, const float* __restrict__ b,
                               float* __restrict__ x, fp16* __restrict__ oh) {
    int row  = blockIdx.x * 4 + (threadIdx.x >> 5);
    int lane = threadIdx.x & 31;
    int node = row % NODES;
    int bb   = row / NODES;
    float v[4];
    float sum = 0.f;
#pragma unroll
    for (int i = 0; i < 4; i++) {
        int d = lane + 32 * i;
        float val;
        if (node < 6)       val = patch[(size_t)(bb * 6 + node) * D + d];
        else if (node < 11) val = band [(size_t)(bb * 5 + (node - 6)) * D + d];
        else                val = summ[d];
        v[i] = val;
        x[(size_t)row * D + d] = val;
        sum += val;
    }
#pragma unroll
    for (int o = 16; o; o >>= 1) sum += __shfl_xor_sync(0xffffffffu, sum, o);
    float mu = sum * (1.0f / 128.0f);
    float sq = 0.f;
#pragma unroll
    for (int i = 0; i < 4; i++) { float c = v[i] - mu; sq += c * c; }
#pragma unroll
    for (int o = 16; o; o >>= 1) sq += __shfl_xor_sync(0xffffffffu, sq, o);
    float inv = rsqrtf(sq * (1.0f / 128.0f) + 1e-5f);
#pragma unroll
    for (int i = 0; i < 4; i++) {
        int d = lane + 32 * i;
        float y = (v[i] - mu) * inv * s[d] + b[d];
        oh[(size_t)row * D + d] = __float2half_rn(y);
    }
}

// ---------------- weight packing (single fp16, [n][k] layout) ----------------
__global__ void pack_qkvw_kernel(const float* __restrict__ wq, const float* __restrict__ wk,
                                 const float* __restrict__ wv,
                                 const float* __restrict__ bq, const float* __restrict__ bk,
                                 const float* __restrict__ bv,
                                 fp16* __restrict__ qw, float* __restrict__ bqkv) {
    int idx = blockIdx.x * 256 + threadIdx.x;
    if (idx < 98304) { // wqkv: [l][n<384][k<128]
        int l = idx / 49152, r = idx % 49152;
        int n = r / 128, k = r % 128;
        const float* src = (n < 128) ? wq : ((n < 256) ? wk : wv);
        qw[idx] = __float2half_rn(src[(size_t)l * 16384 + k * 128 + (n & 127)]);
    }
    if (idx < 768) {
        int l = idx / 384, n = idx % 384;
        const float* sb = (n < 128) ? bq : ((n < 256) ? bk : bv);
        bqkv[idx] = sb[l * 128 + (n & 127)];
    }
}
__global__ void pack_rest_kernel(const float* __restrict__ wo,
                                 const float* __restrict__ w1, const float* __restrict__ w2,
                                 fp16* __restrict__ ow, fp16* __restrict__ w1w,
                                 fp16* __restrict__ w2w) {
    int idx = blockIdx.x * 256 + threadIdx.x;
    if (idx < 32768) { // wo: [l][n<128][k<128]
        int l = idx / 16384, r = idx % 16384;
        int n = r / 128, k = r % 128;
        ow[idx] = __float2half_rn(wo[(size_t)l * 16384 + k * 128 + n]);
    } else if (idx < 163840) { // w1: [l][n<512][k<128]
        int t = idx - 32768;
        int l = t / 65536, r = t % 65536;
        int n = r / 128, k = r % 128;
        w1w[t] = __float2half_rn(w1[(size_t)l * 65536 + (size_t)k * 512 + n]);
    } else if (idx < 294912) { // w2: [l][n<128][k<512]
        int t = idx - 163840;
        int l = t / 65536, r = t % 65536;
        int n = r / 512, k = r % 512;
        w2w[t] = __float2half_rn(w2[(size_t)l * 65536 + (size_t)k * 128 + n]);
    }
}

// ---------------- fp16 GEMM: BM=128 BN=128 BK=16, 256 thr (8 warps of 32x64) --------
// A fp16 [M][K], W fp16 [N][K]. 4-stage cp.async, ONE sync per stage; 2 CTAs/SM.
// mode 0: outf = D + bias (ldo)
// mode 1: v = D+bias+resid -> outf (N=128); if ln_s: fused rowwise LN -> oh
// mode 2: gelu(D+bias) -> oh (ldh)
#define STG_B   12288
#define GEMM_SMEM 65536   // >= max(4*STG_B=49152, 128*128*4 for LN staging)

__global__ __launch_bounds__(256, 2) void tgemm_kernel(
    const fp16* __restrict__ A, const fp16* __restrict__ W, int K,
    const float* __restrict__ bias,
    float* __restrict__ outf, int ldo,
    fp16* __restrict__ oh, int ldh,
    const float* __restrict__ resid,
    const float* __restrict__ ln_s, const float* __restrict__ ln_b, int mode) {
    extern __shared__ __align__(16) char sm[];
    uint32_t sb = smem_u32(sm);
    const int tid = threadIdx.x, lane = tid & 31, wid = tid >> 5;
    const int bm = blockIdx.y * 128, bn = blockIdx.x * 128;
    const int wm = (wid & 3) * 32, wn = (wid >> 2) * 64;   // 4x2 warps, 32x64 tiles
    const int nst = K >> 4;

    // loader: pair-coalesced; each thread 2 cp16/stage (one A row-half, one W row-half)
    const int lrow = tid >> 1, lhf = tid & 1;
    const fp16* p0 = A + (size_t)(bm + lrow) * K + lhf * 8;
    const fp16* p1 = W + (size_t)(bn + lrow) * K + lhf * 8;
    const uint32_t d0 = (uint32_t)(lrow * 48 + lhf * 16);

    float acc[2][8][4];
#pragma unroll
    for (int i = 0; i < 2; i++)
#pragma unroll
        for (int j = 0; j < 8; j++)
#pragma unroll
            for (int c = 0; c < 4; c++) acc[i][j][c] = 0.f;

    const uint32_t aoff = (uint32_t)((lane & 15) * 48 + (lane >> 4) * 16);
    const uint32_t boff = (uint32_t)(((((lane >> 4) << 3) + (lane & 7)) * 48) + ((lane >> 3) & 1) * 16);

#define LOAD_STAGE(s) do { \
    uint32_t base_ = sb + ((s) & 3) * STG_B; \
    int ko_ = (s) * 16; \
    cp16(base_ + d0,         p0 + ko_); \
    cp16(base_ + 6144 + d0,  p1 + ko_); \
} while (0)

    LOAD_STAGE(0); CP_COMMIT();
    if (nst > 1) { LOAD_STAGE(1); CP_COMMIT(); }
    if (nst > 2) { LOAD_STAGE(2); CP_COMMIT(); }

    for (int s = 0; s < nst; s++) {
        int rem = nst - 1 - s;   // stages committed beyond s
        if (rem >= 2) CP_WAIT(2);
        else if (rem == 1) CP_WAIT(1);
        else CP_WAIT(0);
        __syncthreads();          // all warps done reading buffer (s-1)&3, stage s resident
        if (s + 3 < nst) { LOAD_STAGE(s + 3); CP_COMMIT(); }

        uint32_t base = sb + (s & 3) * STG_B;
        uint32_t fa[2][4];
#pragma unroll
        for (int mi = 0; mi < 2; mi++)
            ldsm4(fa[mi], base + (uint32_t)((wm + mi * 16) * 48) + aoff);
#pragma unroll
        for (int nj = 0; nj < 4; nj++) {
            uint32_t fw[4];
            ldsm4(fw, base + 6144u + (uint32_t)((wn + nj * 16) * 48) + boff);
#pragma unroll
            for (int mi = 0; mi < 2; mi++) {
                mma_f16(acc[mi][nj * 2],     fa[mi], fw[0], fw[1]);
                mma_f16(acc[mi][nj * 2 + 1], fa[mi], fw[2], fw[3]);
            }
        }
    }
    __syncthreads();

    if (mode == 1) {
        float* smf = (float*)sm;  // 128x128 f32 = 64KB
#pragma unroll
        for (int mi = 0; mi < 2; mi++) {
            int lr0 = wm + mi * 16 + (lane >> 2);
            int lr1 = lr0 + 8;
#pragma unroll
            for (int ni = 0; ni < 8; ni++) {
                int col = wn + ni * 8 + 2 * (lane & 3);
                float b0 = bias[col], b1 = bias[col + 1];
                size_t o0 = (size_t)(bm + lr0) * 128 + col, o1 = (size_t)(bm + lr1) * 128 + col;
                float v0 = acc[mi][ni][0] + b0 + resid[o0];
                float v1 = acc[mi][ni][1] + b1 + resid[o0 + 1];
                float v2 = acc[mi][ni][2] + b0 + resid[o1];
                float v3 = acc[mi][ni][3] + b1 + resid[o1 + 1];
                *(float2*)&outf[o0] = make_float2(v0, v1);
                *(float2*)&outf[o1] = make_float2(v2, v3);
                smf[lr0 * 128 + col] = v0; smf[lr0 * 128 + col + 1] = v1;
                smf[lr1 * 128 + col] = v2; smf[lr1 * 128 + col + 1] = v3;
            }
        }
        if (ln_s) {
            __syncthreads();
            float4 s4 = *(const float4*)(ln_s + lane * 4);
            float4 b4 = *(const float4*)(ln_b + lane * 4);
#pragma unroll
            for (int t = 0; t < 16; t++) {
                int rr = wid * 16 + t;
                float4 v = ((const float4*)smf)[rr * 32 + lane];
                float sum = (v.x + v.y) + (v.z + v.w);
                float sq  = fmaf(v.x, v.x, fmaf(v.y, v.y, fmaf(v.z, v.z, v.w * v.w)));
#pragma unroll
                for (int o = 16; o; o >>= 1) {
                    sum += __shfl_xor_sync(0xffffffffu, sum, o);
                    sq  += __shfl_xor_sync(0xffffffffu, sq, o);
                }
                float mu  = sum * (1.0f / 128.0f);
                float var = sq * (1.0f / 128.0f) - mu * mu;
                float inv = rsqrtf(var + 1e-5f);
                __half2 h0 = __floats2half2_rn((v.x - mu) * inv * s4.x + b4.x,
                                               (v.y - mu) * inv * s4.y + b4.y);
                __half2 h1 = __floats2half2_rn((v.z - mu) * inv * s4.z + b4.z,
                                               (v.w - mu) * inv * s4.w + b4.w);
                uint2 uh{*(uint32_t*)&h0, *(uint32_t*)&h1};
                *(uint2*)(oh + (size_t)(bm + rr) * 128 + lane * 4) = uh;
            }
        }
        return;
    }

#pragma unroll
    for (int mi = 0; mi < 2; mi++) {
        int r0 = bm + wm + mi * 16 + (lane >> 2);
        int r1 = r0 + 8;
#pragma unroll
        for (int ni = 0; ni < 8; ni++) {
            int col = bn + wn + ni * 8 + 2 * (lane & 3);
            float b0 = bias[col], b1 = bias[col + 1];
            float v0 = acc[mi][ni][0] + b0, v1 = acc[mi][ni][1] + b1;
            float v2 = acc[mi][ni][2] + b0, v3 = acc[mi][ni][3] + b1;
            if (mode == 0) {
                size_t o0 = (size_t)r0 * ldo + col, o1 = (size_t)r1 * ldo + col;
                *(float2*)&outf[o0] = make_float2(v0, v1);
                *(float2*)&outf[o1] = make_float2(v2, v3);
            } else {
                size_t o0 = (size_t)r0 * ldh + col, o1 = (size_t)r1 * ldh + col;
                __half2 h0 = __floats2half2_rn(gelu_exact(v0), gelu_exact(v1));
                __half2 h1 = __floats2half2_rn(gelu_exact(v2), gelu_exact(v3));
                *(__half2*)&oh[o0] = h0;
                *(__half2*)&oh[o1] = h1;
            }
        }
    }
#undef LOAD_STAGE
}

// ---------------- dense 12-node attention, float4-vectorized ----------------
__global__ __launch_bounds__(64) void attn_kernel(const float* __restrict__ qkv,
                                                  const float* __restrict__ edge_bias,
                                                  fp16* __restrict__ mh) {
    __shared__ float4 sk[NODES * 32];
    __shared__ float4 sv[NODES * 32];
    __shared__ float seb[36];
    int b = blockIdx.x;
    const float4* q4 = (const float4*)(qkv + (size_t)b * NODES * 384);
    for (int i = threadIdx.x; i < NODES * 32; i += 64) {
        int node = i >> 5, c = i & 31;
        sk[i] = q4[node * 96 + 32 + c];
        sv[i] = q4[node * 96 + 64 + c];
    }
    if (threadIdx.x < 36) seb[threadIdx.x] = edge_bias[threadIdx.x];
    __syncthreads();
    int tt = threadIdx.x;
    if (tt >= NODES * NHEAD) return;
    int dst = tt >> 2, hd = tt & 3;
    int kd = dst < 6 ? 0 : (dst < 11 ? 1 : 2);

    float4 q[8];
    const float4* qp = q4 + dst * 96 + hd * 8;
#pragma unroll
    for (int i = 0; i < 8; i++) q[i] = qp[i];

    float logits[NODES];
    float mx = -1e30f;
#pragma unroll
    for (int j = 0; j < NODES; j++) {
        const float4* kp = &sk[j * 32 + hd * 8];
        float d0 = 0.f, d1 = 0.f, d2 = 0.f, d3 = 0.f;
#pragma unroll
        for (int i = 0; i < 8; i++) {
            float4 kv = kp[i];
            d0 = fmaf(q[i].x, kv.x, d0);
            d1 = fmaf(q[i].y, kv.y, d1);
            d2 = fmaf(q[i].z, kv.z, d2);
            d3 = fmaf(q[i].w, kv.w, d3);
        }
        int ks = j < 6 ? 0 : (j < 11 ? 1 : 2);
        float lg = ((d0 + d1) + (d2 + d3)) * SCALE + seb[(ks * 3 + kd) * NHEAD + hd];
        logits[j] = lg;
        mx = fmaxf(mx, lg);
    }
    float z = 0.f;
#pragma unroll
    for (int j = 0; j < NODES; j++) { logits[j] = __expf(logits[j] - mx); z += logits[j]; }
    float inv = 1.0f / z;

    float4 out[8];
#pragma unroll
    for (int i = 0; i < 8; i++) out[i] = make_float4(0.f, 0.f, 0.f, 0.f);
#pragma unroll
    for (int j = 0; j < NODES; j++) {
        float a = logits[j] * inv;
        const float4* vp = &sv[j * 32 + hd * 8];
#pragma unroll
        for (int i = 0; i < 8; i++) {
            float4 vv = vp[i];
            out[i].x = fmaf(a, vv.x, out[i].x);
            out[i].y = fmaf(a, vv.y, out[i].y);
            out[i].z = fmaf(a, vv.z, out[i].z);
            out[i].w = fmaf(a, vv.w, out[i].w);
        }
    }
    size_t ob = (size_t)b * NODES * D + dst * D + hd * DH;
#pragma unroll
    for (int i = 0; i < 8; i++) {
        __half2 h0 = __floats2half2_rn(out[i].x, out[i].y);
        __half2 h1 = __floats2half2_rn(out[i].z, out[i].w);
        uint2 uh{*(uint32_t*)&h0, *(uint32_t*)&h1};
        *(uint2*)(mh + ob + i * 4) = uh;
    }
}

// ---------------- final: gate/pool + proj + LN + gelu ----------------
__global__ void final_kernel(const float* __restrict__ x,
                             const float* __restrict__ gate_w, const float* __restrict__ gate_b,
                             const float* __restrict__ proj_w, const float* __restrict__ proj_b,
                             const float* __restrict__ pln_s, const float* __restrict__ pln_b,
                             float* __restrict__ out) {
    __shared__ float sx[NODES * D];
    __shared__ float sgate[NODES];
    __shared__ float comb[2 * D];
    __shared__ float red[4];
    int b = blockIdx.x, tid = threadIdx.x;
    for (int i = tid; i < NODES * D; i += 128) sx[i] = x[(size_t)b * NODES * D + i];
    __syncthreads();
    if (tid < NODES) {
        float acc = gate_b[0];
#pragma unroll 8
        for (int d = 0; d < D; d++) acc = fmaf(sx[tid * D + d], gate_w[d], acc);
        sgate[tid] = 1.0f / (1.0f + __expf(-acc));
    }
    __syncthreads();
    float pooled = 0.f;
#pragma unroll
    for (int n = 0; n < NODES; n++) pooled = fmaf(sx[n * D + tid], sgate[n], pooled);
    comb[tid]     = sx[11 * D + tid];
    comb[D + tid] = pooled;
    __syncthreads();
    float y = proj_b[tid];
#pragma unroll 8
    for (int c = 0; c < 2 * D; c++) y = fmaf(comb[c], proj_w[c * D + tid], y);
    float sum = y;
#pragma unroll
    for (int o = 16; o; o >>= 1) sum += __shfl_xor_sync(0xffffffffu, sum, o);
    if ((tid & 31) == 0) red[tid >> 5] = sum;
    __syncthreads();
    float mu = (red[0] + red[1] + red[2] + red[3]) * (1.0f / 128.0f);
    float c0 = y - mu;
    float cs = c0 * c0;
#pragma unroll
    for (int o = 16; o; o >>= 1) cs += __shfl_xor_sync(0xffffffffu, cs, o);
    __syncthreads();
    if ((tid & 31) == 0) red[tid >> 5] = cs;
    __syncthreads();
    float var = (red[0] + red[1] + red[2] + red[3]) * (1.0f / 128.0f);
    float yn = c0 * rsqrtf(var + 1e-5f) * pln_s[tid] + pln_b[tid];
    out[(size_t)b * D + tid] = gelu_exact(yn);
}

// ---------------- host orchestration ----------------
extern "C" void kernel_launch(void* const* d_in, const int* in_sizes, int n_in,
                              void* d_out, int out_size) {
    const float* patch   = (const float*)d_in[0];
    const float* band    = (const float*)d_in[1];
    const float* summ    = (const float*)d_in[2];
    const float* ln1_s   = (const float*)d_in[3];
    const float* ln1_b   = (const float*)d_in[4];
    const float* wq      = (const float*)d_in[5];
    const float* bq      = (const float*)d_in[6];
    const float* wk      = (const float*)d_in[7];
    const float* bk      = (const float*)d_in[8];
    const float* wv      = (const float*)d_in[9];
    const float* bv      = (const float*)d_in[10];
    const float* wo      = (const float*)d_in[11];
    const float* bo      = (const float*)d_in[12];
    const float* edge_b  = (const float*)d_in[13];
    const float* ln2_s   = (const float*)d_in[14];
    const float* ln2_b   = (const float*)d_in[15];
    const float* w1      = (const float*)d_in[16];
    const float* b1      = (const float*)d_in[17];
    const float* w2      = (const float*)d_in[18];
    const float* b2      = (const float*)d_in[19];
    const float* gate_w  = (const float*)d_in[20];
    const float* gate_b  = (const float*)d_in[21];
    const float* proj_w  = (const float*)d_in[22];
    const float* proj_b  = (const float*)d_in[23];
    const float* pln_s   = (const float*)d_in[24];
    const float* pln_b   = (const float*)d_in[25];
    float* out = (float*)d_out;

    float *x, *qkv, *bqkv;
    fp16 *hbuf, *mbuf, *tbuf;
    fp16 *wqkvw, *wow, *w1w, *w2w;
    cudaGetSymbolAddress((void**)&x,     g_x);
    cudaGetSymbolAddress((void**)&qkv,   g_qkv);
    cudaGetSymbolAddress((void**)&bqkv,  g_bqkv);
    cudaGetSymbolAddress((void**)&hbuf,  g_h);
    cudaGetSymbolAddress((void**)&mbuf,  g_m);
    cudaGetSymbolAddress((void**)&tbuf,  g_t);
    cudaGetSymbolAddress((void**)&wqkvw, g_wqkv);
    cudaGetSymbolAddress((void**)&wow,   g_wo);
    cudaGetSymbolAddress((void**)&w1w,   g_w1);
    cudaGetSymbolAddress((void**)&w2w,   g_w2);

    static int smem_set = 0;
    if (!smem_set) {
        cudaFuncSetAttribute(tgemm_kernel, cudaFuncAttributeMaxDynamicSharedMemorySize, GEMM_SMEM);
        smem_set = 1;
    }

    init_ln_kernel<<<NTOK / 4, 128>>>(patch, band, summ, ln1_s, ln1_b, x, hbuf);
    pack_qkvw_kernel<<<(98304 + 255) / 256, 256>>>(wq, wk, wv, bq, bk, bv, wqkvw, bqkv);
    pack_rest_kernel<<<(294912 + 255) / 256, 256>>>(wo, w1, w2, wow, w1w, w2w);

    const int MT = NTOK / 128; // 192
    for (int l = 0; l < 2; l++) {
        // QKV (mode 0): N=384
        tgemm_kernel<<<dim3(3, MT), 256, GEMM_SMEM>>>(
            hbuf, wqkvw + (size_t)l * 384 * 128, 128,
            bqkv + l * 384, qkv, 384, nullptr, 0, nullptr, nullptr, nullptr, 0);
        attn_kernel<<<BATCH, 64>>>(qkv, edge_b + l * 36, mbuf);
        // O-proj + residual + fused LN2 (mode 1): N=128
        tgemm_kernel<<<dim3(1, MT), 256, GEMM_SMEM>>>(
            mbuf, wow + (size_t)l * 128 * 128, 128,
            bo + l * 128, x, 128, hbuf, 128, x, ln2_s + l * 128, ln2_b + l * 128, 1);
        // FFN1 + GELU (mode 2): N=512
        tgemm_kernel<<<dim3(4, MT), 256, GEMM_SMEM>>>(
            hbuf, w1w + (size_t)l * 512 * 128, 128,
            b1 + l * 512, nullptr, 0, tbuf, 512, nullptr, nullptr, nullptr, 2);
        // FFN2 + residual (+ fused next-layer LN1) (mode 1): N=128, K=512
        const float* nls = (l == 0) ? (ln1_s + 128) : nullptr;
        const float* nlb = (l == 0) ? (ln1_b + 128) : nullptr;
        tgemm_kernel<<<dim3(1, MT), 256, GEMM_SMEM>>>(
            tbuf, w2w + (size_t)l * 128 * 512, 512,
            b2 + l * 128, x, 128, hbuf, 128, x, nls, nlb, 1);
    }

    final_kernel<<<BATCH, 128>>>(x, gate_w, gate_b, proj_w, proj_b, pln_s, pln_b, out);
}

// round 12
// speedup vs baseline: 2.0244x; 1.0121x over previous
#include <cuda_runtime.h>
#include <cuda_fp16.h>
#include <math.h>
#include <stdint.h>

#define BATCH      2048
#define NODES      12
#define NTOK       (BATCH * NODES)     // 24576
#define D          128
#define F          512
#define NHEAD      4
#define DH         32
#define SCALE      0.17677669529663687f

typedef __half fp16;

// ---------------- scratch (device globals; no allocation) ----------------
__device__ __align__(16) float g_x   [NTOK * D];
__device__ __align__(16) fp16 g_qkv [NTOK * 384];
__device__ __align__(16) fp16 g_h [NTOK * D];
__device__ __align__(16) fp16 g_m [NTOK * D];
__device__ __align__(16) fp16 g_t [NTOK * F];
__device__ __align__(16) fp16 g_wqkv[2 * 384 * D];   // [l][n][k]
__device__ __align__(16) fp16 g_wo  [2 * D * D];
__device__ __align__(16) fp16 g_w1  [2 * F * D];
__device__ __align__(16) fp16 g_w2  [2 * D * F];
__device__ float g_bqkv[2 * 384];

__device__ __forceinline__ float gelu_exact(float x) {
    return 0.5f * x * (1.0f + erff(x * 0.7071067811865476f));
}
__device__ __forceinline__ uint32_t smem_u32(const void* p) {
    uint32_t a;
    asm("{ .reg .u64 t; cvta.to.shared.u64 t, %1; cvt.u32.u64 %0, t; }" : "=r"(a) : "l"(p));
    return a;
}
__device__ __forceinline__ void cp16(uint32_t dst, const void* src) {
    asm volatile("cp.async.ca.shared.global [%0], [%1], 16;" :: "r"(dst), "l"(src));
}
#define CP_COMMIT() asm volatile("cp.async.commit_group;" ::: "memory")
#define CP_WAIT(n)  asm volatile("cp.async.wait_group %0;" :: "n"(n) : "memory")

__device__ __forceinline__ void ldsm4(uint32_t* r, uint32_t addr) {
    asm volatile("ldmatrix.sync.aligned.m8n8.x4.shared.b16 {%0,%1,%2,%3}, [%4];"
        : "=r"(r[0]), "=r"(r[1]), "=r"(r[2]), "=r"(r[3]) : "r"(addr));
}
__device__ __forceinline__ void mma_f16(float* c, const uint32_t* a, uint32_t b0, uint32_t b1) {
    asm volatile(
        "mma.sync.aligned.m16n8k16.row.col.f32.f16.f16.f32 "
        "{%0,%1,%2,%3}, {%4,%5,%6,%7}, {%8,%9}, {%0,%1,%2,%3};"
        : "+f"(c[0]), "+f"(c[1]), "+f"(c[2]), "+f"(c[3])
        : "r"(a[0]), "r"(a[1]), "r"(a[2]), "r"(a[3]), "r"(b0), "r"(b1));
}

// ---------------- init + layer0 LN1 ----------------
__global__ void init_ln_kernel(const float* __restrict__ patch,
                               const float* __restrict__ band,
                               const float* __restrict__ summ,
                               const float* __restrict__ s, const float* __restrict__ b,
                               float* __restrict__ x, fp16* __restrict__ oh) {
    int row  = blockIdx.x * 4 + (threadIdx.x >> 5);
    int lane = threadIdx.x & 31;
    int node = row % NODES;
    int bb   = row / NODES;
    float v[4];
    float sum = 0.f;
#pragma unroll
    for (int i = 0; i < 4; i++) {
        int d = lane + 32 * i;
        float val;
        if (node < 6)       val = patch[(size_t)(bb * 6 + node) * D + d];
        else if (node < 11) val = band [(size_t)(bb * 5 + (node - 6)) * D + d];
        else                val = summ[d];
        v[i] = val;
        x[(size_t)row * D + d] = val;
        sum += val;
    }
#pragma unroll
    for (int o = 16; o; o >>= 1) sum += __shfl_xor_sync(0xffffffffu, sum, o);
    float mu = sum * (1.0f / 128.0f);
    float sq = 0.f;
#pragma unroll
    for (int i = 0; i < 4; i++) { float c = v[i] - mu; sq += c * c; }
#pragma unroll
    for (int o = 16; o; o >>= 1) sq += __shfl_xor_sync(0xffffffffu, sq, o);
    float inv = rsqrtf(sq * (1.0f / 128.0f) + 1e-5f);
#pragma unroll
    for (int i = 0; i < 4; i++) {
        int d = lane + 32 * i;
        float y = (v[i] - mu) * inv * s[d] + b[d];
        oh[(size_t)row * D + d] = __float2half_rn(y);
    }
}

// ---------------- weight packing (single fp16, [n][k] layout) ----------------
__global__ void pack_qkvw_kernel(const float* __restrict__ wq, const float* __restrict__ wk,
                                 const float* __restrict__ wv,
                                 const float* __restrict__ bq, const float* __restrict__ bk,
                                 const float* __restrict__ bv,
                                 fp16* __restrict__ qw, float* __restrict__ bqkv) {
    int idx = blockIdx.x * 256 + threadIdx.x;
    if (idx < 98304) {
        int l = idx / 49152, r = idx % 49152;
        int n = r / 128, k = r % 128;
        const float* src = (n < 128) ? wq : ((n < 256) ? wk : wv);
        qw[idx] = __float2half_rn(src[(size_t)l * 16384 + k * 128 + (n & 127)]);
    }
    if (idx < 768) {
        int l = idx / 384, n = idx % 384;
        const float* sb = (n < 128) ? bq : ((n < 256) ? bk : bv);
        bqkv[idx] = sb[l * 128 + (n & 127)];
    }
}
__global__ void pack_rest_kernel(const float* __restrict__ wo,
                                 const float* __restrict__ w1, const float* __restrict__ w2,
                                 fp16* __restrict__ ow, fp16* __restrict__ w1w,
                                 fp16* __restrict__ w2w) {
    int idx = blockIdx.x * 256 + threadIdx.x;
    if (idx < 32768) {
        int l = idx / 16384, r = idx % 16384;
        int n = r / 128, k = r % 128;
        ow[idx] = __float2half_rn(wo[(size_t)l * 16384 + k * 128 + n]);
    } else if (idx < 163840) {
        int t = idx - 32768;
        int l = t / 65536, r = t % 65536;
        int n = r / 128, k = r % 128;
        w1w[t] = __float2half_rn(w1[(size_t)l * 65536 + (size_t)k * 512 + n]);
    } else if (idx < 294912) {
        int t = idx - 163840;
        int l = t / 65536, r = t % 65536;
        int n = r / 512, k = r % 512;
        w2w[t] = __float2half_rn(w2[(size_t)l * 65536 + (size_t)k * 128 + n]);
    }
}

// ---------------- fp16 GEMM: BM=128 BN=128 BK=32 (2x k16 sub-tiles/stage) ------------
// 256 thr, 8 warps of 32x64; 3-stage cp.async; one __syncthreads per 32-K; 2 CTAs/SM.
// mode 0: oh = half(D + bias) (ldh)
// mode 1: v = D+bias+resid -> outf (N=128); if ln_s: fused rowwise LN -> oh
// mode 2: oh = half(gelu(D+bias)) (ldh)
#define STG_B   24576
#define GEMM_SMEM 73728   // 3*STG_B; also >= 64KB LN staging

__global__ __launch_bounds__(256, 2) void tgemm_kernel(
    const fp16* __restrict__ A, const fp16* __restrict__ W, int K,
    const float* __restrict__ bias,
    float* __restrict__ outf,
    fp16* __restrict__ oh, int ldh,
    const float* __restrict__ resid,
    const float* __restrict__ ln_s, const float* __restrict__ ln_b, int mode) {
    extern __shared__ __align__(16) char sm[];
    uint32_t sb = smem_u32(sm);
    const int tid = threadIdx.x, lane = tid & 31, wid = tid >> 5;
    const int bm = blockIdx.y * 128, bn = blockIdx.x * 128;
    const int wm = (wid & 3) * 32, wn = (wid >> 2) * 64;
    const int nst = K >> 5;

    // loader: pair-coalesced rows; 4 cp16/thread/stage (A sub0, A sub1, W sub0, W sub1)
    const int lrow = tid >> 1, lhf = tid & 1;
    const fp16* p0 = A + (size_t)(bm + lrow) * K + lhf * 8;
    const fp16* p1 = W + (size_t)(bn + lrow) * K + lhf * 8;
    const uint32_t d0 = (uint32_t)(lrow * 48 + lhf * 16);

    float acc[2][8][4];
#pragma unroll
    for (int i = 0; i < 2; i++)
#pragma unroll
        for (int j = 0; j < 8; j++)
#pragma unroll
            for (int c = 0; c < 4; c++) acc[i][j][c] = 0.f;

    const uint32_t aoff = (uint32_t)((lane & 15) * 48 + (lane >> 4) * 16);
    const uint32_t boff = (uint32_t)(((((lane >> 4) << 3) + (lane & 7)) * 48) + ((lane >> 3) & 1) * 16);

#define LOAD_STAGE(s) do { \
    uint32_t base_ = sb + ((s) % 3) * STG_B; \
    int ko_ = (s) * 32; \
    cp16(base_ + d0,          p0 + ko_); \
    cp16(base_ + 6144 + d0,   p0 + ko_ + 16); \
    cp16(base_ + 12288 + d0,  p1 + ko_); \
    cp16(base_ + 18432 + d0,  p1 + ko_ + 16); \
} while (0)

    LOAD_STAGE(0); CP_COMMIT();
    if (nst > 1) { LOAD_STAGE(1); CP_COMMIT(); }

    for (int s = 0; s < nst; s++) {
        if (s + 1 < nst) CP_WAIT(1); else CP_WAIT(0);
        __syncthreads();
        if (s + 2 < nst) { LOAD_STAGE(s + 2); CP_COMMIT(); }

        uint32_t base = sb + (s % 3) * STG_B;
        uint32_t fa[2][2][4];   // [sub][mi]
#pragma unroll
        for (int mi = 0; mi < 2; mi++) {
            uint32_t ad = base + (uint32_t)((wm + mi * 16) * 48) + aoff;
            ldsm4(fa[0][mi], ad);
            ldsm4(fa[1][mi], ad + 6144);
        }
#pragma unroll
        for (int sub = 0; sub < 2; sub++) {
            uint32_t wb = base + 12288u + (uint32_t)sub * 6144u;
#pragma unroll
            for (int nj = 0; nj < 4; nj++) {
                uint32_t fw[4];
                ldsm4(fw, wb + (uint32_t)((wn + nj * 16) * 48) + boff);
#pragma unroll
                for (int mi = 0; mi < 2; mi++) {
                    mma_f16(acc[mi][nj * 2],     fa[sub][mi], fw[0], fw[1]);
                    mma_f16(acc[mi][nj * 2 + 1], fa[sub][mi], fw[2], fw[3]);
                }
            }
        }
    }
    __syncthreads();

    if (mode == 1) {
        float* smf = (float*)sm;  // 128x128 f32 = 64KB
#pragma unroll
        for (int mi = 0; mi < 2; mi++) {
            int lr0 = wm + mi * 16 + (lane >> 2);
            int lr1 = lr0 + 8;
#pragma unroll
            for (int ni = 0; ni < 8; ni++) {
                int col = wn + ni * 8 + 2 * (lane & 3);
                float b0 = bias[col], b1 = bias[col + 1];
                size_t o0 = (size_t)(bm + lr0) * 128 + col, o1 = (size_t)(bm + lr1) * 128 + col;
                float v0 = acc[mi][ni][0] + b0 + resid[o0];
                float v1 = acc[mi][ni][1] + b1 + resid[o0 + 1];
                float v2 = acc[mi][ni][2] + b0 + resid[o1];
                float v3 = acc[mi][ni][3] + b1 + resid[o1 + 1];
                *(float2*)&outf[o0] = make_float2(v0, v1);
                *(float2*)&outf[o1] = make_float2(v2, v3);
                smf[lr0 * 128 + col] = v0; smf[lr0 * 128 + col + 1] = v1;
                smf[lr1 * 128 + col] = v2; smf[lr1 * 128 + col + 1] = v3;
            }
        }
        if (ln_s) {
            __syncthreads();
            float4 s4 = *(const float4*)(ln_s + lane * 4);
            float4 b4 = *(const float4*)(ln_b + lane * 4);
#pragma unroll
            for (int t = 0; t < 16; t++) {
                int rr = wid * 16 + t;
                float4 v = ((const float4*)smf)[rr * 32 + lane];
                float sum = (v.x + v.y) + (v.z + v.w);
                float sq  = fmaf(v.x, v.x, fmaf(v.y, v.y, fmaf(v.z, v.z, v.w * v.w)));
#pragma unroll
                for (int o = 16; o; o >>= 1) {
                    sum += __shfl_xor_sync(0xffffffffu, sum, o);
                    sq  += __shfl_xor_sync(0xffffffffu, sq, o);
                }
                float mu  = sum * (1.0f / 128.0f);
                float var = sq * (1.0f / 128.0f) - mu * mu;
                float inv = rsqrtf(var + 1e-5f);
                __half2 h0 = __floats2half2_rn((v.x - mu) * inv * s4.x + b4.x,
                                               (v.y - mu) * inv * s4.y + b4.y);
                __half2 h1 = __floats2half2_rn((v.z - mu) * inv * s4.z + b4.z,
                                               (v.w - mu) * inv * s4.w + b4.w);
                uint2 uh{*(uint32_t*)&h0, *(uint32_t*)&h1};
                *(uint2*)(oh + (size_t)(bm + rr) * 128 + lane * 4) = uh;
            }
        }
        return;
    }

#pragma unroll
    for (int mi = 0; mi < 2; mi++) {
        int r0 = bm + wm + mi * 16 + (lane >> 2);
        int r1 = r0 + 8;
#pragma unroll
        for (int ni = 0; ni < 8; ni++) {
            int col = bn + wn + ni * 8 + 2 * (lane & 3);
            float b0 = bias[col], b1 = bias[col + 1];
            float v0 = acc[mi][ni][0] + b0, v1 = acc[mi][ni][1] + b1;
            float v2 = acc[mi][ni][2] + b0, v3 = acc[mi][ni][3] + b1;
            size_t o0 = (size_t)r0 * ldh + col, o1 = (size_t)r1 * ldh + col;
            if (mode == 2) {
                v0 = gelu_exact(v0); v1 = gelu_exact(v1);
                v2 = gelu_exact(v2); v3 = gelu_exact(v3);
            }
            __half2 h0 = __floats2half2_rn(v0, v1);
            __half2 h1 = __floats2half2_rn(v2, v3);
            *(__half2*)&oh[o0] = h0;
            *(__half2*)&oh[o1] = h1;
        }
    }
#undef LOAD_STAGE
}

// ---------------- dense 12-node attention (fp16 qkv input) ----------------
__global__ __launch_bounds__(64) void attn_kernel(const fp16* __restrict__ qkv,
                                                  const float* __restrict__ edge_bias,
                                                  fp16* __restrict__ mh) {
    __shared__ float sk[NODES * D];
    __shared__ float sv[NODES * D];
    __shared__ float seb[36];
    int b = blockIdx.x;
    const uint4* src = (const uint4*)(qkv + (size_t)b * NODES * 384);  // 48 uint4 per node row
    for (int i = threadIdx.x; i < NODES * 32; i += 64) {
        int node = i >> 5, c = i & 31;   // c<16 -> k chunk, else v chunk
        uint4 u = src[node * 48 + 16 + c];
        float* dp = (c < 16) ? &sk[node * D + c * 8] : &sv[node * D + (c - 16) * 8];
        float2 f0 = __half22float2(*(__half2*)&u.x);
        float2 f1 = __half22float2(*(__half2*)&u.y);
        float2 f2 = __half22float2(*(__half2*)&u.z);
        float2 f3 = __half22float2(*(__half2*)&u.w);
        dp[0] = f0.x; dp[1] = f0.y; dp[2] = f1.x; dp[3] = f1.y;
        dp[4] = f2.x; dp[5] = f2.y; dp[6] = f3.x; dp[7] = f3.y;
    }
    if (threadIdx.x < 36) seb[threadIdx.x] = edge_bias[threadIdx.x];
    __syncthreads();
    int tt = threadIdx.x;
    if (tt >= NODES * NHEAD) return;
    int dst = tt >> 2, hd = tt & 3;
    int kd = dst < 6 ? 0 : (dst < 11 ? 1 : 2);

    // q: 32 halfs = 4 uint4 from gmem
    float q[DH];
    {
        const uint4* qp = src + dst * 48 + hd * 4;
#pragma unroll
        for (int i = 0; i < 4; i++) {
            uint4 u = qp[i];
            float2 f0 = __half22float2(*(__half2*)&u.x);
            float2 f1 = __half22float2(*(__half2*)&u.y);
            float2 f2 = __half22float2(*(__half2*)&u.z);
            float2 f3 = __half22float2(*(__half2*)&u.w);
            q[i * 8 + 0] = f0.x; q[i * 8 + 1] = f0.y; q[i * 8 + 2] = f1.x; q[i * 8 + 3] = f1.y;
            q[i * 8 + 4] = f2.x; q[i * 8 + 5] = f2.y; q[i * 8 + 6] = f3.x; q[i * 8 + 7] = f3.y;
        }
    }

    float logits[NODES];
    float mx = -1e30f;
#pragma unroll
    for (int j = 0; j < NODES; j++) {
        const float4* kp = (const float4*)&sk[j * D + hd * DH];
        float d0 = 0.f, d1 = 0.f, d2 = 0.f, d3 = 0.f;
#pragma unroll
        for (int i = 0; i < 8; i++) {
            float4 kv = kp[i];
            d0 = fmaf(q[i * 4 + 0], kv.x, d0);
            d1 = fmaf(q[i * 4 + 1], kv.y, d1);
            d2 = fmaf(q[i * 4 + 2], kv.z, d2);
            d3 = fmaf(q[i * 4 + 3], kv.w, d3);
        }
        int ks = j < 6 ? 0 : (j < 11 ? 1 : 2);
        float lg = ((d0 + d1) + (d2 + d3)) * SCALE + seb[(ks * 3 + kd) * NHEAD + hd];
        logits[j] = lg;
        mx = fmaxf(mx, lg);
    }
    float z = 0.f;
#pragma unroll
    for (int j = 0; j < NODES; j++) { logits[j] = __expf(logits[j] - mx); z += logits[j]; }
    float inv = 1.0f / z;

    float4 out[8];
#pragma unroll
    for (int i = 0; i < 8; i++) out[i] = make_float4(0.f, 0.f, 0.f, 0.f);
#pragma unroll
    for (int j = 0; j < NODES; j++) {
        float a = logits[j] * inv;
        const float4* vp = (const float4*)&sv[j * D + hd * DH];
#pragma unroll
        for (int i = 0; i < 8; i++) {
            float4 vv = vp[i];
            out[i].x = fmaf(a, vv.x, out[i].x);
            out[i].y = fmaf(a, vv.y, out[i].y);
            out[i].z = fmaf(a, vv.z, out[i].z);
            out[i].w = fmaf(a, vv.w, out[i].w);
        }
    }
    size_t ob = (size_t)b * NODES * D + dst * D + hd * DH;
#pragma unroll
    for (int i = 0; i < 8; i++) {
        __half2 h0 = __floats2half2_rn(out[i].x, out[i].y);
        __half2 h1 = __floats2half2_rn(out[i].z, out[i].w);
        uint2 uh{*(uint32_t*)&h0, *(uint32_t*)&h1};
        *(uint2*)(mh + ob + i * 4) = uh;
    }
}

// ---------------- final: gate/pool + proj + LN + gelu ----------------
__global__ void final_kernel(const float* __restrict__ x,
                             const float* __restrict__ gate_w, const float* __restrict__ gate_b,
                             const float* __restrict__ proj_w, const float* __restrict__ proj_b,
                             const float* __restrict__ pln_s, const float* __restrict__ pln_b,
                             float* __restrict__ out) {
    __shared__ float sx[NODES * D];
    __shared__ float sgate[NODES];
    __shared__ float comb[2 * D];
    __shared__ float red[4];
    int b = blockIdx.x, tid = threadIdx.x;
    for (int i = tid; i < NODES * D; i += 128) sx[i] = x[(size_t)b * NODES * D + i];
    __syncthreads();
    if (tid < NODES) {
        float acc = gate_b[0];
#pragma unroll 8
        for (int d = 0; d < D; d++) acc = fmaf(sx[tid * D + d], gate_w[d], acc);
        sgate[tid] = 1.0f / (1.0f + __expf(-acc));
    }
    __syncthreads();
    float pooled = 0.f;
#pragma unroll
    for (int n = 0; n < NODES; n++) pooled = fmaf(sx[n * D + tid], sgate[n], pooled);
    comb[tid]     = sx[11 * D + tid];
    comb[D + tid] = pooled;
    __syncthreads();
    float y = proj_b[tid];
#pragma unroll 8
    for (int c = 0; c < 2 * D; c++) y = fmaf(comb[c], proj_w[c * D + tid], y);
    float sum = y;
#pragma unroll
    for (int o = 16; o; o >>= 1) sum += __shfl_xor_sync(0xffffffffu, sum, o);
    if ((tid & 31) == 0) red[tid >> 5] = sum;
    __syncthreads();
    float mu = (red[0] + red[1] + red[2] + red[3]) * (1.0f / 128.0f);
    float c0 = y - mu;
    float cs = c0 * c0;
#pragma unroll
    for (int o = 16; o; o >>= 1) cs += __shfl_xor_sync(0xffffffffu, cs, o);
    __syncthreads();
    if ((tid & 31) == 0) red[tid >> 5] = cs;
    __syncthreads();
    float var = (red[0] + red[1] + red[2] + red[3]) * (1.0f / 128.0f);
    float yn = c0 * rsqrtf(var + 1e-5f) * pln_s[tid] + pln_b[tid];
    out[(size_t)b * D + tid] = gelu_exact(yn);
}

// ---------------- host orchestration ----------------
extern "C" void kernel_launch(void* const* d_in, const int* in_sizes, int n_in,
                              void* d_out, int out_size) {
    const float* patch   = (const float*)d_in[0];
    const float* band    = (const float*)d_in[1];
    const float* summ    = (const float*)d_in[2];
    const float* ln1_s   = (const float*)d_in[3];
    const float* ln1_b   = (const float*)d_in[4];
    const float* wq      = (const float*)d_in[5];
    const float* bq      = (const float*)d_in[6];
    const float* wk      = (const float*)d_in[7];
    const float* bk      = (const float*)d_in[8];
    const float* wv      = (const float*)d_in[9];
    const float* bv      = (const float*)d_in[10];
    const float* wo      = (const float*)d_in[11];
    const float* bo      = (const float*)d_in[12];
    const float* edge_b  = (const float*)d_in[13];
    const float* ln2_s   = (const float*)d_in[14];
    const float* ln2_b   = (const float*)d_in[15];
    const float* w1      = (const float*)d_in[16];
    const float* b1      = (const float*)d_in[17];
    const float* w2      = (const float*)d_in[18];
    const float* b2      = (const float*)d_in[19];
    const float* gate_w  = (const float*)d_in[20];
    const float* gate_b  = (const float*)d_in[21];
    const float* proj_w  = (const float*)d_in[22];
    const float* proj_b  = (const float*)d_in[23];
    const float* pln_s   = (const float*)d_in[24];
    const float* pln_b   = (const float*)d_in[25];
    float* out = (float*)d_out;

    float *x, *bqkv;
    fp16 *qkv, *hbuf, *mbuf, *tbuf;
    fp16 *wqkvw, *wow, *w1w, *w2w;
    cudaGetSymbolAddress((void**)&x,     g_x);
    cudaGetSymbolAddress((void**)&qkv,   g_qkv);
    cudaGetSymbolAddress((void**)&bqkv,  g_bqkv);
    cudaGetSymbolAddress((void**)&hbuf,  g_h);
    cudaGetSymbolAddress((void**)&mbuf,  g_m);
    cudaGetSymbolAddress((void**)&tbuf,  g_t);
    cudaGetSymbolAddress((void**)&wqkvw, g_wqkv);
    cudaGetSymbolAddress((void**)&wow,   g_wo);
    cudaGetSymbolAddress((void**)&w1w,   g_w1);
    cudaGetSymbolAddress((void**)&w2w,   g_w2);

    static int smem_set = 0;
    if (!smem_set) {
        cudaFuncSetAttribute(tgemm_kernel, cudaFuncAttributeMaxDynamicSharedMemorySize, GEMM_SMEM);
        smem_set = 1;
    }

    init_ln_kernel<<<NTOK / 4, 128>>>(patch, band, summ, ln1_s, ln1_b, x, hbuf);
    pack_qkvw_kernel<<<(98304 + 255) / 256, 256>>>(wq, wk, wv, bq, bk, bv, wqkvw, bqkv);
    pack_rest_kernel<<<(294912 + 255) / 256, 256>>>(wo, w1, w2, wow, w1w, w2w);

    const int MT = NTOK / 128; // 192
    for (int l = 0; l < 2; l++) {
        // QKV (mode 0): N=384, fp16 out
        tgemm_kernel<<<dim3(3, MT), 256, GEMM_SMEM>>>(
            hbuf, wqkvw + (size_t)l * 384 * 128, 128,
            bqkv + l * 384, nullptr, qkv, 384, nullptr, nullptr, nullptr, 0);
        attn_kernel<<<BATCH, 64>>>(qkv, edge_b + l * 36, mbuf);
        // O-proj + residual + fused LN2 (mode 1): N=128
        tgemm_kernel<<<dim3(1, MT), 256, GEMM_SMEM>>>(
            mbuf, wow + (size_t)l * 128 * 128, 128,
            bo + l * 128, x, hbuf, 128, x, ln2_s + l * 128, ln2_b + l * 128, 1);
        // FFN1 + GELU (mode 2): N=512
        tgemm_kernel<<<dim3(4, MT), 256, GEMM_SMEM>>>(
            hbuf, w1w + (size_t)l * 512 * 128, 128,
            b1 + l * 512, nullptr, tbuf, 512, nullptr, nullptr, nullptr, 2);
        // FFN2 + residual (+ fused next-layer LN1) (mode 1): N=128, K=512
        const float* nls = (l == 0) ? (ln1_s + 128) : nullptr;
        const float* nlb = (l == 0) ? (ln1_b + 128) : nullptr;
        tgemm_kernel<<<dim3(1, MT), 256, GEMM_SMEM>>>(
            tbuf, w2w + (size_t)l * 128 * 512, 512,
            b2 + l * 128, x, hbuf, 128, x, nls, nlb, 1);
    }

    final_kernel<<<BATCH, 128>>>(x, gate_w, gate_b, proj_w, proj_b, pln_s, pln_b, out);
}

// round 13
// speedup vs baseline: 2.1157x; 1.0451x over previous
#include <cuda_runtime.h>
#include <cuda_fp16.h>
#include <math.h>
#include <stdint.h>

#define BATCH      2048
#define NODES      12
#define NTOK       (BATCH * NODES)     // 24576
#define D          128
#define F          512
#define NHEAD      4
#define DH         32
#define SCALE      0.17677669529663687f

typedef __half fp16;

// ---------------- scratch (device globals; no allocation) ----------------
__device__ __align__(16) float g_x   [NTOK * D];
__device__ __align__(16) fp16 g_qkv [NTOK * 384];
__device__ __align__(16) fp16 g_h [NTOK * D];
__device__ __align__(16) fp16 g_m [NTOK * D];
__device__ __align__(16) fp16 g_t [NTOK * F];
__device__ __align__(16) fp16 g_wqkv[2 * 384 * D];   // [l][n][k]
__device__ __align__(16) fp16 g_wo  [2 * D * D];
__device__ __align__(16) fp16 g_w1  [2 * F * D];
__device__ __align__(16) fp16 g_w2  [2 * D * F];
__device__ float g_bqkv[2 * 384];

__device__ __forceinline__ float gelu_exact(float x) {
    return 0.5f * x * (1.0f + erff(x * 0.7071067811865476f));
}
__device__ __forceinline__ uint32_t smem_u32(const void* p) {
    uint32_t a;
    asm("{ .reg .u64 t; cvta.to.shared.u64 t, %1; cvt.u32.u64 %0, t; }" : "=r"(a) : "l"(p));
    return a;
}
__device__ __forceinline__ void cp16(uint32_t dst, const void* src) {
    asm volatile("cp.async.ca.shared.global [%0], [%1], 16;" :: "r"(dst), "l"(src));
}
#define CP_COMMIT() asm volatile("cp.async.commit_group;" ::: "memory")
#define CP_WAIT(n)  asm volatile("cp.async.wait_group %0;" :: "n"(n) : "memory")

__device__ __forceinline__ void ldsm4(uint32_t* r, uint32_t addr) {
    asm volatile("ldmatrix.sync.aligned.m8n8.x4.shared.b16 {%0,%1,%2,%3}, [%4];"
        : "=r"(r[0]), "=r"(r[1]), "=r"(r[2]), "=r"(r[3]) : "r"(addr));
}
__device__ __forceinline__ void mma_f16(float* c, const uint32_t* a, uint32_t b0, uint32_t b1) {
    asm volatile(
        "mma.sync.aligned.m16n8k16.row.col.f32.f16.f16.f32 "
        "{%0,%1,%2,%3}, {%4,%5,%6,%7}, {%8,%9}, {%0,%1,%2,%3};"
        : "+f"(c[0]), "+f"(c[1]), "+f"(c[2]), "+f"(c[3])
        : "r"(a[0]), "r"(a[1]), "r"(a[2]), "r"(a[3]), "r"(b0), "r"(b1));
}

// ---------------- init + layer0 LN1 ----------------
__global__ void init_ln_kernel(const float* __restrict__ patch,
                               const float* __restrict__ band,
                               const float* __restrict__ summ,
                               const float* __restrict__ s, const float* __restrict__ b,
                               float* __restrict__ x, fp16* __restrict__ oh) {
    int row  = blockIdx.x * 4 + (threadIdx.x >> 5);
    int lane = threadIdx.x & 31;
    int node = row % NODES;
    int bb   = row / NODES;
    float v[4];
    float sum = 0.f;
#pragma unroll
    for (int i = 0; i < 4; i++) {
        int d = lane + 32 * i;
        float val;
        if (node < 6)       val = patch[(size_t)(bb * 6 + node) * D + d];
        else if (node < 11) val = band [(size_t)(bb * 5 + (node - 6)) * D + d];
        else                val = summ[d];
        v[i] = val;
        x[(size_t)row * D + d] = val;
        sum += val;
    }
#pragma unroll
    for (int o = 16; o; o >>= 1) sum += __shfl_xor_sync(0xffffffffu, sum, o);
    float mu = sum * (1.0f / 128.0f);
    float sq = 0.f;
#pragma unroll
    for (int i = 0; i < 4; i++) { float c = v[i] - mu; sq += c * c; }
#pragma unroll
    for (int o = 16; o; o >>= 1) sq += __shfl_xor_sync(0xffffffffu, sq, o);
    float inv = rsqrtf(sq * (1.0f / 128.0f) + 1e-5f);
#pragma unroll
    for (int i = 0; i < 4; i++) {
        int d = lane + 32 * i;
        float y = (v[i] - mu) * inv * s[d] + b[d];
        oh[(size_t)row * D + d] = __float2half_rn(y);
    }
}

// ---------------- weight packing (single fp16, [n][k] layout) ----------------
__global__ void pack_qkvw_kernel(const float* __restrict__ wq, const float* __restrict__ wk,
                                 const float* __restrict__ wv,
                                 const float* __restrict__ bq, const float* __restrict__ bk,
                                 const float* __restrict__ bv,
                                 fp16* __restrict__ qw, float* __restrict__ bqkv) {
    int idx = blockIdx.x * 256 + threadIdx.x;
    if (idx < 98304) {
        int l = idx / 49152, r = idx % 49152;
        int n = r / 128, k = r % 128;
        const float* src = (n < 128) ? wq : ((n < 256) ? wk : wv);
        qw[idx] = __float2half_rn(src[(size_t)l * 16384 + k * 128 + (n & 127)]);
    }
    if (idx < 768) {
        int l = idx / 384, n = idx % 384;
        const float* sb = (n < 128) ? bq : ((n < 256) ? bk : bv);
        bqkv[idx] = sb[l * 128 + (n & 127)];
    }
}
__global__ void pack_rest_kernel(const float* __restrict__ wo,
                                 const float* __restrict__ w1, const float* __restrict__ w2,
                                 fp16* __restrict__ ow, fp16* __restrict__ w1w,
                                 fp16* __restrict__ w2w) {
    int idx = blockIdx.x * 256 + threadIdx.x;
    if (idx < 32768) {
        int l = idx / 16384, r = idx % 16384;
        int n = r / 128, k = r % 128;
        ow[idx] = __float2half_rn(wo[(size_t)l * 16384 + k * 128 + n]);
    } else if (idx < 163840) {
        int t = idx - 32768;
        int l = t / 65536, r = t % 65536;
        int n = r / 128, k = r % 128;
        w1w[t] = __float2half_rn(w1[(size_t)l * 65536 + (size_t)k * 512 + n]);
    } else if (idx < 294912) {
        int t = idx - 163840;
        int l = t / 65536, r = t % 65536;
        int n = r / 512, k = r % 512;
        w2w[t] = __float2half_rn(w2[(size_t)l * 65536 + (size_t)k * 128 + n]);
    }
}

// ---------------- fp16 GEMM (big): BM=128 BN=128 BK=32, 256 thr, 2 CTAs/SM ------------
// mode 0: oh = half(D + bias) (ldh);  mode 2: oh = half(gelu(D+bias)) (ldh)
#define STG_B   24576
#define GEMM_SMEM 73728

__global__ __launch_bounds__(256, 2) void tgemm_kernel(
    const fp16* __restrict__ A, const fp16* __restrict__ W, int K,
    const float* __restrict__ bias,
    fp16* __restrict__ oh, int ldh, int mode) {
    extern __shared__ __align__(16) char sm[];
    uint32_t sb = smem_u32(sm);
    const int tid = threadIdx.x, lane = tid & 31, wid = tid >> 5;
    const int bm = blockIdx.y * 128, bn = blockIdx.x * 128;
    const int wm = (wid & 3) * 32, wn = (wid >> 2) * 64;
    const int nst = K >> 5;

    const int lrow = tid >> 1, lhf = tid & 1;
    const fp16* p0 = A + (size_t)(bm + lrow) * K + lhf * 8;
    const fp16* p1 = W + (size_t)(bn + lrow) * K + lhf * 8;
    const uint32_t d0 = (uint32_t)(lrow * 48 + lhf * 16);

    float acc[2][8][4];
#pragma unroll
    for (int i = 0; i < 2; i++)
#pragma unroll
        for (int j = 0; j < 8; j++)
#pragma unroll
            for (int c = 0; c < 4; c++) acc[i][j][c] = 0.f;

    const uint32_t aoff = (uint32_t)((lane & 15) * 48 + (lane >> 4) * 16);
    const uint32_t boff = (uint32_t)(((((lane >> 4) << 3) + (lane & 7)) * 48) + ((lane >> 3) & 1) * 16);

#define LOAD_STAGE(s) do { \
    uint32_t base_ = sb + ((s) % 3) * STG_B; \
    int ko_ = (s) * 32; \
    cp16(base_ + d0,          p0 + ko_); \
    cp16(base_ + 6144 + d0,   p0 + ko_ + 16); \
    cp16(base_ + 12288 + d0,  p1 + ko_); \
    cp16(base_ + 18432 + d0,  p1 + ko_ + 16); \
} while (0)

    LOAD_STAGE(0); CP_COMMIT();
    if (nst > 1) { LOAD_STAGE(1); CP_COMMIT(); }

    for (int s = 0; s < nst; s++) {
        if (s + 1 < nst) CP_WAIT(1); else CP_WAIT(0);
        __syncthreads();
        if (s + 2 < nst) { LOAD_STAGE(s + 2); CP_COMMIT(); }

        uint32_t base = sb + (s % 3) * STG_B;
        uint32_t fa[2][2][4];
#pragma unroll
        for (int mi = 0; mi < 2; mi++) {
            uint32_t ad = base + (uint32_t)((wm + mi * 16) * 48) + aoff;
            ldsm4(fa[0][mi], ad);
            ldsm4(fa[1][mi], ad + 6144);
        }
#pragma unroll
        for (int sub = 0; sub < 2; sub++) {
            uint32_t wb = base + 12288u + (uint32_t)sub * 6144u;
#pragma unroll
            for (int nj = 0; nj < 4; nj++) {
                uint32_t fw[4];
                ldsm4(fw, wb + (uint32_t)((wn + nj * 16) * 48) + boff);
#pragma unroll
                for (int mi = 0; mi < 2; mi++) {
                    mma_f16(acc[mi][nj * 2],     fa[sub][mi], fw[0], fw[1]);
                    mma_f16(acc[mi][nj * 2 + 1], fa[sub][mi], fw[2], fw[3]);
                }
            }
        }
    }

#pragma unroll
    for (int mi = 0; mi < 2; mi++) {
        int r0 = bm + wm + mi * 16 + (lane >> 2);
        int r1 = r0 + 8;
#pragma unroll
        for (int ni = 0; ni < 8; ni++) {
            int col = bn + wn + ni * 8 + 2 * (lane & 3);
            float b0 = bias[col], b1 = bias[col + 1];
            float v0 = acc[mi][ni][0] + b0, v1 = acc[mi][ni][1] + b1;
            float v2 = acc[mi][ni][2] + b0, v3 = acc[mi][ni][3] + b1;
            size_t o0 = (size_t)r0 * ldh + col, o1 = (size_t)r1 * ldh + col;
            if (mode == 2) {
                v0 = gelu_exact(v0); v1 = gelu_exact(v1);
                v2 = gelu_exact(v2); v3 = gelu_exact(v3);
            }
            __half2 h0 = __floats2half2_rn(v0, v1);
            __half2 h1 = __floats2half2_rn(v2, v3);
            *(__half2*)&oh[o0] = h0;
            *(__half2*)&oh[o1] = h1;
        }
    }
#undef LOAD_STAGE
}

// ---------------- fp16 GEMM (small-M): BM=64 BN=128 BK=32, 256 thr, 3 CTAs/SM --------
// Always mode-1 semantics: v = D + bias + resid -> outf; if ln_s: fused LN -> oh.
#define STG64_B  18432
#define GEMM64_SMEM 55296   // 3 stages; also >= 32KB LN staging

__global__ __launch_bounds__(256, 3) void tgemm64_kernel(
    const fp16* __restrict__ A, const fp16* __restrict__ W, int K,
    const float* __restrict__ bias,
    float* __restrict__ outf,
    fp16* __restrict__ oh,
    const float* __restrict__ resid,
    const float* __restrict__ ln_s, const float* __restrict__ ln_b) {
    extern __shared__ __align__(16) char sm[];
    uint32_t sb = smem_u32(sm);
    const int tid = threadIdx.x, lane = tid & 31, wid = tid >> 5;
    const int bm = blockIdx.y * 64;
    const int wm = (wid & 1) * 32, wn = (wid >> 1) * 32;   // 2x4 warps, 32x32 tiles
    const int nst = K >> 5;

    // loaders: A: 1 cp16/thread (sub = tid>>7, idx = tid&127); W: 2 cp16/thread
    const int asub = tid >> 7, at = tid & 127;
    const int arow = at >> 1, ahf = at & 1;
    const fp16* pa = A + (size_t)(bm + arow) * K + asub * 16 + ahf * 8;
    const uint32_t da = (uint32_t)(asub * 3072 + arow * 48 + ahf * 16);
    const int wrow = tid >> 1, whf = tid & 1;
    const fp16* pw = W + (size_t)wrow * K + whf * 8;
    const uint32_t dw = (uint32_t)(6144 + wrow * 48 + whf * 16);

    float acc[2][4][4];
#pragma unroll
    for (int i = 0; i < 2; i++)
#pragma unroll
        for (int j = 0; j < 4; j++)
#pragma unroll
            for (int c = 0; c < 4; c++) acc[i][j][c] = 0.f;

    const uint32_t aoff = (uint32_t)((lane & 15) * 48 + (lane >> 4) * 16);
    const uint32_t boff = (uint32_t)(((((lane >> 4) << 3) + (lane & 7)) * 48) + ((lane >> 3) & 1) * 16);

#define LOAD_STAGE64(s) do { \
    uint32_t base_ = sb + ((s) % 3) * STG64_B; \
    int ko_ = (s) * 32; \
    cp16(base_ + da,         pa + ko_); \
    cp16(base_ + dw,         pw + ko_); \
    cp16(base_ + 6144 + dw,  pw + ko_ + 16); \
} while (0)

    LOAD_STAGE64(0); CP_COMMIT();
    if (nst > 1) { LOAD_STAGE64(1); CP_COMMIT(); }

    for (int s = 0; s < nst; s++) {
        if (s + 1 < nst) CP_WAIT(1); else CP_WAIT(0);
        __syncthreads();
        if (s + 2 < nst) { LOAD_STAGE64(s + 2); CP_COMMIT(); }

        uint32_t base = sb + (s % 3) * STG64_B;
#pragma unroll
        for (int sub = 0; sub < 2; sub++) {
            uint32_t fa[2][4];
#pragma unroll
            for (int mi = 0; mi < 2; mi++)
                ldsm4(fa[mi], base + (uint32_t)sub * 3072u + (uint32_t)((wm + mi * 16) * 48) + aoff);
            uint32_t wb = base + 6144u + (uint32_t)sub * 6144u;
#pragma unroll
            for (int nj = 0; nj < 2; nj++) {
                uint32_t fw[4];
                ldsm4(fw, wb + (uint32_t)((wn + nj * 16) * 48) + boff);
#pragma unroll
                for (int mi = 0; mi < 2; mi++) {
                    mma_f16(acc[mi][nj * 2],     fa[mi], fw[0], fw[1]);
                    mma_f16(acc[mi][nj * 2 + 1], fa[mi], fw[2], fw[3]);
                }
            }
        }
    }
    __syncthreads();

    // residual add -> outf, stage in smem, optional fused LN -> oh
    float* smf = (float*)sm;  // 64x128 f32 = 32KB
#pragma unroll
    for (int mi = 0; mi < 2; mi++) {
        int lr0 = wm + mi * 16 + (lane >> 2);
        int lr1 = lr0 + 8;
#pragma unroll
        for (int ni = 0; ni < 4; ni++) {
            int col = wn + ni * 8 + 2 * (lane & 3);
            float b0 = bias[col], b1 = bias[col + 1];
            size_t o0 = (size_t)(bm + lr0) * 128 + col, o1 = (size_t)(bm + lr1) * 128 + col;
            float v0 = acc[mi][ni][0] + b0 + resid[o0];
            float v1 = acc[mi][ni][1] + b1 + resid[o0 + 1];
            float v2 = acc[mi][ni][2] + b0 + resid[o1];
            float v3 = acc[mi][ni][3] + b1 + resid[o1 + 1];
            *(float2*)&outf[o0] = make_float2(v0, v1);
            *(float2*)&outf[o1] = make_float2(v2, v3);
            smf[lr0 * 128 + col] = v0; smf[lr0 * 128 + col + 1] = v1;
            smf[lr1 * 128 + col] = v2; smf[lr1 * 128 + col + 1] = v3;
        }
    }
    if (ln_s) {
        __syncthreads();
        float4 s4 = *(const float4*)(ln_s + lane * 4);
        float4 b4 = *(const float4*)(ln_b + lane * 4);
#pragma unroll
        for (int t = 0; t < 8; t++) {
            int rr = wid * 8 + t;
            float4 v = ((const float4*)smf)[rr * 32 + lane];
            float sum = (v.x + v.y) + (v.z + v.w);
            float sq  = fmaf(v.x, v.x, fmaf(v.y, v.y, fmaf(v.z, v.z, v.w * v.w)));
#pragma unroll
            for (int o = 16; o; o >>= 1) {
                sum += __shfl_xor_sync(0xffffffffu, sum, o);
                sq  += __shfl_xor_sync(0xffffffffu, sq, o);
            }
            float mu  = sum * (1.0f / 128.0f);
            float var = sq * (1.0f / 128.0f) - mu * mu;
            float inv = rsqrtf(var + 1e-5f);
            __half2 h0 = __floats2half2_rn((v.x - mu) * inv * s4.x + b4.x,
                                           (v.y - mu) * inv * s4.y + b4.y);
            __half2 h1 = __floats2half2_rn((v.z - mu) * inv * s4.z + b4.z,
                                           (v.w - mu) * inv * s4.w + b4.w);
            uint2 uh{*(uint32_t*)&h0, *(uint32_t*)&h1};
            *(uint2*)(oh + (size_t)(bm + rr) * 128 + lane * 4) = uh;
        }
    }
#undef LOAD_STAGE64
}

// ---------------- dense 12-node attention (fp16 qkv input) ----------------
__global__ __launch_bounds__(64) void attn_kernel(const fp16* __restrict__ qkv,
                                                  const float* __restrict__ edge_bias,
                                                  fp16* __restrict__ mh) {
    __shared__ float sk[NODES * D];
    __shared__ float sv[NODES * D];
    __shared__ float seb[36];
    int b = blockIdx.x;
    const uint4* src = (const uint4*)(qkv + (size_t)b * NODES * 384);
    for (int i = threadIdx.x; i < NODES * 32; i += 64) {
        int node = i >> 5, c = i & 31;
        uint4 u = src[node * 48 + 16 + c];
        float* dp = (c < 16) ? &sk[node * D + c * 8] : &sv[node * D + (c - 16) * 8];
        float2 f0 = __half22float2(*(__half2*)&u.x);
        float2 f1 = __half22float2(*(__half2*)&u.y);
        float2 f2 = __half22float2(*(__half2*)&u.z);
        float2 f3 = __half22float2(*(__half2*)&u.w);
        dp[0] = f0.x; dp[1] = f0.y; dp[2] = f1.x; dp[3] = f1.y;
        dp[4] = f2.x; dp[5] = f2.y; dp[6] = f3.x; dp[7] = f3.y;
    }
    if (threadIdx.x < 36) seb[threadIdx.x] = edge_bias[threadIdx.x];
    __syncthreads();
    int tt = threadIdx.x;
    if (tt >= NODES * NHEAD) return;
    int dst = tt >> 2, hd = tt & 3;
    int kd = dst < 6 ? 0 : (dst < 11 ? 1 : 2);

    float q[DH];
    {
        const uint4* qp = src + dst * 48 + hd * 4;
#pragma unroll
        for (int i = 0; i < 4; i++) {
            uint4 u = qp[i];
            float2 f0 = __half22float2(*(__half2*)&u.x);
            float2 f1 = __half22float2(*(__half2*)&u.y);
            float2 f2 = __half22float2(*(__half2*)&u.z);
            float2 f3 = __half22float2(*(__half2*)&u.w);
            q[i * 8 + 0] = f0.x; q[i * 8 + 1] = f0.y; q[i * 8 + 2] = f1.x; q[i * 8 + 3] = f1.y;
            q[i * 8 + 4] = f2.x; q[i * 8 + 5] = f2.y; q[i * 8 + 6] = f3.x; q[i * 8 + 7] = f3.y;
        }
    }

    float logits[NODES];
    float mx = -1e30f;
#pragma unroll
    for (int j = 0; j < NODES; j++) {
        const float4* kp = (const float4*)&sk[j * D + hd * DH];
        float d0 = 0.f, d1 = 0.f, d2 = 0.f, d3 = 0.f;
#pragma unroll
        for (int i = 0; i < 8; i++) {
            float4 kv = kp[i];
            d0 = fmaf(q[i * 4 + 0], kv.x, d0);
            d1 = fmaf(q[i * 4 + 1], kv.y, d1);
            d2 = fmaf(q[i * 4 + 2], kv.z, d2);
            d3 = fmaf(q[i * 4 + 3], kv.w, d3);
        }
        int ks = j < 6 ? 0 : (j < 11 ? 1 : 2);
        float lg = ((d0 + d1) + (d2 + d3)) * SCALE + seb[(ks * 3 + kd) * NHEAD + hd];
        logits[j] = lg;
        mx = fmaxf(mx, lg);
    }
    float z = 0.f;
#pragma unroll
    for (int j = 0; j < NODES; j++) { logits[j] = __expf(logits[j] - mx); z += logits[j]; }
    float inv = 1.0f / z;

    float4 out[8];
#pragma unroll
    for (int i = 0; i < 8; i++) out[i] = make_float4(0.f, 0.f, 0.f, 0.f);
#pragma unroll
    for (int j = 0; j < NODES; j++) {
        float a = logits[j] * inv;
        const float4* vp = (const float4*)&sv[j * D + hd * DH];
#pragma unroll
        for (int i = 0; i < 8; i++) {
            float4 vv = vp[i];
            out[i].x = fmaf(a, vv.x, out[i].x);
            out[i].y = fmaf(a, vv.y, out[i].y);
            out[i].z = fmaf(a, vv.z, out[i].z);
            out[i].w = fmaf(a, vv.w, out[i].w);
        }
    }
    size_t ob = (size_t)b * NODES * D + dst * D + hd * DH;
#pragma unroll
    for (int i = 0; i < 8; i++) {
        __half2 h0 = __floats2half2_rn(out[i].x, out[i].y);
        __half2 h1 = __floats2half2_rn(out[i].z, out[i].w);
        uint2 uh{*(uint32_t*)&h0, *(uint32_t*)&h1};
        *(uint2*)(mh + ob + i * 4) = uh;
    }
}

// ---------------- final: gate/pool + proj + LN + gelu ----------------
__global__ void final_kernel(const float* __restrict__ x,
                             const float* __restrict__ gate_w, const float* __restrict__ gate_b,
                             const float* __restrict__ proj_w, const float* __restrict__ proj_b,
                             const float* __restrict__ pln_s, const float* __restrict__ pln_b,
                             float* __restrict__ out) {
    __shared__ float sx[NODES * D];
    __shared__ float sgate[NODES];
    __shared__ float comb[2 * D];
    __shared__ float red[4];
    int b = blockIdx.x, tid = threadIdx.x;
    for (int i = tid; i < NODES * D; i += 128) sx[i] = x[(size_t)b * NODES * D + i];
    __syncthreads();
    if (tid < NODES) {
        float acc = gate_b[0];
#pragma unroll 8
        for (int d = 0; d < D; d++) acc = fmaf(sx[tid * D + d], gate_w[d], acc);
        sgate[tid] = 1.0f / (1.0f + __expf(-acc));
    }
    __syncthreads();
    float pooled = 0.f;
#pragma unroll
    for (int n = 0; n < NODES; n++) pooled = fmaf(sx[n * D + tid], sgate[n], pooled);
    comb[tid]     = sx[11 * D + tid];
    comb[D + tid] = pooled;
    __syncthreads();
    float y = proj_b[tid];
#pragma unroll 8
    for (int c = 0; c < 2 * D; c++) y = fmaf(comb[c], proj_w[c * D + tid], y);
    float sum = y;
#pragma unroll
    for (int o = 16; o; o >>= 1) sum += __shfl_xor_sync(0xffffffffu, sum, o);
    if ((tid & 31) == 0) red[tid >> 5] = sum;
    __syncthreads();
    float mu = (red[0] + red[1] + red[2] + red[3]) * (1.0f / 128.0f);
    float c0 = y - mu;
    float cs = c0 * c0;
#pragma unroll
    for (int o = 16; o; o >>= 1) cs += __shfl_xor_sync(0xffffffffu, cs, o);
    __syncthreads();
    if ((tid & 31) == 0) red[tid >> 5] = cs;
    __syncthreads();
    float var = (red[0] + red[1] + red[2] + red[3]) * (1.0f / 128.0f);
    float yn = c0 * rsqrtf(var + 1e-5f) * pln_s[tid] + pln_b[tid];
    out[(size_t)b * D + tid] = gelu_exact(yn);
}

// ---------------- host orchestration ----------------
extern "C" void kernel_launch(void* const* d_in, const int* in_sizes, int n_in,
                              void* d_out, int out_size) {
    const float* patch   = (const float*)d_in[0];
    const float* band    = (const float*)d_in[1];
    const float* summ    = (const float*)d_in[2];
    const float* ln1_s   = (const float*)d_in[3];
    const float* ln1_b   = (const float*)d_in[4];
    const float* wq      = (const float*)d_in[5];
    const float* bq      = (const float*)d_in[6];
    const float* wk      = (const float*)d_in[7];
    const float* bk      = (const float*)d_in[8];
    const float* wv      = (const float*)d_in[9];
    const float* bv      = (const float*)d_in[10];
    const float* wo      = (const float*)d_in[11];
    const float* bo      = (const float*)d_in[12];
    const float* edge_b  = (const float*)d_in[13];
    const float* ln2_s   = (const float*)d_in[14];
    const float* ln2_b   = (const float*)d_in[15];
    const float* w1      = (const float*)d_in[16];
    const float* b1      = (const float*)d_in[17];
    const float* w2      = (const float*)d_in[18];
    const float* b2      = (const float*)d_in[19];
    const float* gate_w  = (const float*)d_in[20];
    const float* gate_b  = (const float*)d_in[21];
    const float* proj_w  = (const float*)d_in[22];
    const float* proj_b  = (const float*)d_in[23];
    const float* pln_s   = (const float*)d_in[24];
    const float* pln_b   = (const float*)d_in[25];
    float* out = (float*)d_out;

    float *x, *bqkv;
    fp16 *qkv, *hbuf, *mbuf, *tbuf;
    fp16 *wqkvw, *wow, *w1w, *w2w;
    cudaGetSymbolAddress((void**)&x,     g_x);
    cudaGetSymbolAddress((void**)&qkv,   g_qkv);
    cudaGetSymbolAddress((void**)&bqkv,  g_bqkv);
    cudaGetSymbolAddress((void**)&hbuf,  g_h);
    cudaGetSymbolAddress((void**)&mbuf,  g_m);
    cudaGetSymbolAddress((void**)&tbuf,  g_t);
    cudaGetSymbolAddress((void**)&wqkvw, g_wqkv);
    cudaGetSymbolAddress((void**)&wow,   g_wo);
    cudaGetSymbolAddress((void**)&w1w,   g_w1);
    cudaGetSymbolAddress((void**)&w2w,   g_w2);

    static int smem_set = 0;
    if (!smem_set) {
        cudaFuncSetAttribute(tgemm_kernel, cudaFuncAttributeMaxDynamicSharedMemorySize, GEMM_SMEM);
        cudaFuncSetAttribute(tgemm64_kernel, cudaFuncAttributeMaxDynamicSharedMemorySize, GEMM64_SMEM);
        smem_set = 1;
    }

    init_ln_kernel<<<NTOK / 4, 128>>>(patch, band, summ, ln1_s, ln1_b, x, hbuf);
    pack_qkvw_kernel<<<(98304 + 255) / 256, 256>>>(wq, wk, wv, bq, bk, bv, wqkvw, bqkv);
    pack_rest_kernel<<<(294912 + 255) / 256, 256>>>(wo, w1, w2, wow, w1w, w2w);

    const int MT = NTOK / 128;    // 192
    const int MT64 = NTOK / 64;   // 384
    for (int l = 0; l < 2; l++) {
        // QKV (mode 0): N=384, fp16 out
        tgemm_kernel<<<dim3(3, MT), 256, GEMM_SMEM>>>(
            hbuf, wqkvw + (size_t)l * 384 * 128, 128, bqkv + l * 384, qkv, 384, 0);
        attn_kernel<<<BATCH, 64>>>(qkv, edge_b + l * 36, mbuf);
        // O-proj + residual + fused LN2: N=128 (small-M config)
        tgemm64_kernel<<<dim3(1, MT64), 256, GEMM64_SMEM>>>(
            mbuf, wow + (size_t)l * 128 * 128, 128,
            bo + l * 128, x, hbuf, x, ln2_s + l * 128, ln2_b + l * 128);
        // FFN1 + GELU (mode 2): N=512
        tgemm_kernel<<<dim3(4, MT), 256, GEMM_SMEM>>>(
            hbuf, w1w + (size_t)l * 512 * 128, 128, b1 + l * 512, tbuf, 512, 2);
        // FFN2 + residual (+ fused next-layer LN1): N=128, K=512 (small-M config)
        const float* nls = (l == 0) ? (ln1_s + 128) : nullptr;
        const float* nlb = (l == 0) ? (ln1_b + 128) : nullptr;
        tgemm64_kernel<<<dim3(1, MT64), 256, GEMM64_SMEM>>>(
            tbuf, w2w + (size_t)l * 128 * 512, 512,
            b2 + l * 128, x, hbuf, x, nls, nlb);
    }

    final_kernel<<<BATCH, 128>>>(x, gate_w, gate_b, proj_w, proj_b, pln_s, pln_b, out);
}